// round 1
// baseline (speedup 1.0000x reference)
#include <cuda_runtime.h>
#include <cuda_bf16.h>

// Problem constants (TTWindowAttention): B_=2048, N=49, C=384, H=12, d=32, nW=64
#define BWIN   2048
#define NTOK   49
#define CDIM   384
#define HNUM   12
#define DHEAD  32
#define NWIN   64
#define MROWS  (BWIN * NTOK)     // 100352
#define QKVC   (3 * CDIM)        // 1152

// Scratch (static device globals — no allocation allowed in kernel_launch)
__device__ __align__(16) float g_qkv[(size_t)MROWS * QKVC];  // [b*49+n][t*384 + h*32 + d]
__device__ __align__(16) float g_att[(size_t)MROWS * CDIM];  // [b*49+n][h*32 + d]

// ---------------------------------------------------------------------------
// Tiled SGEMM: C[M x NMAT] = A[M x 384] @ B[384 x NMAT] + bias
// 64x64 block tile, BK=16, 256 threads, 4x4 per-thread micro-tile.
// M, NMAT, K all divisible by tile sizes -> no bounds checks.
// ---------------------------------------------------------------------------
template <int NMAT>
__device__ __forceinline__ void sgemm_body(const float* __restrict__ A,
                                           const float* __restrict__ B,
                                           const float* __restrict__ bias,
                                           float* __restrict__ C)
{
    constexpr int K = 384, BM = 64, BN = 64, BK = 16;

    __shared__ float As[BK][BM];
    __shared__ float Bs[BK][BN];

    const int tid = threadIdx.x;
    const int tx  = tid & 15;        // 0..15 -> col group
    const int ty  = tid >> 4;        // 0..15 -> row group
    const int bm  = blockIdx.y * BM;
    const int bn  = blockIdx.x * BN;

    // A-load mapping: each thread loads one float4 along K
    const int rowA = tid >> 2;           // 0..63
    const int kqa  = (tid & 3) * 4;      // 0,4,8,12
    // B-load mapping: each thread loads one float4 along N
    const int kB = tid >> 4;             // 0..15
    const int nq = (tid & 15) * 4;       // 0..60

    float acc[4][4];
#pragma unroll
    for (int i = 0; i < 4; ++i)
#pragma unroll
        for (int j = 0; j < 4; ++j) acc[i][j] = 0.f;

    for (int kb = 0; kb < K; kb += BK) {
        float4 va = *reinterpret_cast<const float4*>(
            &A[(size_t)(bm + rowA) * K + kb + kqa]);
        As[kqa + 0][rowA] = va.x;
        As[kqa + 1][rowA] = va.y;
        As[kqa + 2][rowA] = va.z;
        As[kqa + 3][rowA] = va.w;

        float4 vb = *reinterpret_cast<const float4*>(
            &B[(size_t)(kb + kB) * NMAT + bn + nq]);
        *reinterpret_cast<float4*>(&Bs[kB][nq]) = vb;

        __syncthreads();

#pragma unroll
        for (int k = 0; k < BK; ++k) {
            float4 a = *reinterpret_cast<const float4*>(&As[k][ty * 4]);
            float4 b = *reinterpret_cast<const float4*>(&Bs[k][tx * 4]);
            acc[0][0] += a.x * b.x; acc[0][1] += a.x * b.y;
            acc[0][2] += a.x * b.z; acc[0][3] += a.x * b.w;
            acc[1][0] += a.y * b.x; acc[1][1] += a.y * b.y;
            acc[1][2] += a.y * b.z; acc[1][3] += a.y * b.w;
            acc[2][0] += a.z * b.x; acc[2][1] += a.z * b.y;
            acc[2][2] += a.z * b.z; acc[2][3] += a.z * b.w;
            acc[3][0] += a.w * b.x; acc[3][1] += a.w * b.y;
            acc[3][2] += a.w * b.z; acc[3][3] += a.w * b.w;
        }
        __syncthreads();
    }

    float4 bv = *reinterpret_cast<const float4*>(&bias[bn + tx * 4]);
#pragma unroll
    for (int i = 0; i < 4; ++i) {
        const int row = bm + ty * 4 + i;
        float4 o;
        o.x = acc[i][0] + bv.x;
        o.y = acc[i][1] + bv.y;
        o.z = acc[i][2] + bv.z;
        o.w = acc[i][3] + bv.w;
        *reinterpret_cast<float4*>(&C[(size_t)row * NMAT + bn + tx * 4]) = o;
    }
}

__global__ __launch_bounds__(256)
void qkv_gemm_kernel(const float* __restrict__ x,
                     const float* __restrict__ w,
                     const float* __restrict__ b)
{
    sgemm_body<QKVC>(x, w, b, g_qkv);
}

__global__ __launch_bounds__(256)
void proj_gemm_kernel(const float* __restrict__ w,
                      const float* __restrict__ b,
                      float* __restrict__ out)
{
    sgemm_body<CDIM>(g_att, w, b, out);
}

// ---------------------------------------------------------------------------
// Attention: one block per (window b, head h). 128 threads = 4 warps.
// q,k,v tiles (49x32) staged to smem (pad 33 to kill bank conflicts on the
// m-varying K reads). Each warp owns query rows n = warp, warp+4, ...
// Lanes split the 49 key positions as {lane, lane+32}.
// ---------------------------------------------------------------------------
__global__ __launch_bounds__(128)
void attn_kernel(const float* __restrict__ relb,
                 const float* __restrict__ mask)
{
    const int b = blockIdx.x;
    const int h = blockIdx.y;

    __shared__ float q_s[NTOK][33];
    __shared__ float k_s[NTOK][33];
    __shared__ float v_s[NTOK][33];
    __shared__ float p_s[4][64];

    const int tid = threadIdx.x;
    const float* base = g_qkv + (size_t)b * NTOK * QKVC + h * DHEAD;

    for (int idx = tid; idx < NTOK * DHEAD; idx += 128) {
        const int n = idx >> 5;
        const int d = idx & 31;
        const float* src = base + (size_t)n * QKVC + d;
        q_s[n][d] = src[0];
        k_s[n][d] = src[CDIM];
        v_s[n][d] = src[2 * CDIM];
    }
    __syncthreads();

    const int   w    = b & (NWIN - 1);
    const int   warp = tid >> 5;
    const int   lane = tid & 31;
    const float scale = 0.17677669529663687f;  // 32^-0.5

    const float* rb = relb + (size_t)h * NTOK * NTOK;
    const float* mk = mask + (size_t)w * NTOK * NTOK;

    for (int n = warp; n < NTOK; n += 4) {
        const int  m0 = lane;
        const int  m1 = lane + 32;
        const bool v1 = (m1 < NTOK);
        const int  m1c = v1 ? m1 : 0;

        float acc0 = 0.f, acc1 = 0.f;
#pragma unroll
        for (int d = 0; d < DHEAD; ++d) {
            const float qv = q_s[n][d];
            acc0 += qv * k_s[m0][d];
            acc1 += qv * k_s[m1c][d];
        }
        acc0 = acc0 * scale + rb[n * NTOK + m0] + mk[n * NTOK + m0];
        acc1 = v1 ? (acc1 * scale + rb[n * NTOK + m1] + mk[n * NTOK + m1])
                  : -1e30f;

        float mx = fmaxf(acc0, acc1);
#pragma unroll
        for (int o = 16; o; o >>= 1)
            mx = fmaxf(mx, __shfl_xor_sync(0xffffffffu, mx, o));

        const float e0 = __expf(acc0 - mx);
        const float e1 = v1 ? __expf(acc1 - mx) : 0.f;
        float s = e0 + e1;
#pragma unroll
        for (int o = 16; o; o >>= 1)
            s += __shfl_xor_sync(0xffffffffu, s, o);
        const float inv = 1.f / s;

        p_s[warp][m0] = e0 * inv;
        if (v1) p_s[warp][m1] = e1 * inv;
        __syncwarp();

        float o = 0.f;
#pragma unroll
        for (int m = 0; m < NTOK; ++m)
            o += p_s[warp][m] * v_s[m][lane];

        g_att[((size_t)b * NTOK + n) * CDIM + h * DHEAD + lane] = o;
        __syncwarp();
    }
}

// ---------------------------------------------------------------------------
extern "C" void kernel_launch(void* const* d_in, const int* in_sizes, int n_in,
                              void* d_out, int out_size)
{
    const float* x      = (const float*)d_in[0];
    const float* mask   = (const float*)d_in[1];
    const float* qkv_w  = (const float*)d_in[2];
    const float* qkv_b  = (const float*)d_in[3];
    const float* proj_w = (const float*)d_in[4];
    const float* proj_b = (const float*)d_in[5];
    const float* relb   = (const float*)d_in[6];
    float* out = (float*)d_out;

    // 1) QKV GEMM + bias
    {
        dim3 grid(QKVC / 64, MROWS / 64);
        qkv_gemm_kernel<<<grid, 256>>>(x, qkv_w, qkv_b);
    }
    // 2) windowed attention (softmax(QK^T*scale + relpos + mask) @ V)
    {
        dim3 grid(BWIN, HNUM);
        attn_kernel<<<grid, 128>>>(relb, mask);
    }
    // 3) output projection + bias
    {
        dim3 grid(CDIM / 64, MROWS / 64);
        proj_gemm_kernel<<<grid, 256>>>(proj_w, proj_b, out);
    }
}

// round 3
// speedup vs baseline: 1.7510x; 1.7510x over previous
#include <cuda_runtime.h>
#include <cuda_bf16.h>
#include <cstdint>

// Problem constants: B_=2048, N=49, C=384, H=12, d=32, nW=64
#define BWIN   2048
#define NTOK   49
#define CDIM   384
#define HNUM   12
#define DHEAD  32
#define NWIN   64
#define MROWS  (BWIN * NTOK)     // 100352
#define QKVC   (3 * CDIM)        // 1152
#define KDIM   384
#define KV     1152              // virtual K = 3 * 384 (bf16x3 split)

// GEMM tiling
#define GBM   256
#define GBN   128
#define GKC   32                 // k per chunk
#define NCH   (KV / GKC)         // 36
#define ROWB  80                 // smem row stride (bytes) — conflict-free pad
#define AS_BYTES (GBM * ROWB)    // 20480
#define BS_BYTES (GBN * ROWB)    // 10240
#define SMEM_GEMM (2 * AS_BYTES + 2 * BS_BYTES)   // 61440
#define MTILES (MROWS / GBM)     // 392

// -------------------- device scratch (no runtime alloc allowed) -----------
__device__ __align__(16) __nv_bfloat16 g_xbf [(size_t)MROWS * 768];  // x hi|lo
__device__ __align__(16) __nv_bfloat16 g_attbf[(size_t)MROWS * 768]; // attn-out hi|lo
__device__ __align__(16) float         g_qkv [(size_t)MROWS * QKVC];
__device__ __align__(16) __nv_bfloat16 g_wqt [(size_t)QKVC * KV];    // [1152][1152]
__device__ __align__(16) __nv_bfloat16 g_wpt [(size_t)CDIM * KV];    // [384][1152]

// -------------------- PTX helpers -----------------------------------------
__device__ __forceinline__ uint32_t smem_u32(const void* p) {
    uint32_t a;
    asm("{ .reg .u64 t; cvta.to.shared.u64 t, %1; cvt.u32.u64 %0, t; }"
        : "=r"(a) : "l"(p));
    return a;
}
__device__ __forceinline__ void cp16(uint32_t s, const void* g) {
    asm volatile("cp.async.cg.shared.global [%0], [%1], 16;" :: "r"(s), "l"(g));
}
__device__ __forceinline__ void cp_commit() {
    asm volatile("cp.async.commit_group;" ::: "memory");
}
__device__ __forceinline__ void ldsm4(uint32_t* r, uint32_t addr) {
    asm volatile("ldmatrix.sync.aligned.m8n8.x4.shared.b16 {%0,%1,%2,%3}, [%4];"
        : "=r"(r[0]), "=r"(r[1]), "=r"(r[2]), "=r"(r[3]) : "r"(addr));
}
__device__ __forceinline__ void mma16816(float* d, const uint32_t* a, const uint32_t* b) {
    asm volatile(
        "mma.sync.aligned.m16n8k16.row.col.f32.bf16.bf16.f32 "
        "{%0,%1,%2,%3}, {%4,%5,%6,%7}, {%8,%9}, {%0,%1,%2,%3};"
        : "+f"(d[0]), "+f"(d[1]), "+f"(d[2]), "+f"(d[3])
        : "r"(a[0]), "r"(a[1]), "r"(a[2]), "r"(a[3]), "r"(b[0]), "r"(b[1]));
}

// -------------------- prep: x fp32 -> bf16 hi/lo [M,768] -------------------
__global__ __launch_bounds__(256)
void prep_x_kernel(const float* __restrict__ x, __nv_bfloat16* __restrict__ dst)
{
    size_t id = (size_t)blockIdx.x * 256 + threadIdx.x;   // one per 4 cols
    if (id >= (size_t)MROWS * (KDIM / 4)) return;
    size_t row = id / (KDIM / 4);
    int c4 = (int)(id % (KDIM / 4)) * 4;
    float4 v = *reinterpret_cast<const float4*>(&x[row * KDIM + c4]);
    __nv_bfloat16 h[4], l[4];
    h[0] = __float2bfloat16_rn(v.x); l[0] = __float2bfloat16_rn(v.x - __bfloat162float(h[0]));
    h[1] = __float2bfloat16_rn(v.y); l[1] = __float2bfloat16_rn(v.y - __bfloat162float(h[1]));
    h[2] = __float2bfloat16_rn(v.z); l[2] = __float2bfloat16_rn(v.z - __bfloat162float(h[2]));
    h[3] = __float2bfloat16_rn(v.w); l[3] = __float2bfloat16_rn(v.w - __bfloat162float(h[3]));
    *reinterpret_cast<uint2*>(&dst[row * 768 + c4])       = *reinterpret_cast<uint2*>(h);
    *reinterpret_cast<uint2*>(&dst[row * 768 + 384 + c4]) = *reinterpret_cast<uint2*>(l);
}

// -------------------- prep: W [384,N] fp32 -> Bt [N][1152] bf16 ------------
// Bt[n][k] = hi(W[k][n]); Bt[n][384+k] = hi; Bt[n][768+k] = lo.
__global__ __launch_bounds__(256)
void prep_w_kernel(const float* __restrict__ w, __nv_bfloat16* __restrict__ bt, int N)
{
    int id = blockIdx.x * 256 + threadIdx.x;
    if (id >= KDIM * N) return;
    int k = id / N, n = id % N;
    float a = w[(size_t)k * N + n];
    __nv_bfloat16 h = __float2bfloat16_rn(a);
    __nv_bfloat16 l = __float2bfloat16_rn(a - __bfloat162float(h));
    __nv_bfloat16* row = bt + (size_t)n * KV;
    row[k]        = h;
    row[384 + k]  = h;
    row[768 + k]  = l;
}

// -------------------- GEMM: C[M x N] = A'[M x 1152] @ B'[1152 x N] + bias --
// A stored as [M,768] bf16 (hi 0..383 | lo 384..767); virtual col k'>=768 maps
// back to hi (k'-768). B stored as Bt [N,1152] bf16 (already tripled).
// Block 256x128, 8 warps (4x2), warp tile 64x64, mma m16n8k16 bf16.
__global__ __launch_bounds__(256, 1)
void gemm_bf16x3_kernel(const __nv_bfloat16* __restrict__ Ab,
                        const __nv_bfloat16* __restrict__ Bt,
                        const float* __restrict__ bias,
                        float* __restrict__ C, int ldc)
{
    extern __shared__ char smem[];
    const uint32_t s_a = smem_u32(smem);
    const uint32_t s_b = s_a + 2 * AS_BYTES;

    const int tid  = threadIdx.x;
    const int wid  = tid >> 5;
    const int lane = tid & 31;
    const int wm   = wid >> 1;          // 0..3 (M)
    const int wn   = wid & 1;           // 0..1 (N)
    const int bm   = blockIdx.x * GBM;
    const int bn   = blockIdx.y * GBN;

    // cp.async source/dest mapping (per chunk)
    const int arow = tid >> 2;          // A: 4 iters cover rows 0..255
    const int ac16 = tid & 3;
    const int brow = tid >> 2;          // B: 2 iters cover rows 0..127
    const int bc16 = tid & 3;

    float acc[4][8][4];
#pragma unroll
    for (int i = 0; i < 4; ++i)
#pragma unroll
        for (int j = 0; j < 8; ++j)
#pragma unroll
            for (int q = 0; q < 4; ++q) acc[i][j][q] = 0.f;

    // ldmatrix lane addressing (bytes within tile row windows)
    const int a_r  = (lane & 7) + ((lane >> 3) & 1) * 8;
    const int a_cb = (lane >> 4) * 16;
    const int b_r  = (lane & 7) + ((lane >> 4) & 1) * 8;
    const int b_cb = ((lane >> 3) & 1) * 16;

    auto issue = [&](int kc, int buf) {
        const int kp  = kc * GKC;
        const int src = (kp < 768) ? kp : (kp - 768);
#pragma unroll
        for (int i = 0; i < 4; ++i) {
            int r = arow + i * 64;
            cp16(s_a + buf * AS_BYTES + r * ROWB + ac16 * 16,
                 Ab + (size_t)(bm + r) * 768 + src + ac16 * 8);
        }
#pragma unroll
        for (int i = 0; i < 2; ++i) {
            int r = brow + i * 64;
            cp16(s_b + buf * BS_BYTES + r * ROWB + bc16 * 16,
                 Bt + (size_t)(bn + r) * KV + kp + bc16 * 8);
        }
        cp_commit();
    };

    issue(0, 0);

    for (int kc = 0; kc < NCH; ++kc) {
        const int buf = kc & 1;
        if (kc + 1 < NCH) {
            issue(kc + 1, buf ^ 1);
            asm volatile("cp.async.wait_group 1;" ::: "memory");
        } else {
            asm volatile("cp.async.wait_group 0;" ::: "memory");
        }
        __syncthreads();

        const uint32_t abase = s_a + buf * AS_BYTES + (wm * 64 + a_r) * ROWB + a_cb;
        const uint32_t bbase = s_b + buf * BS_BYTES + (wn * 64 + b_r) * ROWB + b_cb;

#pragma unroll
        for (int ks = 0; ks < 2; ++ks) {
            const int kb = ks * 32;     // 16 bf16 = 32 bytes
            uint32_t af[4][4];
#pragma unroll
            for (int fm = 0; fm < 4; ++fm)
                ldsm4(af[fm], abase + fm * 16 * ROWB + kb);
            uint32_t bf[8][2];
#pragma unroll
            for (int j = 0; j < 4; ++j) {
                uint32_t r[4];
                ldsm4(r, bbase + j * 16 * ROWB + kb);
                bf[2 * j][0] = r[0]; bf[2 * j][1] = r[1];
                bf[2 * j + 1][0] = r[2]; bf[2 * j + 1][1] = r[3];
            }
#pragma unroll
            for (int fm = 0; fm < 4; ++fm)
#pragma unroll
                for (int fn = 0; fn < 8; ++fn)
                    mma16816(acc[fm][fn], af[fm], bf[fn]);
        }
        __syncthreads();
    }

    // Epilogue: direct frag stores + bias (float2)
#pragma unroll
    for (int fm = 0; fm < 4; ++fm) {
        const int row0 = bm + wm * 64 + fm * 16 + (lane >> 2);
#pragma unroll
        for (int fn = 0; fn < 8; ++fn) {
            const int col = bn + wn * 64 + fn * 8 + (lane & 3) * 2;
            const float b0 = __ldg(&bias[col]);
            const float b1 = __ldg(&bias[col + 1]);
            float2 o0 = make_float2(acc[fm][fn][0] + b0, acc[fm][fn][1] + b1);
            float2 o1 = make_float2(acc[fm][fn][2] + b0, acc[fm][fn][3] + b1);
            *reinterpret_cast<float2*>(&C[(size_t)row0 * ldc + col])       = o0;
            *reinterpret_cast<float2*>(&C[(size_t)(row0 + 8) * ldc + col]) = o1;
        }
    }
}

// -------------------- attention: writes bf16 hi/lo for proj GEMM -----------
__global__ __launch_bounds__(128)
void attn_kernel(const float* __restrict__ relb,
                 const float* __restrict__ mask)
{
    const int b = blockIdx.x;
    const int h = blockIdx.y;

    __shared__ float q_s[NTOK][33];
    __shared__ float k_s[NTOK][33];
    __shared__ float v_s[NTOK][33];
    __shared__ float p_s[4][64];

    const int tid = threadIdx.x;
    const float* base = g_qkv + (size_t)b * NTOK * QKVC + h * DHEAD;

    for (int idx = tid; idx < NTOK * DHEAD; idx += 128) {
        const int n = idx >> 5;
        const int d = idx & 31;
        const float* src = base + (size_t)n * QKVC + d;
        q_s[n][d] = src[0];
        k_s[n][d] = src[CDIM];
        v_s[n][d] = src[2 * CDIM];
    }
    __syncthreads();

    const int   w    = b & (NWIN - 1);
    const int   warp = tid >> 5;
    const int   lane = tid & 31;
    const float scale = 0.17677669529663687f;

    const float* rb = relb + (size_t)h * NTOK * NTOK;
    const float* mk = mask + (size_t)w * NTOK * NTOK;

    for (int n = warp; n < NTOK; n += 4) {
        const int  m0 = lane;
        const int  m1 = lane + 32;
        const bool v1 = (m1 < NTOK);
        const int  m1c = v1 ? m1 : 0;

        float acc0 = 0.f, acc1 = 0.f;
#pragma unroll
        for (int d = 0; d < DHEAD; ++d) {
            const float qv = q_s[n][d];
            acc0 += qv * k_s[m0][d];
            acc1 += qv * k_s[m1c][d];
        }
        acc0 = acc0 * scale + rb[n * NTOK + m0] + mk[n * NTOK + m0];
        acc1 = v1 ? (acc1 * scale + rb[n * NTOK + m1] + mk[n * NTOK + m1])
                  : -1e30f;

        float mx = fmaxf(acc0, acc1);
#pragma unroll
        for (int o = 16; o; o >>= 1)
            mx = fmaxf(mx, __shfl_xor_sync(0xffffffffu, mx, o));

        const float e0 = __expf(acc0 - mx);
        const float e1 = v1 ? __expf(acc1 - mx) : 0.f;
        float s = e0 + e1;
#pragma unroll
        for (int o = 16; o; o >>= 1)
            s += __shfl_xor_sync(0xffffffffu, s, o);
        const float inv = 1.f / s;

        p_s[warp][m0] = e0 * inv;
        if (v1) p_s[warp][m1] = e1 * inv;
        __syncwarp();

        float o = 0.f;
#pragma unroll
        for (int m = 0; m < NTOK; ++m)
            o += p_s[warp][m] * v_s[m][lane];

        const size_t row = (size_t)b * NTOK + n;
        __nv_bfloat16 hv = __float2bfloat16_rn(o);
        __nv_bfloat16 lv = __float2bfloat16_rn(o - __bfloat162float(hv));
        g_attbf[row * 768 + h * DHEAD + lane]       = hv;
        g_attbf[row * 768 + 384 + h * DHEAD + lane] = lv;
        __syncwarp();
    }
}

// ---------------------------------------------------------------------------
extern "C" void kernel_launch(void* const* d_in, const int* in_sizes, int n_in,
                              void* d_out, int out_size)
{
    const float* x      = (const float*)d_in[0];
    const float* mask   = (const float*)d_in[1];
    const float* qkv_w  = (const float*)d_in[2];
    const float* qkv_b  = (const float*)d_in[3];
    const float* proj_w = (const float*)d_in[4];
    const float* proj_b = (const float*)d_in[5];
    const float* relb   = (const float*)d_in[6];
    float* out = (float*)d_out;

    void *p_xbf, *p_attbf, *p_qkv, *p_wqt, *p_wpt;
    cudaGetSymbolAddress(&p_xbf,   g_xbf);
    cudaGetSymbolAddress(&p_attbf, g_attbf);
    cudaGetSymbolAddress(&p_qkv,   g_qkv);
    cudaGetSymbolAddress(&p_wqt,   g_wqt);
    cudaGetSymbolAddress(&p_wpt,   g_wpt);

    cudaFuncSetAttribute(gemm_bf16x3_kernel,
                         cudaFuncAttributeMaxDynamicSharedMemorySize, SMEM_GEMM);

    // 1) preps
    {
        size_t tx = (size_t)MROWS * (KDIM / 4);
        prep_x_kernel<<<(unsigned)((tx + 255) / 256), 256>>>(x, (__nv_bfloat16*)p_xbf);
        int tq = KDIM * QKVC;
        prep_w_kernel<<<(tq + 255) / 256, 256>>>(qkv_w, (__nv_bfloat16*)p_wqt, QKVC);
        int tp = KDIM * CDIM;
        prep_w_kernel<<<(tp + 255) / 256, 256>>>(proj_w, (__nv_bfloat16*)p_wpt, CDIM);
    }
    // 2) QKV GEMM (tensor cores, bf16x3)
    {
        dim3 grid(MTILES, QKVC / GBN);    // 392 x 9
        gemm_bf16x3_kernel<<<grid, 256, SMEM_GEMM>>>(
            (const __nv_bfloat16*)p_xbf, (const __nv_bfloat16*)p_wqt,
            qkv_b, (float*)p_qkv, QKVC);
    }
    // 3) windowed attention (emits bf16 hi/lo)
    {
        dim3 grid(BWIN, HNUM);
        attn_kernel<<<grid, 128>>>(relb, mask);
    }
    // 4) projection GEMM (tensor cores, bf16x3)
    {
        dim3 grid(MTILES, CDIM / GBN);    // 392 x 3
        gemm_bf16x3_kernel<<<grid, 256, SMEM_GEMM>>>(
            (const __nv_bfloat16*)p_attbf, (const __nv_bfloat16*)p_wpt,
            proj_b, out, CDIM);
    }
}

// round 4
// speedup vs baseline: 1.9146x; 1.0934x over previous
#include <cuda_runtime.h>
#include <cuda_bf16.h>
#include <cstdint>

// Problem constants: B_=2048, N=49, C=384, H=12, d=32, nW=64
#define BWIN   2048
#define NTOK   49
#define CDIM   384
#define HNUM   12
#define DHEAD  32
#define NWIN   64
#define MROWS  (BWIN * NTOK)     // 100352
#define QKVC   (3 * CDIM)        // 1152
#define KDIM   384
#define KV     1152              // virtual K = 3 * 384 (bf16x3 split)

// GEMM tiling
#define GBM   256
#define GBN   128
#define GKC   64                 // k per chunk (64 bf16 = 128B row)
#define NCH   (KV / GKC)         // 18
#define NSTG  3                  // cp.async stages
#define ROWB  144                // smem row stride (128B data + 16B pad)
#define A_ST  (GBM * ROWB)       // 36864
#define B_ST  (GBN * ROWB)       // 18432
#define STG_B (A_ST + B_ST)      // 55296
#define SMEM_GEMM (NSTG * STG_B) // 165888
#define MTILES (MROWS / GBM)     // 392

// -------------------- device scratch (no runtime alloc allowed) -----------
__device__ __align__(16) __nv_bfloat16 g_xbf [(size_t)MROWS * 768];  // x hi|lo
__device__ __align__(16) __nv_bfloat16 g_attbf[(size_t)MROWS * 768]; // attn-out hi|lo
__device__ __align__(16) float         g_qkv [(size_t)MROWS * QKVC];
__device__ __align__(16) __nv_bfloat16 g_wqt [(size_t)QKVC * KV];    // [1152][1152]
__device__ __align__(16) __nv_bfloat16 g_wpt [(size_t)CDIM * KV];    // [384][1152]

// -------------------- PTX helpers -----------------------------------------
__device__ __forceinline__ uint32_t smem_u32(const void* p) {
    uint32_t a;
    asm("{ .reg .u64 t; cvta.to.shared.u64 t, %1; cvt.u32.u64 %0, t; }"
        : "=r"(a) : "l"(p));
    return a;
}
__device__ __forceinline__ void cp16(uint32_t s, const void* g) {
    asm volatile("cp.async.cg.shared.global [%0], [%1], 16;" :: "r"(s), "l"(g));
}
__device__ __forceinline__ void cp_commit() {
    asm volatile("cp.async.commit_group;" ::: "memory");
}
__device__ __forceinline__ void ldsm4(uint32_t* r, uint32_t addr) {
    asm volatile("ldmatrix.sync.aligned.m8n8.x4.shared.b16 {%0,%1,%2,%3}, [%4];"
        : "=r"(r[0]), "=r"(r[1]), "=r"(r[2]), "=r"(r[3]) : "r"(addr));
}
__device__ __forceinline__ void mma16816(float* d, const uint32_t* a, const uint32_t* b) {
    asm volatile(
        "mma.sync.aligned.m16n8k16.row.col.f32.bf16.bf16.f32 "
        "{%0,%1,%2,%3}, {%4,%5,%6,%7}, {%8,%9}, {%0,%1,%2,%3};"
        : "+f"(d[0]), "+f"(d[1]), "+f"(d[2]), "+f"(d[3])
        : "r"(a[0]), "r"(a[1]), "r"(a[2]), "r"(a[3]), "r"(b[0]), "r"(b[1]));
}

// -------------------- prep: x fp32 -> bf16 hi/lo [M,768] -------------------
__global__ __launch_bounds__(256)
void prep_x_kernel(const float* __restrict__ x, __nv_bfloat16* __restrict__ dst)
{
    size_t id = (size_t)blockIdx.x * 256 + threadIdx.x;   // one per 4 cols
    if (id >= (size_t)MROWS * (KDIM / 4)) return;
    size_t row = id / (KDIM / 4);
    int c4 = (int)(id % (KDIM / 4)) * 4;
    float4 v = *reinterpret_cast<const float4*>(&x[row * KDIM + c4]);
    __nv_bfloat16 h[4], l[4];
    h[0] = __float2bfloat16_rn(v.x); l[0] = __float2bfloat16_rn(v.x - __bfloat162float(h[0]));
    h[1] = __float2bfloat16_rn(v.y); l[1] = __float2bfloat16_rn(v.y - __bfloat162float(h[1]));
    h[2] = __float2bfloat16_rn(v.z); l[2] = __float2bfloat16_rn(v.z - __bfloat162float(h[2]));
    h[3] = __float2bfloat16_rn(v.w); l[3] = __float2bfloat16_rn(v.w - __bfloat162float(h[3]));
    *reinterpret_cast<uint2*>(&dst[row * 768 + c4])       = *reinterpret_cast<uint2*>(h);
    *reinterpret_cast<uint2*>(&dst[row * 768 + 384 + c4]) = *reinterpret_cast<uint2*>(l);
}

// -------------------- prep: W [384,N] fp32 -> Bt [N][1152] bf16 ------------
__global__ __launch_bounds__(256)
void prep_w_kernel(const float* __restrict__ w, __nv_bfloat16* __restrict__ bt, int N)
{
    int id = blockIdx.x * 256 + threadIdx.x;
    if (id >= KDIM * N) return;
    int k = id / N, n = id % N;
    float a = w[(size_t)k * N + n];
    __nv_bfloat16 h = __float2bfloat16_rn(a);
    __nv_bfloat16 l = __float2bfloat16_rn(a - __bfloat162float(h));
    __nv_bfloat16* row = bt + (size_t)n * KV;
    row[k]        = h;
    row[384 + k]  = h;
    row[768 + k]  = l;
}

// -------------------- GEMM: C[M x N] = A'[M x 1152] @ B'[1152 x N] + bias --
// 3-stage cp.async pipeline, K chunk 64, block 256x128, warp tile 64x64.
// grid = (N/GBN, MTILES): consecutive CTAs share the A tile -> L2 reuse.
__global__ __launch_bounds__(256, 1)
void gemm_bf16x3_kernel(const __nv_bfloat16* __restrict__ Ab,
                        const __nv_bfloat16* __restrict__ Bt,
                        const float* __restrict__ bias,
                        float* __restrict__ C, int ldc)
{
    extern __shared__ char smem[];
    const uint32_t s0 = smem_u32(smem);

    const int tid  = threadIdx.x;
    const int wid  = tid >> 5;
    const int lane = tid & 31;
    const int wm   = wid >> 1;          // 0..3 (M)
    const int wn   = wid & 1;           // 0..1 (N)
    const int bn   = blockIdx.x * GBN;
    const int bm   = blockIdx.y * GBM;

    const int lrow = tid >> 3;          // 0..31
    const int seg  = tid & 7;           // 16B segment within 128B row

    float acc[4][8][4];
#pragma unroll
    for (int i = 0; i < 4; ++i)
#pragma unroll
        for (int j = 0; j < 8; ++j)
#pragma unroll
            for (int q = 0; q < 4; ++q) acc[i][j][q] = 0.f;

    // ldmatrix lane addressing
    const int a_r  = (lane & 7) + ((lane >> 3) & 1) * 8;
    const int a_cb = (lane >> 4) * 16;
    const int b_r  = (lane & 7) + ((lane >> 4) & 1) * 8;
    const int b_cb = ((lane >> 3) & 1) * 16;

    auto issue = [&](int kc, int stg) {
        const int kp  = kc * GKC;
        const int src = (kp < 768) ? kp : (kp - 768);
        const uint32_t sa = s0 + stg * STG_B;
        const uint32_t sbb = sa + A_ST;
#pragma unroll
        for (int i = 0; i < 8; ++i) {
            int r = lrow + i * 32;
            cp16(sa + r * ROWB + seg * 16,
                 Ab + (size_t)(bm + r) * 768 + src + seg * 8);
        }
#pragma unroll
        for (int i = 0; i < 4; ++i) {
            int r = lrow + i * 32;
            cp16(sbb + r * ROWB + seg * 16,
                 Bt + (size_t)(bn + r) * KV + kp + seg * 8);
        }
        cp_commit();
    };

    issue(0, 0);
    issue(1, 1);

    for (int kc = 0; kc < NCH; ++kc) {
        if (kc < NCH - 1)
            asm volatile("cp.async.wait_group 1;" ::: "memory");
        else
            asm volatile("cp.async.wait_group 0;" ::: "memory");
        __syncthreads();

        if (kc + 2 < NCH) issue(kc + 2, (kc + 2) % NSTG);

        const uint32_t sa = s0 + (kc % NSTG) * STG_B;
        const uint32_t abase = sa + (wm * 64 + a_r) * ROWB + a_cb;
        const uint32_t bbase = sa + A_ST + (wn * 64 + b_r) * ROWB + b_cb;

#pragma unroll
        for (int ks = 0; ks < 4; ++ks) {
            const int kb = ks * 32;     // 16 bf16 = 32 bytes
            uint32_t af[4][4];
#pragma unroll
            for (int fm = 0; fm < 4; ++fm)
                ldsm4(af[fm], abase + fm * 16 * ROWB + kb);
            uint32_t bfr[8][2];
#pragma unroll
            for (int j = 0; j < 4; ++j) {
                uint32_t r[4];
                ldsm4(r, bbase + j * 16 * ROWB + kb);
                bfr[2 * j][0] = r[0]; bfr[2 * j][1] = r[1];
                bfr[2 * j + 1][0] = r[2]; bfr[2 * j + 1][1] = r[3];
            }
#pragma unroll
            for (int fm = 0; fm < 4; ++fm)
#pragma unroll
                for (int fn = 0; fn < 8; ++fn)
                    mma16816(acc[fm][fn], af[fm], bfr[fn]);
        }
    }

    // Epilogue: direct frag stores + bias
#pragma unroll
    for (int fm = 0; fm < 4; ++fm) {
        const int row0 = bm + wm * 64 + fm * 16 + (lane >> 2);
#pragma unroll
        for (int fn = 0; fn < 8; ++fn) {
            const int col = bn + wn * 64 + fn * 8 + (lane & 3) * 2;
            const float b0 = __ldg(&bias[col]);
            const float b1 = __ldg(&bias[col + 1]);
            float2 o0 = make_float2(acc[fm][fn][0] + b0, acc[fm][fn][1] + b1);
            float2 o1 = make_float2(acc[fm][fn][2] + b0, acc[fm][fn][3] + b1);
            *reinterpret_cast<float2*>(&C[(size_t)row0 * ldc + col])       = o0;
            *reinterpret_cast<float2*>(&C[(size_t)(row0 + 8) * ldc + col]) = o1;
        }
    }
}

// -------------------- attention: 8 warps, deferred normalization -----------
__global__ __launch_bounds__(256)
void attn_kernel(const float* __restrict__ relb,
                 const float* __restrict__ mask)
{
    const int b = blockIdx.x;
    const int h = blockIdx.y;

    __shared__ float q_s[NTOK][33];
    __shared__ float k_s[NTOK][33];
    __shared__ float v_s[NTOK][33];
    __shared__ float p_s[8][64];

    const int tid = threadIdx.x;
    const float* base = g_qkv + (size_t)b * NTOK * QKVC + h * DHEAD;

    for (int idx = tid; idx < NTOK * DHEAD; idx += 256) {
        const int n = idx >> 5;
        const int d = idx & 31;
        const float* src = base + (size_t)n * QKVC + d;
        q_s[n][d] = src[0];
        k_s[n][d] = src[CDIM];
        v_s[n][d] = src[2 * CDIM];
    }
    __syncthreads();

    const int   w    = b & (NWIN - 1);
    const int   warp = tid >> 5;
    const int   lane = tid & 31;
    const float scale = 0.17677669529663687f;

    const float* rb = relb + (size_t)h * NTOK * NTOK;
    const float* mk = mask + (size_t)w * NTOK * NTOK;

    for (int n = warp; n < NTOK; n += 8) {
        const int  m0 = lane;
        const int  m1 = lane + 32;
        const bool v1 = (m1 < NTOK);
        const int  m1c = v1 ? m1 : 0;

        float acc0 = 0.f, acc1 = 0.f;
#pragma unroll
        for (int d = 0; d < DHEAD; ++d) {
            const float qv = q_s[n][d];
            acc0 += qv * k_s[m0][d];
            acc1 += qv * k_s[m1c][d];
        }
        acc0 = acc0 * scale + rb[n * NTOK + m0] + mk[n * NTOK + m0];
        acc1 = v1 ? (acc1 * scale + rb[n * NTOK + m1] + mk[n * NTOK + m1])
                  : -1e30f;

        float mx = fmaxf(acc0, acc1);
#pragma unroll
        for (int o = 16; o; o >>= 1)
            mx = fmaxf(mx, __shfl_xor_sync(0xffffffffu, mx, o));

        const float e0 = __expf(acc0 - mx);
        const float e1 = v1 ? __expf(acc1 - mx) : 0.f;
        float s = e0 + e1;
#pragma unroll
        for (int o = 16; o; o >>= 1)
            s += __shfl_xor_sync(0xffffffffu, s, o);
        const float inv = 1.f / s;

        p_s[warp][m0] = e0;
        if (v1) p_s[warp][m1] = e1;
        __syncwarp();

        float o = 0.f;
#pragma unroll
        for (int m = 0; m < NTOK; ++m)
            o += p_s[warp][m] * v_s[m][lane];
        o *= inv;

        const size_t row = (size_t)b * NTOK + n;
        __nv_bfloat16 hv = __float2bfloat16_rn(o);
        __nv_bfloat16 lv = __float2bfloat16_rn(o - __bfloat162float(hv));
        g_attbf[row * 768 + h * DHEAD + lane]       = hv;
        g_attbf[row * 768 + 384 + h * DHEAD + lane] = lv;
        __syncwarp();
    }
}

// ---------------------------------------------------------------------------
extern "C" void kernel_launch(void* const* d_in, const int* in_sizes, int n_in,
                              void* d_out, int out_size)
{
    const float* x      = (const float*)d_in[0];
    const float* mask   = (const float*)d_in[1];
    const float* qkv_w  = (const float*)d_in[2];
    const float* qkv_b  = (const float*)d_in[3];
    const float* proj_w = (const float*)d_in[4];
    const float* proj_b = (const float*)d_in[5];
    const float* relb   = (const float*)d_in[6];
    float* out = (float*)d_out;

    void *p_xbf, *p_attbf, *p_qkv, *p_wqt, *p_wpt;
    cudaGetSymbolAddress(&p_xbf,   g_xbf);
    cudaGetSymbolAddress(&p_attbf, g_attbf);
    cudaGetSymbolAddress(&p_qkv,   g_qkv);
    cudaGetSymbolAddress(&p_wqt,   g_wqt);
    cudaGetSymbolAddress(&p_wpt,   g_wpt);

    cudaFuncSetAttribute(gemm_bf16x3_kernel,
                         cudaFuncAttributeMaxDynamicSharedMemorySize, SMEM_GEMM);

    // 1) preps
    {
        size_t tx = (size_t)MROWS * (KDIM / 4);
        prep_x_kernel<<<(unsigned)((tx + 255) / 256), 256>>>(x, (__nv_bfloat16*)p_xbf);
        int tq = KDIM * QKVC;
        prep_w_kernel<<<(tq + 255) / 256, 256>>>(qkv_w, (__nv_bfloat16*)p_wqt, QKVC);
        int tp = KDIM * CDIM;
        prep_w_kernel<<<(tp + 255) / 256, 256>>>(proj_w, (__nv_bfloat16*)p_wpt, CDIM);
    }
    // 2) QKV GEMM (N-tiles fastest -> A tile L2 reuse)
    {
        dim3 grid(QKVC / GBN, MTILES);    // 9 x 392
        gemm_bf16x3_kernel<<<grid, 256, SMEM_GEMM>>>(
            (const __nv_bfloat16*)p_xbf, (const __nv_bfloat16*)p_wqt,
            qkv_b, (float*)p_qkv, QKVC);
    }
    // 3) windowed attention
    {
        dim3 grid(BWIN, HNUM);
        attn_kernel<<<grid, 256>>>(relb, mask);
    }
    // 4) projection GEMM
    {
        dim3 grid(CDIM / GBN, MTILES);    // 3 x 392
        gemm_bf16x3_kernel<<<grid, 256, SMEM_GEMM>>>(
            (const __nv_bfloat16*)p_attbf, (const __nv_bfloat16*)p_wpt,
            proj_b, out, CDIM);
    }
}

// round 5
// speedup vs baseline: 2.7628x; 1.4430x over previous
#include <cuda_runtime.h>
#include <cuda_bf16.h>
#include <cstdint>

// Problem constants: B_=2048, N=49, C=384, H=12, d=32, nW=64
#define BWIN   2048
#define NTOK   49
#define CDIM   384
#define HNUM   12
#define DHEAD  32
#define NWIN   64
#define MROWS  (BWIN * NTOK)     // 100352
#define QKVC   (3 * CDIM)        // 1152
#define KDIM   384
#define KV     1152              // virtual K = 3 * 384 (bf16x3 split)

// GEMM tiling: 128x128 tile, 128 threads, 2 CTAs/SM
#define GBM   128
#define GBN   128
#define GKC   64                 // k per chunk (64 bf16 = 128B row)
#define NCH   (KV / GKC)         // 18
#define NSTG  3
#define ROWB  144                // smem row stride (128B data + 16B pad)
#define A_ST  (GBM * ROWB)       // 18432
#define B_ST  (GBN * ROWB)       // 18432
#define STG_B (A_ST + B_ST)      // 36864
#define SMEM_GEMM (NSTG * STG_B) // 110592
#define MTILES (MROWS / GBM)     // 784

// -------------------- device scratch (no runtime alloc allowed) -----------
__device__ __align__(16) __nv_bfloat16 g_xbf [(size_t)MROWS * 768];  // x hi|lo
__device__ __align__(16) __nv_bfloat16 g_attbf[(size_t)MROWS * 768]; // attn-out hi|lo
__device__ __align__(16) float         g_qkv [(size_t)MROWS * QKVC];
__device__ __align__(16) __nv_bfloat16 g_wqt [(size_t)QKVC * KV];    // [1152][1152]
__device__ __align__(16) __nv_bfloat16 g_wpt [(size_t)CDIM * KV];    // [384][1152]

// -------------------- PTX helpers -----------------------------------------
__device__ __forceinline__ uint32_t smem_u32(const void* p) {
    uint32_t a;
    asm("{ .reg .u64 t; cvta.to.shared.u64 t, %1; cvt.u32.u64 %0, t; }"
        : "=r"(a) : "l"(p));
    return a;
}
__device__ __forceinline__ void cp16(uint32_t s, const void* g) {
    asm volatile("cp.async.cg.shared.global [%0], [%1], 16;" :: "r"(s), "l"(g));
}
__device__ __forceinline__ void cp_commit() {
    asm volatile("cp.async.commit_group;" ::: "memory");
}
__device__ __forceinline__ void ldsm4(uint32_t* r, uint32_t addr) {
    asm volatile("ldmatrix.sync.aligned.m8n8.x4.shared.b16 {%0,%1,%2,%3}, [%4];"
        : "=r"(r[0]), "=r"(r[1]), "=r"(r[2]), "=r"(r[3]) : "r"(addr));
}
__device__ __forceinline__ void mma16816(float* d, const uint32_t* a, const uint32_t* b) {
    asm volatile(
        "mma.sync.aligned.m16n8k16.row.col.f32.bf16.bf16.f32 "
        "{%0,%1,%2,%3}, {%4,%5,%6,%7}, {%8,%9}, {%0,%1,%2,%3};"
        : "+f"(d[0]), "+f"(d[1]), "+f"(d[2]), "+f"(d[3])
        : "r"(a[0]), "r"(a[1]), "r"(a[2]), "r"(a[3]), "r"(b[0]), "r"(b[1]));
}

// -------------------- prep: x fp32 -> bf16 hi/lo [M,768] -------------------
__global__ __launch_bounds__(256)
void prep_x_kernel(const float* __restrict__ x, __nv_bfloat16* __restrict__ dst)
{
    size_t id = (size_t)blockIdx.x * 256 + threadIdx.x;
    if (id >= (size_t)MROWS * (KDIM / 4)) return;
    size_t row = id / (KDIM / 4);
    int c4 = (int)(id % (KDIM / 4)) * 4;
    float4 v = *reinterpret_cast<const float4*>(&x[row * KDIM + c4]);
    __nv_bfloat16 h[4], l[4];
    h[0] = __float2bfloat16_rn(v.x); l[0] = __float2bfloat16_rn(v.x - __bfloat162float(h[0]));
    h[1] = __float2bfloat16_rn(v.y); l[1] = __float2bfloat16_rn(v.y - __bfloat162float(h[1]));
    h[2] = __float2bfloat16_rn(v.z); l[2] = __float2bfloat16_rn(v.z - __bfloat162float(h[2]));
    h[3] = __float2bfloat16_rn(v.w); l[3] = __float2bfloat16_rn(v.w - __bfloat162float(h[3]));
    *reinterpret_cast<uint2*>(&dst[row * 768 + c4])       = *reinterpret_cast<uint2*>(h);
    *reinterpret_cast<uint2*>(&dst[row * 768 + 384 + c4]) = *reinterpret_cast<uint2*>(l);
}

// -------------------- prep: W [384,N] fp32 -> Bt [N][1152] bf16 ------------
__global__ __launch_bounds__(256)
void prep_w_kernel(const float* __restrict__ w, __nv_bfloat16* __restrict__ bt, int N)
{
    int id = blockIdx.x * 256 + threadIdx.x;
    if (id >= KDIM * N) return;
    int k = id / N, n = id % N;
    float a = w[(size_t)k * N + n];
    __nv_bfloat16 h = __float2bfloat16_rn(a);
    __nv_bfloat16 l = __float2bfloat16_rn(a - __bfloat162float(h));
    __nv_bfloat16* row = bt + (size_t)n * KV;
    row[k]        = h;
    row[384 + k]  = h;
    row[768 + k]  = l;
}

// -------------------- GEMM: 128x128 tile, 128 threads, 2 CTAs/SM ----------
__global__ __launch_bounds__(128, 2)
void gemm_bf16x3_kernel(const __nv_bfloat16* __restrict__ Ab,
                        const __nv_bfloat16* __restrict__ Bt,
                        const float* __restrict__ bias,
                        float* __restrict__ C, int ldc)
{
    extern __shared__ char smem[];
    const uint32_t s0 = smem_u32(smem);

    const int tid  = threadIdx.x;
    const int wid  = tid >> 5;
    const int lane = tid & 31;
    const int wm   = wid >> 1;          // 0..1 (M)
    const int wn   = wid & 1;           // 0..1 (N)
    const int bn   = blockIdx.x * GBN;
    const int bm   = blockIdx.y * GBM;

    const int lrow = tid >> 3;          // 0..15
    const int seg  = tid & 7;

    float acc[4][8][4];
#pragma unroll
    for (int i = 0; i < 4; ++i)
#pragma unroll
        for (int j = 0; j < 8; ++j)
#pragma unroll
            for (int q = 0; q < 4; ++q) acc[i][j][q] = 0.f;

    const int a_r  = (lane & 7) + ((lane >> 3) & 1) * 8;
    const int a_cb = (lane >> 4) * 16;
    const int b_r  = (lane & 7) + ((lane >> 4) & 1) * 8;
    const int b_cb = ((lane >> 3) & 1) * 16;

    auto issue = [&](int kc, int stg) {
        const int kp  = kc * GKC;
        const int src = (kp < 768) ? kp : (kp - 768);
        const uint32_t sa  = s0 + stg * STG_B;
        const uint32_t sbb = sa + A_ST;
#pragma unroll
        for (int i = 0; i < 8; ++i) {
            int r = lrow + i * 16;
            cp16(sa + r * ROWB + seg * 16,
                 Ab + (size_t)(bm + r) * 768 + src + seg * 8);
        }
#pragma unroll
        for (int i = 0; i < 8; ++i) {
            int r = lrow + i * 16;
            cp16(sbb + r * ROWB + seg * 16,
                 Bt + (size_t)(bn + r) * KV + kp + seg * 8);
        }
        cp_commit();
    };

    issue(0, 0);
    issue(1, 1);

    for (int kc = 0; kc < NCH; ++kc) {
        if (kc < NCH - 1)
            asm volatile("cp.async.wait_group 1;" ::: "memory");
        else
            asm volatile("cp.async.wait_group 0;" ::: "memory");
        __syncthreads();

        if (kc + 2 < NCH) issue(kc + 2, (kc + 2) % NSTG);

        const uint32_t sa = s0 + (kc % NSTG) * STG_B;
        const uint32_t abase = sa + (wm * 64 + a_r) * ROWB + a_cb;
        const uint32_t bbase = sa + A_ST + (wn * 64 + b_r) * ROWB + b_cb;

#pragma unroll
        for (int ks = 0; ks < 4; ++ks) {
            const int kb = ks * 32;
            uint32_t af[4][4];
#pragma unroll
            for (int fm = 0; fm < 4; ++fm)
                ldsm4(af[fm], abase + fm * 16 * ROWB + kb);
            uint32_t bfr[8][2];
#pragma unroll
            for (int j = 0; j < 4; ++j) {
                uint32_t r[4];
                ldsm4(r, bbase + j * 16 * ROWB + kb);
                bfr[2 * j][0] = r[0]; bfr[2 * j][1] = r[1];
                bfr[2 * j + 1][0] = r[2]; bfr[2 * j + 1][1] = r[3];
            }
#pragma unroll
            for (int fm = 0; fm < 4; ++fm)
#pragma unroll
                for (int fn = 0; fn < 8; ++fn)
                    mma16816(acc[fm][fn], af[fm], bfr[fn]);
        }
    }

#pragma unroll
    for (int fm = 0; fm < 4; ++fm) {
        const int row0 = bm + wm * 64 + fm * 16 + (lane >> 2);
#pragma unroll
        for (int fn = 0; fn < 8; ++fn) {
            const int col = bn + wn * 64 + fn * 8 + (lane & 3) * 2;
            const float b0 = __ldg(&bias[col]);
            const float b1 = __ldg(&bias[col + 1]);
            float2 o0 = make_float2(acc[fm][fn][0] + b0, acc[fm][fn][1] + b1);
            float2 o1 = make_float2(acc[fm][fn][2] + b0, acc[fm][fn][3] + b1);
            *reinterpret_cast<float2*>(&C[(size_t)row0 * ldc + col])       = o0;
            *reinterpret_cast<float2*>(&C[(size_t)(row0 + 8) * ldc + col]) = o1;
        }
    }
}

// -------------------- attention: single pass, V-reuse ----------------------
// One block per (b,h). 8 warps; warp w owns query rows n = w, w+8, ... (<=7).
// Lanes = key index (m0=lane, m1=lane+32). All rows processed together so
// each V row is read once per warp (not once per query row).
#define QPAD 36      // floats per row (144B) — conflict-free for float4 row reads
#define PPAD 52      // p row floats (13 float4 groups; 49..51 zero pad)

__global__ __launch_bounds__(256)
void attn_kernel(const float* __restrict__ relb,
                 const float* __restrict__ mask)
{
    const int b = blockIdx.x;
    const int h = blockIdx.y;

    __shared__ float q_s[NTOK][QPAD];
    __shared__ float k_s[NTOK][QPAD];
    __shared__ float v_s[52][QPAD];
    __shared__ float p_s[8][7][PPAD];

    const int tid  = threadIdx.x;
    const int warp = tid >> 5;
    const int lane = tid & 31;

    // ---- stage q,k,v (float4) ----
    const float* base = g_qkv + (size_t)b * NTOK * QKVC + h * DHEAD;
    for (int idx = tid; idx < NTOK * 8; idx += 256) {
        const int n = idx >> 3, d4 = (idx & 7) * 4;
        const float* src = base + (size_t)n * QKVC + d4;
        *reinterpret_cast<float4*>(&q_s[n][d4]) =
            *reinterpret_cast<const float4*>(src);
        *reinterpret_cast<float4*>(&k_s[n][d4]) =
            *reinterpret_cast<const float4*>(src + CDIM);
    }
    for (int idx = tid; idx < 52 * 8; idx += 256) {
        const int n = idx >> 3, d4 = (idx & 7) * 4;
        float4 v = (n < NTOK)
            ? *reinterpret_cast<const float4*>(base + (size_t)n * QKVC + 2 * CDIM + d4)
            : make_float4(0.f, 0.f, 0.f, 0.f);
        *reinterpret_cast<float4*>(&v_s[n][d4]) = v;
    }
    // zero p pad columns (49..51)
    if (tid < 8 * 7) {
        p_s[tid / 7][tid % 7][49] = 0.f;
        p_s[tid / 7][tid % 7][50] = 0.f;
        p_s[tid / 7][tid % 7][51] = 0.f;
    }
    __syncthreads();

    const int   w     = b & (NWIN - 1);
    const float scale = 0.17677669529663687f;
    const float* rb = relb + (size_t)h * NTOK * NTOK;
    const float* mk = mask + (size_t)w * NTOK * NTOK;

    const int  m0  = lane;
    const int  m1  = lane + 32;
    const bool v1  = (m1 < NTOK);
    const int  m1c = v1 ? m1 : 0;

    int  nr[7];
    bool nv[7];
#pragma unroll
    for (int r = 0; r < 7; ++r) {
        int n = warp + 8 * r;
        nv[r] = (n < NTOK);
        nr[r] = nv[r] ? n : 0;
    }

    // ---- QK^T: 7 rows x 2 key cols per lane ----
    float acc0[7], acc1[7];
#pragma unroll
    for (int r = 0; r < 7; ++r) { acc0[r] = 0.f; acc1[r] = 0.f; }

#pragma unroll
    for (int d4 = 0; d4 < 8; ++d4) {
        const float4 k0 = *reinterpret_cast<const float4*>(&k_s[m0][d4 * 4]);
        const float4 k1 = *reinterpret_cast<const float4*>(&k_s[m1c][d4 * 4]);
#pragma unroll
        for (int r = 0; r < 7; ++r) {
            const float4 q = *reinterpret_cast<const float4*>(&q_s[nr[r]][d4 * 4]);
            acc0[r] += q.x * k0.x + q.y * k0.y + q.z * k0.z + q.w * k0.w;
            acc1[r] += q.x * k1.x + q.y * k1.y + q.z * k1.z + q.w * k1.w;
        }
    }

    // ---- softmax (7 rows interleaved for ILP) ----
    float inv[7];
#pragma unroll
    for (int r = 0; r < 7; ++r) {
        float l0 = acc0[r] * scale + rb[nr[r] * NTOK + m0] + mk[nr[r] * NTOK + m0];
        float l1 = v1 ? (acc1[r] * scale + rb[nr[r] * NTOK + m1] + mk[nr[r] * NTOK + m1])
                      : -1e30f;
        float mx = fmaxf(l0, l1);
#pragma unroll
        for (int o = 16; o; o >>= 1)
            mx = fmaxf(mx, __shfl_xor_sync(0xffffffffu, mx, o));
        const float e0 = __expf(l0 - mx);
        const float e1 = v1 ? __expf(l1 - mx) : 0.f;
        float s = e0 + e1;
#pragma unroll
        for (int o = 16; o; o >>= 1)
            s += __shfl_xor_sync(0xffffffffu, s, o);
        inv[r] = 1.f / s;
        p_s[warp][r][m0] = e0;
        if (v1) p_s[warp][r][m1] = e1;
    }
    __syncwarp();

    // ---- PV: each V row read once per warp; p as float4 broadcasts ----
    float out[7];
#pragma unroll
    for (int r = 0; r < 7; ++r) out[r] = 0.f;

#pragma unroll
    for (int m4 = 0; m4 < 13; ++m4) {
        const int m = m4 * 4;
        const float vv0 = v_s[m + 0][lane];
        const float vv1 = v_s[m + 1][lane];
        const float vv2 = v_s[m + 2][lane];
        const float vv3 = v_s[m + 3][lane];
#pragma unroll
        for (int r = 0; r < 7; ++r) {
            const float4 p = *reinterpret_cast<const float4*>(&p_s[warp][r][m]);
            out[r] += p.x * vv0 + p.y * vv1 + p.z * vv2 + p.w * vv3;
        }
    }

    // ---- write hi/lo bf16 ----
#pragma unroll
    for (int r = 0; r < 7; ++r) {
        if (!nv[r]) continue;
        const float o = out[r] * inv[r];
        const size_t row = (size_t)b * NTOK + nr[r];
        __nv_bfloat16 hv = __float2bfloat16_rn(o);
        __nv_bfloat16 lv = __float2bfloat16_rn(o - __bfloat162float(hv));
        g_attbf[row * 768 + h * DHEAD + lane]       = hv;
        g_attbf[row * 768 + 384 + h * DHEAD + lane] = lv;
    }
}

// ---------------------------------------------------------------------------
extern "C" void kernel_launch(void* const* d_in, const int* in_sizes, int n_in,
                              void* d_out, int out_size)
{
    const float* x      = (const float*)d_in[0];
    const float* mask   = (const float*)d_in[1];
    const float* qkv_w  = (const float*)d_in[2];
    const float* qkv_b  = (const float*)d_in[3];
    const float* proj_w = (const float*)d_in[4];
    const float* proj_b = (const float*)d_in[5];
    const float* relb   = (const float*)d_in[6];
    float* out = (float*)d_out;

    void *p_xbf, *p_attbf, *p_qkv, *p_wqt, *p_wpt;
    cudaGetSymbolAddress(&p_xbf,   g_xbf);
    cudaGetSymbolAddress(&p_attbf, g_attbf);
    cudaGetSymbolAddress(&p_qkv,   g_qkv);
    cudaGetSymbolAddress(&p_wqt,   g_wqt);
    cudaGetSymbolAddress(&p_wpt,   g_wpt);

    cudaFuncSetAttribute(gemm_bf16x3_kernel,
                         cudaFuncAttributeMaxDynamicSharedMemorySize, SMEM_GEMM);

    // 1) preps
    {
        size_t tx = (size_t)MROWS * (KDIM / 4);
        prep_x_kernel<<<(unsigned)((tx + 255) / 256), 256>>>(x, (__nv_bfloat16*)p_xbf);
        int tq = KDIM * QKVC;
        prep_w_kernel<<<(tq + 255) / 256, 256>>>(qkv_w, (__nv_bfloat16*)p_wqt, QKVC);
        int tp = KDIM * CDIM;
        prep_w_kernel<<<(tp + 255) / 256, 256>>>(proj_w, (__nv_bfloat16*)p_wpt, CDIM);
    }
    // 2) QKV GEMM
    {
        dim3 grid(QKVC / GBN, MTILES);    // 9 x 784
        gemm_bf16x3_kernel<<<grid, 128, SMEM_GEMM>>>(
            (const __nv_bfloat16*)p_xbf, (const __nv_bfloat16*)p_wqt,
            qkv_b, (float*)p_qkv, QKVC);
    }
    // 3) windowed attention
    {
        dim3 grid(BWIN, HNUM);
        attn_kernel<<<grid, 256>>>(relb, mask);
    }
    // 4) projection GEMM
    {
        dim3 grid(CDIM / GBN, MTILES);    // 3 x 784
        gemm_bf16x3_kernel<<<grid, 128, SMEM_GEMM>>>(
            (const __nv_bfloat16*)p_attbf, (const __nv_bfloat16*)p_wpt,
            proj_b, out, CDIM);
    }
}

// round 6
// speedup vs baseline: 2.7965x; 1.0122x over previous
#include <cuda_runtime.h>
#include <cuda_bf16.h>
#include <cstdint>

// Problem constants: B_=2048, N=49, C=384, H=12, d=32, nW=64
#define BWIN   2048
#define NTOK   49
#define CDIM   384
#define HNUM   12
#define DHEAD  32
#define NWIN   64
#define MROWS  (BWIN * NTOK)     // 100352
#define QKVC   (3 * CDIM)        // 1152
#define KDIM   384
#define KV     1152              // virtual K = 3 * 384 (bf16x3 split)
#define NN     (NTOK * NTOK)     // 2401

// GEMM tiling: 128x128 tile, 256 threads (8 warps, warp tile 32x64), 2 CTAs/SM
#define GBM   128
#define GBN   128
#define GKC   64                 // k per chunk (64 bf16 = 128B row)
#define NCH   (KV / GKC)         // 18
#define NSTG  3
#define ROWB  144                // smem row stride (128B data + 16B pad)
#define A_ST  (GBM * ROWB)       // 18432
#define B_ST  (GBN * ROWB)       // 18432
#define STG_B (A_ST + B_ST)      // 36864
#define SMEM_GEMM (NSTG * STG_B) // 110592
#define MTILES (MROWS / GBM)     // 784

// -------------------- device scratch (no runtime alloc allowed) -----------
__device__ __align__(16) __nv_bfloat16 g_xbf [(size_t)MROWS * 768];  // x hi|lo
__device__ __align__(16) __nv_bfloat16 g_attbf[(size_t)MROWS * 768]; // attn-out hi|lo
__device__ __align__(16) float         g_qkv [(size_t)MROWS * QKVC];
__device__ __align__(16) __nv_bfloat16 g_wqt [(size_t)QKVC * KV];
__device__ __align__(16) __nv_bfloat16 g_wpt [(size_t)CDIM * KV];
__device__ __align__(16) float         g_bias[(size_t)HNUM * NWIN * NN]; // rb+mask fused

// -------------------- PTX helpers -----------------------------------------
__device__ __forceinline__ uint32_t smem_u32(const void* p) {
    uint32_t a;
    asm("{ .reg .u64 t; cvta.to.shared.u64 t, %1; cvt.u32.u64 %0, t; }"
        : "=r"(a) : "l"(p));
    return a;
}
__device__ __forceinline__ void cp16(uint32_t s, const void* g) {
    asm volatile("cp.async.cg.shared.global [%0], [%1], 16;" :: "r"(s), "l"(g));
}
__device__ __forceinline__ void cp_commit() {
    asm volatile("cp.async.commit_group;" ::: "memory");
}
__device__ __forceinline__ void ldsm4(uint32_t* r, uint32_t addr) {
    asm volatile("ldmatrix.sync.aligned.m8n8.x4.shared.b16 {%0,%1,%2,%3}, [%4];"
        : "=r"(r[0]), "=r"(r[1]), "=r"(r[2]), "=r"(r[3]) : "r"(addr));
}
__device__ __forceinline__ void mma16816(float* d, const uint32_t* a, const uint32_t* b) {
    asm volatile(
        "mma.sync.aligned.m16n8k16.row.col.f32.bf16.bf16.f32 "
        "{%0,%1,%2,%3}, {%4,%5,%6,%7}, {%8,%9}, {%0,%1,%2,%3};"
        : "+f"(d[0]), "+f"(d[1]), "+f"(d[2]), "+f"(d[3])
        : "r"(a[0]), "r"(a[1]), "r"(a[2]), "r"(a[3]), "r"(b[0]), "r"(b[1]));
}

// -------------------- prep: x fp32 -> bf16 hi/lo [M,768] -------------------
__global__ __launch_bounds__(256)
void prep_x_kernel(const float* __restrict__ x, __nv_bfloat16* __restrict__ dst)
{
    size_t id = (size_t)blockIdx.x * 256 + threadIdx.x;
    if (id >= (size_t)MROWS * (KDIM / 4)) return;
    size_t row = id / (KDIM / 4);
    int c4 = (int)(id % (KDIM / 4)) * 4;
    float4 v = *reinterpret_cast<const float4*>(&x[row * KDIM + c4]);
    __nv_bfloat16 h[4], l[4];
    h[0] = __float2bfloat16_rn(v.x); l[0] = __float2bfloat16_rn(v.x - __bfloat162float(h[0]));
    h[1] = __float2bfloat16_rn(v.y); l[1] = __float2bfloat16_rn(v.y - __bfloat162float(h[1]));
    h[2] = __float2bfloat16_rn(v.z); l[2] = __float2bfloat16_rn(v.z - __bfloat162float(h[2]));
    h[3] = __float2bfloat16_rn(v.w); l[3] = __float2bfloat16_rn(v.w - __bfloat162float(h[3]));
    *reinterpret_cast<uint2*>(&dst[row * 768 + c4])       = *reinterpret_cast<uint2*>(h);
    *reinterpret_cast<uint2*>(&dst[row * 768 + 384 + c4]) = *reinterpret_cast<uint2*>(l);
}

// -------------------- prep: W [384,N] fp32 -> Bt [N][1152] bf16 ------------
__global__ __launch_bounds__(256)
void prep_w_kernel(const float* __restrict__ w, __nv_bfloat16* __restrict__ bt, int N)
{
    int id = blockIdx.x * 256 + threadIdx.x;
    if (id >= KDIM * N) return;
    int k = id / N, n = id % N;
    float a = w[(size_t)k * N + n];
    __nv_bfloat16 h = __float2bfloat16_rn(a);
    __nv_bfloat16 l = __float2bfloat16_rn(a - __bfloat162float(h));
    __nv_bfloat16* row = bt + (size_t)n * KV;
    row[k]        = h;
    row[384 + k]  = h;
    row[768 + k]  = l;
}

// -------------------- prep: fused bias table rb[h] + mask[w] ----------------
__global__ __launch_bounds__(256)
void prep_bias_kernel(const float* __restrict__ relb, const float* __restrict__ mask)
{
    size_t id = (size_t)blockIdx.x * 256 + threadIdx.x;
    if (id >= (size_t)HNUM * NWIN * NN) return;
    int i  = (int)(id % NN);
    int hw = (int)(id / NN);
    int w  = hw & (NWIN - 1);
    int h  = hw >> 6;
    g_bias[id] = relb[(size_t)h * NN + i] + mask[(size_t)w * NN + i];
}

// -------------------- GEMM: 128x128 tile, 256 threads, warp tile 32x64 -----
__global__ __launch_bounds__(256, 2)
void gemm_bf16x3_kernel(const __nv_bfloat16* __restrict__ Ab,
                        const __nv_bfloat16* __restrict__ Bt,
                        const float* __restrict__ bias,
                        float* __restrict__ C, int ldc)
{
    extern __shared__ char smem[];
    const uint32_t s0 = smem_u32(smem);

    const int tid  = threadIdx.x;
    const int wid  = tid >> 5;
    const int lane = tid & 31;
    const int wm   = wid >> 1;          // 0..3 (M, 32 rows each)
    const int wn   = wid & 1;           // 0..1 (N, 64 cols each)
    const int bn   = blockIdx.x * GBN;
    const int bm   = blockIdx.y * GBM;

    const int lrow = tid >> 3;          // 0..31
    const int seg  = tid & 7;

    float acc[2][8][4];
#pragma unroll
    for (int i = 0; i < 2; ++i)
#pragma unroll
        for (int j = 0; j < 8; ++j)
#pragma unroll
            for (int q = 0; q < 4; ++q) acc[i][j][q] = 0.f;

    const int a_r  = (lane & 7) + ((lane >> 3) & 1) * 8;
    const int a_cb = (lane >> 4) * 16;
    const int b_r  = (lane & 7) + ((lane >> 4) & 1) * 8;
    const int b_cb = ((lane >> 3) & 1) * 16;

    auto issue = [&](int kc, int stg) {
        const int kp  = kc * GKC;
        const int src = (kp < 768) ? kp : (kp - 768);
        const uint32_t sa  = s0 + stg * STG_B;
        const uint32_t sbb = sa + A_ST;
#pragma unroll
        for (int i = 0; i < 4; ++i) {
            int r = lrow + i * 32;
            cp16(sa + r * ROWB + seg * 16,
                 Ab + (size_t)(bm + r) * 768 + src + seg * 8);
        }
#pragma unroll
        for (int i = 0; i < 4; ++i) {
            int r = lrow + i * 32;
            cp16(sbb + r * ROWB + seg * 16,
                 Bt + (size_t)(bn + r) * KV + kp + seg * 8);
        }
        cp_commit();
    };

    issue(0, 0);
    issue(1, 1);

    for (int kc = 0; kc < NCH; ++kc) {
        if (kc < NCH - 1)
            asm volatile("cp.async.wait_group 1;" ::: "memory");
        else
            asm volatile("cp.async.wait_group 0;" ::: "memory");
        __syncthreads();

        if (kc + 2 < NCH) issue(kc + 2, (kc + 2) % NSTG);

        const uint32_t sa = s0 + (kc % NSTG) * STG_B;
        const uint32_t abase = sa + (wm * 32 + a_r) * ROWB + a_cb;
        const uint32_t bbase = sa + A_ST + (wn * 64 + b_r) * ROWB + b_cb;

#pragma unroll
        for (int ks = 0; ks < 4; ++ks) {
            const int kb = ks * 32;
            uint32_t af[2][4];
#pragma unroll
            for (int fm = 0; fm < 2; ++fm)
                ldsm4(af[fm], abase + fm * 16 * ROWB + kb);
            uint32_t bfr[8][2];
#pragma unroll
            for (int j = 0; j < 4; ++j) {
                uint32_t r[4];
                ldsm4(r, bbase + j * 16 * ROWB + kb);
                bfr[2 * j][0] = r[0]; bfr[2 * j][1] = r[1];
                bfr[2 * j + 1][0] = r[2]; bfr[2 * j + 1][1] = r[3];
            }
#pragma unroll
            for (int fm = 0; fm < 2; ++fm)
#pragma unroll
                for (int fn = 0; fn < 8; ++fn)
                    mma16816(acc[fm][fn], af[fm], bfr[fn]);
        }
    }

#pragma unroll
    for (int fm = 0; fm < 2; ++fm) {
        const int row0 = bm + wm * 32 + fm * 16 + (lane >> 2);
#pragma unroll
        for (int fn = 0; fn < 8; ++fn) {
            const int col = bn + wn * 64 + fn * 8 + (lane & 3) * 2;
            const float b0 = __ldg(&bias[col]);
            const float b1 = __ldg(&bias[col + 1]);
            float2 o0 = make_float2(acc[fm][fn][0] + b0, acc[fm][fn][1] + b1);
            float2 o1 = make_float2(acc[fm][fn][2] + b0, acc[fm][fn][3] + b1);
            *reinterpret_cast<float2*>(&C[(size_t)row0 * ldc + col])       = o0;
            *reinterpret_cast<float2*>(&C[(size_t)(row0 + 8) * ldc + col]) = o1;
        }
    }
}

// -------------------- attention: single pass, V-reuse, fused bias ----------
#define QPAD 36
#define PPAD 52

__global__ __launch_bounds__(256)
void attn_kernel()
{
    const int b = blockIdx.x;
    const int h = blockIdx.y;

    __shared__ float q_s[NTOK][QPAD];
    __shared__ float k_s[NTOK][QPAD];
    __shared__ float v_s[52][QPAD];
    __shared__ float p_s[8][7][PPAD];

    const int tid  = threadIdx.x;
    const int warp = tid >> 5;
    const int lane = tid & 31;

    const float* base = g_qkv + (size_t)b * NTOK * QKVC + h * DHEAD;
    for (int idx = tid; idx < NTOK * 8; idx += 256) {
        const int n = idx >> 3, d4 = (idx & 7) * 4;
        const float* src = base + (size_t)n * QKVC + d4;
        *reinterpret_cast<float4*>(&q_s[n][d4]) =
            *reinterpret_cast<const float4*>(src);
        *reinterpret_cast<float4*>(&k_s[n][d4]) =
            *reinterpret_cast<const float4*>(src + CDIM);
    }
    for (int idx = tid; idx < 52 * 8; idx += 256) {
        const int n = idx >> 3, d4 = (idx & 7) * 4;
        float4 v = (n < NTOK)
            ? *reinterpret_cast<const float4*>(base + (size_t)n * QKVC + 2 * CDIM + d4)
            : make_float4(0.f, 0.f, 0.f, 0.f);
        *reinterpret_cast<float4*>(&v_s[n][d4]) = v;
    }
    if (tid < 8 * 7) {
        p_s[tid / 7][tid % 7][49] = 0.f;
        p_s[tid / 7][tid % 7][50] = 0.f;
        p_s[tid / 7][tid % 7][51] = 0.f;
    }
    __syncthreads();

    const int   w     = b & (NWIN - 1);
    const float scale = 0.17677669529663687f;
    const float* bt = g_bias + ((size_t)h * NWIN + w) * NN;

    const int  m0  = lane;
    const int  m1  = lane + 32;
    const bool v1  = (m1 < NTOK);
    const int  m1c = v1 ? m1 : 0;

    int  nr[7];
    bool nv[7];
#pragma unroll
    for (int r = 0; r < 7; ++r) {
        int n = warp + 8 * r;
        nv[r] = (n < NTOK);
        nr[r] = nv[r] ? n : 0;
    }

    float acc0[7], acc1[7];
#pragma unroll
    for (int r = 0; r < 7; ++r) { acc0[r] = 0.f; acc1[r] = 0.f; }

#pragma unroll
    for (int d4 = 0; d4 < 8; ++d4) {
        const float4 k0 = *reinterpret_cast<const float4*>(&k_s[m0][d4 * 4]);
        const float4 k1 = *reinterpret_cast<const float4*>(&k_s[m1c][d4 * 4]);
#pragma unroll
        for (int r = 0; r < 7; ++r) {
            const float4 q = *reinterpret_cast<const float4*>(&q_s[nr[r]][d4 * 4]);
            acc0[r] += q.x * k0.x + q.y * k0.y + q.z * k0.z + q.w * k0.w;
            acc1[r] += q.x * k1.x + q.y * k1.y + q.z * k1.z + q.w * k1.w;
        }
    }

    float inv[7];
#pragma unroll
    for (int r = 0; r < 7; ++r) {
        float l0 = acc0[r] * scale + bt[nr[r] * NTOK + m0];
        float l1 = v1 ? (acc1[r] * scale + bt[nr[r] * NTOK + m1]) : -1e30f;
        float mx = fmaxf(l0, l1);
#pragma unroll
        for (int o = 16; o; o >>= 1)
            mx = fmaxf(mx, __shfl_xor_sync(0xffffffffu, mx, o));
        const float e0 = __expf(l0 - mx);
        const float e1 = v1 ? __expf(l1 - mx) : 0.f;
        float s = e0 + e1;
#pragma unroll
        for (int o = 16; o; o >>= 1)
            s += __shfl_xor_sync(0xffffffffu, s, o);
        inv[r] = 1.f / s;
        p_s[warp][r][m0] = e0;
        if (v1) p_s[warp][r][m1] = e1;
    }
    __syncwarp();

    float out[7];
#pragma unroll
    for (int r = 0; r < 7; ++r) out[r] = 0.f;

#pragma unroll
    for (int m4 = 0; m4 < 13; ++m4) {
        const int m = m4 * 4;
        const float vv0 = v_s[m + 0][lane];
        const float vv1 = v_s[m + 1][lane];
        const float vv2 = v_s[m + 2][lane];
        const float vv3 = v_s[m + 3][lane];
#pragma unroll
        for (int r = 0; r < 7; ++r) {
            const float4 p = *reinterpret_cast<const float4*>(&p_s[warp][r][m]);
            out[r] += p.x * vv0 + p.y * vv1 + p.z * vv2 + p.w * vv3;
        }
    }

#pragma unroll
    for (int r = 0; r < 7; ++r) {
        if (!nv[r]) continue;
        const float o = out[r] * inv[r];
        const size_t row = (size_t)b * NTOK + nr[r];
        __nv_bfloat16 hv = __float2bfloat16_rn(o);
        __nv_bfloat16 lv = __float2bfloat16_rn(o - __bfloat162float(hv));
        g_attbf[row * 768 + h * DHEAD + lane]       = hv;
        g_attbf[row * 768 + 384 + h * DHEAD + lane] = lv;
    }
}

// ---------------------------------------------------------------------------
extern "C" void kernel_launch(void* const* d_in, const int* in_sizes, int n_in,
                              void* d_out, int out_size)
{
    const float* x      = (const float*)d_in[0];
    const float* mask   = (const float*)d_in[1];
    const float* qkv_w  = (const float*)d_in[2];
    const float* qkv_b  = (const float*)d_in[3];
    const float* proj_w = (const float*)d_in[4];
    const float* proj_b = (const float*)d_in[5];
    const float* relb   = (const float*)d_in[6];
    float* out = (float*)d_out;

    void *p_xbf, *p_attbf, *p_qkv, *p_wqt, *p_wpt;
    cudaGetSymbolAddress(&p_xbf,   g_xbf);
    cudaGetSymbolAddress(&p_attbf, g_attbf);
    cudaGetSymbolAddress(&p_qkv,   g_qkv);
    cudaGetSymbolAddress(&p_wqt,   g_wqt);
    cudaGetSymbolAddress(&p_wpt,   g_wpt);

    cudaFuncSetAttribute(gemm_bf16x3_kernel,
                         cudaFuncAttributeMaxDynamicSharedMemorySize, SMEM_GEMM);

    // 1) preps
    {
        size_t tx = (size_t)MROWS * (KDIM / 4);
        prep_x_kernel<<<(unsigned)((tx + 255) / 256), 256>>>(x, (__nv_bfloat16*)p_xbf);
        int tq = KDIM * QKVC;
        prep_w_kernel<<<(tq + 255) / 256, 256>>>(qkv_w, (__nv_bfloat16*)p_wqt, QKVC);
        int tp = KDIM * CDIM;
        prep_w_kernel<<<(tp + 255) / 256, 256>>>(proj_w, (__nv_bfloat16*)p_wpt, CDIM);
        size_t tb = (size_t)HNUM * NWIN * NN;
        prep_bias_kernel<<<(unsigned)((tb + 255) / 256), 256>>>(relb, mask);
    }
    // 2) QKV GEMM
    {
        dim3 grid(QKVC / GBN, MTILES);    // 9 x 784
        gemm_bf16x3_kernel<<<grid, 256, SMEM_GEMM>>>(
            (const __nv_bfloat16*)p_xbf, (const __nv_bfloat16*)p_wqt,
            qkv_b, (float*)p_qkv, QKVC);
    }
    // 3) windowed attention
    {
        dim3 grid(BWIN, HNUM);
        attn_kernel<<<grid, 256>>>();
    }
    // 4) projection GEMM
    {
        dim3 grid(CDIM / GBN, MTILES);    // 3 x 784
        gemm_bf16x3_kernel<<<grid, 256, SMEM_GEMM>>>(
            (const __nv_bfloat16*)p_attbf, (const __nv_bfloat16*)p_wpt,
            proj_b, out, CDIM);
    }
}

// round 7
// speedup vs baseline: 3.1366x; 1.1216x over previous
#include <cuda_runtime.h>
#include <cuda_bf16.h>
#include <cstdint>

// Problem constants: B_=2048, N=49, C=384, H=12, d=32, nW=64
#define BWIN   2048
#define NTOK   49
#define CDIM   384
#define HNUM   12
#define DHEAD  32
#define NWIN   64
#define MROWS  (BWIN * NTOK)     // 100352
#define QKVC   (3 * CDIM)        // 1152
#define KDIM   384
#define KV     1152              // virtual K = 3 * 384 (bf16x3 split)

// GEMM tiling: 128x128 tile, 256 threads (8 warps, warp tile 32x64), 2 CTAs/SM
#define GBM   128
#define GBN   128
#define GKC   64
#define NSTG  3
#define ROWB  144
#define A_ST  (GBM * ROWB)
#define B_ST  (GBN * ROWB)
#define STG_B (A_ST + B_ST)
#define SMEM_GEMM (NSTG * STG_B)
#define MTILES (MROWS / GBM)     // 784

// prep_all block ranges
#define PX_BLKS 37632            // MROWS*96/256
#define WQ_BLKS 1728             // 442368/256
#define WP_BLKS 576              // 147456/256

// -------------------- device scratch --------------------------------------
__device__ __align__(16) __nv_bfloat16 g_xbf [(size_t)MROWS * 768];
__device__ __align__(16) __nv_bfloat16 g_attbf[(size_t)MROWS * 768];
__device__ __align__(16) float         g_qkv [(size_t)MROWS * QKVC];
__device__ __align__(16) __nv_bfloat16 g_wqt [(size_t)QKVC * KV];
__device__ __align__(16) __nv_bfloat16 g_wpt [(size_t)CDIM * KV];

// -------------------- PTX helpers -----------------------------------------
__device__ __forceinline__ uint32_t smem_u32(const void* p) {
    uint32_t a;
    asm("{ .reg .u64 t; cvta.to.shared.u64 t, %1; cvt.u32.u64 %0, t; }"
        : "=r"(a) : "l"(p));
    return a;
}
__device__ __forceinline__ void cp16(uint32_t s, const void* g) {
    asm volatile("cp.async.cg.shared.global [%0], [%1], 16;" :: "r"(s), "l"(g));
}
__device__ __forceinline__ void cp_commit() {
    asm volatile("cp.async.commit_group;" ::: "memory");
}
__device__ __forceinline__ void ldsm4(uint32_t* r, uint32_t addr) {
    asm volatile("ldmatrix.sync.aligned.m8n8.x4.shared.b16 {%0,%1,%2,%3}, [%4];"
        : "=r"(r[0]), "=r"(r[1]), "=r"(r[2]), "=r"(r[3]) : "r"(addr));
}
__device__ __forceinline__ void mma16816(float* d, const uint32_t* a, const uint32_t* b) {
    asm volatile(
        "mma.sync.aligned.m16n8k16.row.col.f32.bf16.bf16.f32 "
        "{%0,%1,%2,%3}, {%4,%5,%6,%7}, {%8,%9}, {%0,%1,%2,%3};"
        : "+f"(d[0]), "+f"(d[1]), "+f"(d[2]), "+f"(d[3])
        : "r"(a[0]), "r"(a[1]), "r"(a[2]), "r"(a[3]), "r"(b[0]), "r"(b[1]));
}

// -------------------- fused prep: x hi/lo + both weight layouts ------------
__global__ __launch_bounds__(256)
void prep_all_kernel(const float* __restrict__ x,
                     const float* __restrict__ qkv_w,
                     const float* __restrict__ proj_w)
{
    const int bid = blockIdx.x;
    const int tid = threadIdx.x;

    if (bid < PX_BLKS) {
        size_t id = (size_t)bid * 256 + tid;   // one per 4 cols of x
        size_t row = id / 96;
        int c4 = (int)(id % 96) * 4;
        float4 v = *reinterpret_cast<const float4*>(&x[row * KDIM + c4]);
        __nv_bfloat16 h[4], l[4];
        h[0] = __float2bfloat16_rn(v.x); l[0] = __float2bfloat16_rn(v.x - __bfloat162float(h[0]));
        h[1] = __float2bfloat16_rn(v.y); l[1] = __float2bfloat16_rn(v.y - __bfloat162float(h[1]));
        h[2] = __float2bfloat16_rn(v.z); l[2] = __float2bfloat16_rn(v.z - __bfloat162float(h[2]));
        h[3] = __float2bfloat16_rn(v.w); l[3] = __float2bfloat16_rn(v.w - __bfloat162float(h[3]));
        *reinterpret_cast<uint2*>(&g_xbf[row * 768 + c4])       = *reinterpret_cast<uint2*>(h);
        *reinterpret_cast<uint2*>(&g_xbf[row * 768 + 384 + c4]) = *reinterpret_cast<uint2*>(l);
    } else if (bid < PX_BLKS + WQ_BLKS) {
        int id = (bid - PX_BLKS) * 256 + tid;
        if (id < KDIM * QKVC) {
            int k = id / QKVC, n = id % QKVC;
            float a = qkv_w[(size_t)k * QKVC + n];
            __nv_bfloat16 h = __float2bfloat16_rn(a);
            __nv_bfloat16 l = __float2bfloat16_rn(a - __bfloat162float(h));
            __nv_bfloat16* row = g_wqt + (size_t)n * KV;
            row[k] = h; row[384 + k] = h; row[768 + k] = l;
        }
    } else {
        int id = (bid - PX_BLKS - WQ_BLKS) * 256 + tid;
        if (id < KDIM * CDIM) {
            int k = id / CDIM, n = id % CDIM;
            float a = proj_w[(size_t)k * CDIM + n];
            __nv_bfloat16 h = __float2bfloat16_rn(a);
            __nv_bfloat16 l = __float2bfloat16_rn(a - __bfloat162float(h));
            __nv_bfloat16* row = g_wpt + (size_t)n * KV;
            row[k] = h; row[384 + k] = h; row[768 + k] = l;
        }
    }
}

// -------------------- GEMM: variable chunk count ---------------------------
// nch=12: computes A_hi*Bh + A_lo*Bh = x*W_hi (2-term, for Q/K columns)
// nch=18: adds chunks 12..17 = A_hi*B_lo -> full bf16x3 (for V / proj)
__global__ __launch_bounds__(256, 2)
void gemm_bf16x3_kernel(const __nv_bfloat16* __restrict__ Ab,
                        const __nv_bfloat16* __restrict__ Bt,
                        const float* __restrict__ bias,
                        float* __restrict__ C, int ldc, int nch)
{
    extern __shared__ char smem[];
    const uint32_t s0 = smem_u32(smem);

    const int tid  = threadIdx.x;
    const int wid  = tid >> 5;
    const int lane = tid & 31;
    const int wm   = wid >> 1;
    const int wn   = wid & 1;
    const int bn   = blockIdx.x * GBN;
    const int bm   = blockIdx.y * GBM;

    const int lrow = tid >> 3;
    const int seg  = tid & 7;

    float acc[2][8][4];
#pragma unroll
    for (int i = 0; i < 2; ++i)
#pragma unroll
        for (int j = 0; j < 8; ++j)
#pragma unroll
            for (int q = 0; q < 4; ++q) acc[i][j][q] = 0.f;

    const int a_r  = (lane & 7) + ((lane >> 3) & 1) * 8;
    const int a_cb = (lane >> 4) * 16;
    const int b_r  = (lane & 7) + ((lane >> 4) & 1) * 8;
    const int b_cb = ((lane >> 3) & 1) * 16;

    auto issue = [&](int kc, int stg) {
        const int kp  = kc * GKC;
        const int src = (kp < 768) ? kp : (kp - 768);
        const uint32_t sa  = s0 + stg * STG_B;
        const uint32_t sbb = sa + A_ST;
#pragma unroll
        for (int i = 0; i < 4; ++i) {
            int r = lrow + i * 32;
            cp16(sa + r * ROWB + seg * 16,
                 Ab + (size_t)(bm + r) * 768 + src + seg * 8);
        }
#pragma unroll
        for (int i = 0; i < 4; ++i) {
            int r = lrow + i * 32;
            cp16(sbb + r * ROWB + seg * 16,
                 Bt + (size_t)(bn + r) * KV + kp + seg * 8);
        }
        cp_commit();
    };

    issue(0, 0);
    issue(1, 1);

    for (int kc = 0; kc < nch; ++kc) {
        if (kc < nch - 1)
            asm volatile("cp.async.wait_group 1;" ::: "memory");
        else
            asm volatile("cp.async.wait_group 0;" ::: "memory");
        __syncthreads();

        if (kc + 2 < nch) issue(kc + 2, (kc + 2) % NSTG);

        const uint32_t sa = s0 + (kc % NSTG) * STG_B;
        const uint32_t abase = sa + (wm * 32 + a_r) * ROWB + a_cb;
        const uint32_t bbase = sa + A_ST + (wn * 64 + b_r) * ROWB + b_cb;

#pragma unroll
        for (int ks = 0; ks < 4; ++ks) {
            const int kb = ks * 32;
            uint32_t af[2][4];
#pragma unroll
            for (int fm = 0; fm < 2; ++fm)
                ldsm4(af[fm], abase + fm * 16 * ROWB + kb);
            uint32_t bfr[8][2];
#pragma unroll
            for (int j = 0; j < 4; ++j) {
                uint32_t r[4];
                ldsm4(r, bbase + j * 16 * ROWB + kb);
                bfr[2 * j][0] = r[0]; bfr[2 * j][1] = r[1];
                bfr[2 * j + 1][0] = r[2]; bfr[2 * j + 1][1] = r[3];
            }
#pragma unroll
            for (int fm = 0; fm < 2; ++fm)
#pragma unroll
                for (int fn = 0; fn < 8; ++fn)
                    mma16816(acc[fm][fn], af[fm], bfr[fn]);
        }
    }

#pragma unroll
    for (int fm = 0; fm < 2; ++fm) {
        const int row0 = bm + wm * 32 + fm * 16 + (lane >> 2);
#pragma unroll
        for (int fn = 0; fn < 8; ++fn) {
            const int col = bn + wn * 64 + fn * 8 + (lane & 3) * 2;
            const float b0 = __ldg(&bias[col]);
            const float b1 = __ldg(&bias[col + 1]);
            float2 o0 = make_float2(acc[fm][fn][0] + b0, acc[fm][fn][1] + b1);
            float2 o1 = make_float2(acc[fm][fn][2] + b0, acc[fm][fn][3] + b1);
            *reinterpret_cast<float2*>(&C[(size_t)row0 * ldc + col])       = o0;
            *reinterpret_cast<float2*>(&C[(size_t)(row0 + 8) * ldc + col]) = o1;
        }
    }
}

// -------------------- attention: no-max softmax, V-reuse -------------------
#define QPAD 36
#define PPAD 52

__global__ __launch_bounds__(256)
void attn_kernel(const float* __restrict__ relb,
                 const float* __restrict__ mask)
{
    const int b = blockIdx.x;
    const int h = blockIdx.y;

    __shared__ float q_s[NTOK][QPAD];
    __shared__ float k_s[NTOK][QPAD];
    __shared__ float v_s[52][QPAD];
    __shared__ float p_s[8][7][PPAD];

    const int tid  = threadIdx.x;
    const int warp = tid >> 5;
    const int lane = tid & 31;

    const float* base = g_qkv + (size_t)b * NTOK * QKVC + h * DHEAD;
    for (int idx = tid; idx < NTOK * 8; idx += 256) {
        const int n = idx >> 3, d4 = (idx & 7) * 4;
        const float* src = base + (size_t)n * QKVC + d4;
        *reinterpret_cast<float4*>(&q_s[n][d4]) =
            *reinterpret_cast<const float4*>(src);
        *reinterpret_cast<float4*>(&k_s[n][d4]) =
            *reinterpret_cast<const float4*>(src + CDIM);
    }
    for (int idx = tid; idx < 52 * 8; idx += 256) {
        const int n = idx >> 3, d4 = (idx & 7) * 4;
        float4 v = (n < NTOK)
            ? *reinterpret_cast<const float4*>(base + (size_t)n * QKVC + 2 * CDIM + d4)
            : make_float4(0.f, 0.f, 0.f, 0.f);
        *reinterpret_cast<float4*>(&v_s[n][d4]) = v;
    }
    if (tid < 8 * 7) {
        p_s[tid / 7][tid % 7][49] = 0.f;
        p_s[tid / 7][tid % 7][50] = 0.f;
        p_s[tid / 7][tid % 7][51] = 0.f;
    }
    __syncthreads();

    const int   w     = b & (NWIN - 1);
    const float scale = 0.17677669529663687f;
    const float* rb = relb + (size_t)h * NTOK * NTOK;
    const float* mk = mask + (size_t)w * NTOK * NTOK;

    const int  m0  = lane;
    const int  m1  = lane + 32;
    const bool v1  = (m1 < NTOK);
    const int  m1c = v1 ? m1 : 0;

    int  nr[7];
    bool nv[7];
#pragma unroll
    for (int r = 0; r < 7; ++r) {
        int n = warp + 8 * r;
        nv[r] = (n < NTOK);
        nr[r] = nv[r] ? n : 0;
    }

    float acc0[7], acc1[7];
#pragma unroll
    for (int r = 0; r < 7; ++r) { acc0[r] = 0.f; acc1[r] = 0.f; }

#pragma unroll
    for (int d4 = 0; d4 < 8; ++d4) {
        const float4 k0 = *reinterpret_cast<const float4*>(&k_s[m0][d4 * 4]);
        const float4 k1 = *reinterpret_cast<const float4*>(&k_s[m1c][d4 * 4]);
#pragma unroll
        for (int r = 0; r < 7; ++r) {
            const float4 q = *reinterpret_cast<const float4*>(&q_s[nr[r]][d4 * 4]);
            acc0[r] += q.x * k0.x + q.y * k0.y + q.z * k0.z + q.w * k0.w;
            acc1[r] += q.x * k1.x + q.y * k1.y + q.z * k1.z + q.w * k1.w;
        }
    }

    // softmax without max-subtraction (logits are O(1); softmax shift-invariant)
    float inv[7];
#pragma unroll
    for (int r = 0; r < 7; ++r) {
        float l0 = acc0[r] * scale + rb[nr[r] * NTOK + m0] + mk[nr[r] * NTOK + m0];
        float l1 = v1 ? (acc1[r] * scale + rb[nr[r] * NTOK + m1] + mk[nr[r] * NTOK + m1])
                      : -1e30f;
        const float e0 = __expf(l0);
        const float e1 = v1 ? __expf(l1) : 0.f;
        float s = e0 + e1;
#pragma unroll
        for (int o = 16; o; o >>= 1)
            s += __shfl_xor_sync(0xffffffffu, s, o);
        inv[r] = 1.f / s;
        p_s[warp][r][m0] = e0;
        if (v1) p_s[warp][r][m1] = e1;
    }
    __syncwarp();

    float out[7];
#pragma unroll
    for (int r = 0; r < 7; ++r) out[r] = 0.f;

#pragma unroll
    for (int m4 = 0; m4 < 13; ++m4) {
        const int m = m4 * 4;
        const float vv0 = v_s[m + 0][lane];
        const float vv1 = v_s[m + 1][lane];
        const float vv2 = v_s[m + 2][lane];
        const float vv3 = v_s[m + 3][lane];
#pragma unroll
        for (int r = 0; r < 7; ++r) {
            const float4 p = *reinterpret_cast<const float4*>(&p_s[warp][r][m]);
            out[r] += p.x * vv0 + p.y * vv1 + p.z * vv2 + p.w * vv3;
        }
    }

#pragma unroll
    for (int r = 0; r < 7; ++r) {
        if (!nv[r]) continue;
        const float o = out[r] * inv[r];
        const size_t row = (size_t)b * NTOK + nr[r];
        __nv_bfloat16 hv = __float2bfloat16_rn(o);
        __nv_bfloat16 lv = __float2bfloat16_rn(o - __bfloat162float(hv));
        g_attbf[row * 768 + h * DHEAD + lane]       = hv;
        g_attbf[row * 768 + 384 + h * DHEAD + lane] = lv;
    }
}

// ---------------------------------------------------------------------------
extern "C" void kernel_launch(void* const* d_in, const int* in_sizes, int n_in,
                              void* d_out, int out_size)
{
    const float* x      = (const float*)d_in[0];
    const float* mask   = (const float*)d_in[1];
    const float* qkv_w  = (const float*)d_in[2];
    const float* qkv_b  = (const float*)d_in[3];
    const float* proj_w = (const float*)d_in[4];
    const float* proj_b = (const float*)d_in[5];
    const float* relb   = (const float*)d_in[6];
    float* out = (float*)d_out;

    void *p_xbf, *p_attbf, *p_qkv, *p_wqt, *p_wpt;
    cudaGetSymbolAddress(&p_xbf,   g_xbf);
    cudaGetSymbolAddress(&p_attbf, g_attbf);
    cudaGetSymbolAddress(&p_qkv,   g_qkv);
    cudaGetSymbolAddress(&p_wqt,   g_wqt);
    cudaGetSymbolAddress(&p_wpt,   g_wpt);

    cudaFuncSetAttribute(gemm_bf16x3_kernel,
                         cudaFuncAttributeMaxDynamicSharedMemorySize, SMEM_GEMM);

    // 0) fused preps
    prep_all_kernel<<<PX_BLKS + WQ_BLKS + WP_BLKS, 256>>>(x, qkv_w, proj_w);

    // 1) Q/K GEMM: 2-term (x * W_hi), N cols 0..767
    {
        dim3 grid(768 / GBN, MTILES);    // 6 x 784
        gemm_bf16x3_kernel<<<grid, 256, SMEM_GEMM>>>(
            (const __nv_bfloat16*)p_xbf, (const __nv_bfloat16*)p_wqt,
            qkv_b, (float*)p_qkv, QKVC, 12);
    }
    // 2) V GEMM: full 3-term, N cols 768..1151
    {
        dim3 grid(384 / GBN, MTILES);    // 3 x 784
        gemm_bf16x3_kernel<<<grid, 256, SMEM_GEMM>>>(
            (const __nv_bfloat16*)p_xbf,
            (const __nv_bfloat16*)p_wqt + (size_t)768 * KV,
            qkv_b + 768, (float*)p_qkv + 768, QKVC, 18);
    }
    // 3) windowed attention  (launch idx 3 -> ncu capture)
    {
        dim3 grid(BWIN, HNUM);
        attn_kernel<<<grid, 256>>>(relb, mask);
    }
    // 4) projection GEMM: full 3-term
    {
        dim3 grid(CDIM / GBN, MTILES);   // 3 x 784
        gemm_bf16x3_kernel<<<grid, 256, SMEM_GEMM>>>(
            (const __nv_bfloat16*)p_attbf, (const __nv_bfloat16*)p_wpt,
            proj_b, out, CDIM, 18);
    }
}

// round 8
// speedup vs baseline: 3.1438x; 1.0023x over previous
#include <cuda_runtime.h>
#include <cuda_bf16.h>
#include <cstdint>

// Problem constants: B_=2048, N=49, C=384, H=12, d=32, nW=64
#define BWIN   2048
#define NTOK   49
#define CDIM   384
#define HNUM   12
#define DHEAD  32
#define NWIN   64
#define MROWS  (BWIN * NTOK)     // 100352
#define QKVC   (3 * CDIM)        // 1152
#define KDIM   384
#define KV     1152              // virtual K = 3 * 384 (bf16x3 split)

// GEMM tiling (unchanged from R7)
#define GBM   128
#define GBN   128
#define GKC   64
#define NSTG  3
#define ROWB  144
#define A_ST  (GBM * ROWB)
#define B_ST  (GBN * ROWB)
#define STG_B (A_ST + B_ST)
#define SMEM_GEMM (NSTG * STG_B)
#define MTILES (MROWS / GBM)     // 784

#define PX_BLKS 37632
#define WQ_BLKS 1728
#define WP_BLKS 576

// attention smem layout (per block: 4 warps)
#define QS_STRIDE 80             // 40 bf16 per q row (32 data + pad)
#define KS_STRIDE 80
#define VT_STRIDE 136            // 68 bf16 per vT row (64 keys + pad)
#define SM_BIAS 0
#define SM_QS   9616
#define SM_KS   (SM_QS + 4 * 64 * QS_STRIDE)   // 30096
#define SM_VH   (SM_KS + 4 * 56 * KS_STRIDE)   // 48016
#define SM_VL   (SM_VH + 4 * 32 * VT_STRIDE)   // 65424
#define SM_ATT  (SM_VL + 4 * 32 * VT_STRIDE)   // 82832

// -------------------- device scratch --------------------------------------
__device__ __align__(16) __nv_bfloat16 g_xbf [(size_t)MROWS * 768];
__device__ __align__(16) __nv_bfloat16 g_attbf[(size_t)MROWS * 768];
__device__ __align__(16) float         g_qkv [(size_t)MROWS * QKVC];
__device__ __align__(16) __nv_bfloat16 g_wqt [(size_t)QKVC * KV];
__device__ __align__(16) __nv_bfloat16 g_wpt [(size_t)CDIM * KV];

// -------------------- PTX helpers -----------------------------------------
__device__ __forceinline__ uint32_t smem_u32(const void* p) {
    uint32_t a;
    asm("{ .reg .u64 t; cvta.to.shared.u64 t, %1; cvt.u32.u64 %0, t; }"
        : "=r"(a) : "l"(p));
    return a;
}
__device__ __forceinline__ void cp16(uint32_t s, const void* g) {
    asm volatile("cp.async.cg.shared.global [%0], [%1], 16;" :: "r"(s), "l"(g));
}
__device__ __forceinline__ void cp_commit() {
    asm volatile("cp.async.commit_group;" ::: "memory");
}
__device__ __forceinline__ void ldsm4(uint32_t* r, uint32_t addr) {
    asm volatile("ldmatrix.sync.aligned.m8n8.x4.shared.b16 {%0,%1,%2,%3}, [%4];"
        : "=r"(r[0]), "=r"(r[1]), "=r"(r[2]), "=r"(r[3]) : "r"(addr));
}
__device__ __forceinline__ void mma16816(float* d, const uint32_t* a, const uint32_t* b) {
    asm volatile(
        "mma.sync.aligned.m16n8k16.row.col.f32.bf16.bf16.f32 "
        "{%0,%1,%2,%3}, {%4,%5,%6,%7}, {%8,%9}, {%0,%1,%2,%3};"
        : "+f"(d[0]), "+f"(d[1]), "+f"(d[2]), "+f"(d[3])
        : "r"(a[0]), "r"(a[1]), "r"(a[2]), "r"(a[3]), "r"(b[0]), "r"(b[1]));
}
__device__ __forceinline__ uint32_t pack2(__nv_bfloat16 lo, __nv_bfloat16 hi) {
    return (uint32_t)__bfloat16_as_ushort(lo) | ((uint32_t)__bfloat16_as_ushort(hi) << 16);
}

// -------------------- fused prep (unchanged from R7) -----------------------
__global__ __launch_bounds__(256)
void prep_all_kernel(const float* __restrict__ x,
                     const float* __restrict__ qkv_w,
                     const float* __restrict__ proj_w)
{
    const int bid = blockIdx.x;
    const int tid = threadIdx.x;

    if (bid < PX_BLKS) {
        size_t id = (size_t)bid * 256 + tid;
        size_t row = id / 96;
        int c4 = (int)(id % 96) * 4;
        float4 v = *reinterpret_cast<const float4*>(&x[row * KDIM + c4]);
        __nv_bfloat16 h[4], l[4];
        h[0] = __float2bfloat16_rn(v.x); l[0] = __float2bfloat16_rn(v.x - __bfloat162float(h[0]));
        h[1] = __float2bfloat16_rn(v.y); l[1] = __float2bfloat16_rn(v.y - __bfloat162float(h[1]));
        h[2] = __float2bfloat16_rn(v.z); l[2] = __float2bfloat16_rn(v.z - __bfloat162float(h[2]));
        h[3] = __float2bfloat16_rn(v.w); l[3] = __float2bfloat16_rn(v.w - __bfloat162float(h[3]));
        *reinterpret_cast<uint2*>(&g_xbf[row * 768 + c4])       = *reinterpret_cast<uint2*>(h);
        *reinterpret_cast<uint2*>(&g_xbf[row * 768 + 384 + c4]) = *reinterpret_cast<uint2*>(l);
    } else if (bid < PX_BLKS + WQ_BLKS) {
        int id = (bid - PX_BLKS) * 256 + tid;
        if (id < KDIM * QKVC) {
            int k = id / QKVC, n = id % QKVC;
            float a = qkv_w[(size_t)k * QKVC + n];
            __nv_bfloat16 h = __float2bfloat16_rn(a);
            __nv_bfloat16 l = __float2bfloat16_rn(a - __bfloat162float(h));
            __nv_bfloat16* row = g_wqt + (size_t)n * KV;
            row[k] = h; row[384 + k] = h; row[768 + k] = l;
        }
    } else {
        int id = (bid - PX_BLKS - WQ_BLKS) * 256 + tid;
        if (id < KDIM * CDIM) {
            int k = id / CDIM, n = id % CDIM;
            float a = proj_w[(size_t)k * CDIM + n];
            __nv_bfloat16 h = __float2bfloat16_rn(a);
            __nv_bfloat16 l = __float2bfloat16_rn(a - __bfloat162float(h));
            __nv_bfloat16* row = g_wpt + (size_t)n * KV;
            row[k] = h; row[384 + k] = h; row[768 + k] = l;
        }
    }
}

// -------------------- GEMM (unchanged from R7) ------------------------------
__global__ __launch_bounds__(256, 2)
void gemm_bf16x3_kernel(const __nv_bfloat16* __restrict__ Ab,
                        const __nv_bfloat16* __restrict__ Bt,
                        const float* __restrict__ bias,
                        float* __restrict__ C, int ldc, int nch)
{
    extern __shared__ char smem[];
    const uint32_t s0 = smem_u32(smem);

    const int tid  = threadIdx.x;
    const int wid  = tid >> 5;
    const int lane = tid & 31;
    const int wm   = wid >> 1;
    const int wn   = wid & 1;
    const int bn   = blockIdx.x * GBN;
    const int bm   = blockIdx.y * GBM;

    const int lrow = tid >> 3;
    const int seg  = tid & 7;

    float acc[2][8][4];
#pragma unroll
    for (int i = 0; i < 2; ++i)
#pragma unroll
        for (int j = 0; j < 8; ++j)
#pragma unroll
            for (int q = 0; q < 4; ++q) acc[i][j][q] = 0.f;

    const int a_r  = (lane & 7) + ((lane >> 3) & 1) * 8;
    const int a_cb = (lane >> 4) * 16;
    const int b_r  = (lane & 7) + ((lane >> 4) & 1) * 8;
    const int b_cb = ((lane >> 3) & 1) * 16;

    auto issue = [&](int kc, int stg) {
        const int kp  = kc * GKC;
        const int src = (kp < 768) ? kp : (kp - 768);
        const uint32_t sa  = s0 + stg * STG_B;
        const uint32_t sbb = sa + A_ST;
#pragma unroll
        for (int i = 0; i < 4; ++i) {
            int r = lrow + i * 32;
            cp16(sa + r * ROWB + seg * 16,
                 Ab + (size_t)(bm + r) * 768 + src + seg * 8);
        }
#pragma unroll
        for (int i = 0; i < 4; ++i) {
            int r = lrow + i * 32;
            cp16(sbb + r * ROWB + seg * 16,
                 Bt + (size_t)(bn + r) * KV + kp + seg * 8);
        }
        cp_commit();
    };

    issue(0, 0);
    issue(1, 1);

    for (int kc = 0; kc < nch; ++kc) {
        if (kc < nch - 1)
            asm volatile("cp.async.wait_group 1;" ::: "memory");
        else
            asm volatile("cp.async.wait_group 0;" ::: "memory");
        __syncthreads();

        if (kc + 2 < nch) issue(kc + 2, (kc + 2) % NSTG);

        const uint32_t sa = s0 + (kc % NSTG) * STG_B;
        const uint32_t abase = sa + (wm * 32 + a_r) * ROWB + a_cb;
        const uint32_t bbase = sa + A_ST + (wn * 64 + b_r) * ROWB + b_cb;

#pragma unroll
        for (int ks = 0; ks < 4; ++ks) {
            const int kb = ks * 32;
            uint32_t af[2][4];
#pragma unroll
            for (int fm = 0; fm < 2; ++fm)
                ldsm4(af[fm], abase + fm * 16 * ROWB + kb);
            uint32_t bfr[8][2];
#pragma unroll
            for (int j = 0; j < 4; ++j) {
                uint32_t r[4];
                ldsm4(r, bbase + j * 16 * ROWB + kb);
                bfr[2 * j][0] = r[0]; bfr[2 * j][1] = r[1];
                bfr[2 * j + 1][0] = r[2]; bfr[2 * j + 1][1] = r[3];
            }
#pragma unroll
            for (int fm = 0; fm < 2; ++fm)
#pragma unroll
                for (int fn = 0; fn < 8; ++fn)
                    mma16816(acc[fm][fn], af[fm], bfr[fn]);
        }
    }

#pragma unroll
    for (int fm = 0; fm < 2; ++fm) {
        const int row0 = bm + wm * 32 + fm * 16 + (lane >> 2);
#pragma unroll
        for (int fn = 0; fn < 8; ++fn) {
            const int col = bn + wn * 64 + fn * 8 + (lane & 3) * 2;
            const float b0 = __ldg(&bias[col]);
            const float b1 = __ldg(&bias[col + 1]);
            float2 o0 = make_float2(acc[fm][fn][0] + b0, acc[fm][fn][1] + b1);
            float2 o1 = make_float2(acc[fm][fn][2] + b0, acc[fm][fn][3] + b1);
            *reinterpret_cast<float2*>(&C[(size_t)row0 * ldc + col])       = o0;
            *reinterpret_cast<float2*>(&C[(size_t)(row0 + 8) * ldc + col]) = o1;
        }
    }
}

// -------------------- MMA attention ----------------------------------------
// Block = (w, h, half). 4 warps x 4 windows. Per window one warp does the full
// head: S = Q K^T (bf16 mma), bias+exp (no max), quad-reduce rowsum,
// O = P V with P and V split hi/lo (3-term), scaled by 1/rowsum at store.
__global__ __launch_bounds__(128)
void attn_mma_kernel(const float* __restrict__ relb,
                     const float* __restrict__ mask)
{
    extern __shared__ char smem[];
    const int w = blockIdx.x, h = blockIdx.y, zh = blockIdx.z;
    const int tid = threadIdx.x, warp = tid >> 5, lane = tid & 31;
    const int kq = lane >> 2;          // "groupID" row/col component
    const int kc = (lane & 3) * 2;     // paired-column component

    float* bias_s = reinterpret_cast<float*>(smem + SM_BIAS);
    char* qp  = smem + SM_QS + warp * (64 * QS_STRIDE);
    char* kp  = smem + SM_KS + warp * (56 * KS_STRIDE);
    char* vhp = smem + SM_VH + warp * (32 * VT_STRIDE);
    char* vlp = smem + SM_VL + warp * (32 * VT_STRIDE);

    // fused bias table for this (h, w)
    {
        const float* rb = relb + (size_t)h * NTOK * NTOK;
        const float* mk = mask + (size_t)w * NTOK * NTOK;
        for (int i = tid; i < NTOK * NTOK; i += 128) bias_s[i] = rb[i] + mk[i];
    }
    // zero pads (rows/keys >= 49) — written once, never overwritten
    {
        const __nv_bfloat16 z = __float2bfloat16_rn(0.f);
        for (int r = 49; r < 64; ++r)
            *reinterpret_cast<__nv_bfloat16*>(qp + r * QS_STRIDE + lane * 2) = z;
        for (int r = 49; r < 56; ++r)
            *reinterpret_cast<__nv_bfloat16*>(kp + r * KS_STRIDE + lane * 2) = z;
        for (int k = 49; k < 64; ++k) {
            *reinterpret_cast<__nv_bfloat16*>(vhp + lane * VT_STRIDE + k * 2) = z;
            *reinterpret_cast<__nv_bfloat16*>(vlp + lane * VT_STRIDE + k * 2) = z;
        }
    }
    __syncthreads();

    const float scale = 0.17677669529663687f;

    for (int win = 0; win < 4; ++win) {
        const int j = zh * 16 + warp * 4 + win;
        const int b = j * 64 + w;
        const float* base = g_qkv + (size_t)b * NTOK * QKVC + h * DHEAD;

        __syncwarp();
        // stage q, k (bf16) and v (bf16 hi/lo, transposed) — lane = d
        for (int r = 0; r < NTOK; ++r) {
            const float qv = base[(size_t)r * QKVC + lane];
            const float kv = base[(size_t)r * QKVC + CDIM + lane];
            const float vv = base[(size_t)r * QKVC + 2 * CDIM + lane];
            *reinterpret_cast<__nv_bfloat16*>(qp + r * QS_STRIDE + lane * 2) =
                __float2bfloat16_rn(qv);
            *reinterpret_cast<__nv_bfloat16*>(kp + r * KS_STRIDE + lane * 2) =
                __float2bfloat16_rn(kv);
            const __nv_bfloat16 hv = __float2bfloat16_rn(vv);
            const __nv_bfloat16 lv = __float2bfloat16_rn(vv - __bfloat162float(hv));
            *reinterpret_cast<__nv_bfloat16*>(vhp + lane * VT_STRIDE + r * 2) = hv;
            *reinterpret_cast<__nv_bfloat16*>(vlp + lane * VT_STRIDE + r * 2) = lv;
        }
        __syncwarp();

        // K B-frags: kf[nt][ks] — b0,b1 = K[key][d0,d0+1], b2,b3 = d0+8,d0+9
        uint32_t kf[7][2][2];
#pragma unroll
        for (int nt = 0; nt < 7; ++nt)
#pragma unroll
            for (int ks = 0; ks < 2; ++ks) {
                const char* p = kp + (nt * 8 + kq) * KS_STRIDE + (ks * 16 + kc) * 2;
                kf[nt][ks][0] = *reinterpret_cast<const uint32_t*>(p);
                kf[nt][ks][1] = *reinterpret_cast<const uint32_t*>(p + 16);
            }
        // V B-frags (hi/lo): b0,b1 = V[k0,k0+1][d] = vT[d][k0,k0+1]
        uint32_t vhf[4][4][2], vlf[4][4][2];
#pragma unroll
        for (int nt = 0; nt < 4; ++nt)
#pragma unroll
            for (int kt = 0; kt < 4; ++kt) {
                const int off = (nt * 8 + kq) * VT_STRIDE + (kt * 16 + kc) * 2;
                vhf[nt][kt][0] = *reinterpret_cast<const uint32_t*>(vhp + off);
                vhf[nt][kt][1] = *reinterpret_cast<const uint32_t*>(vhp + off + 16);
                vlf[nt][kt][0] = *reinterpret_cast<const uint32_t*>(vlp + off);
                vlf[nt][kt][1] = *reinterpret_cast<const uint32_t*>(vlp + off + 16);
            }

        for (int mt = 0; mt < 4; ++mt) {
            const int row = mt * 16 + kq;
            // Q A-frags (2 k-steps)
            uint32_t qf[2][4];
#pragma unroll
            for (int ks = 0; ks < 2; ++ks) {
                const int d = ks * 16 + kc;
                qf[ks][0] = *reinterpret_cast<const uint32_t*>(qp + row * QS_STRIDE + d * 2);
                qf[ks][1] = *reinterpret_cast<const uint32_t*>(qp + (row + 8) * QS_STRIDE + d * 2);
                qf[ks][2] = *reinterpret_cast<const uint32_t*>(qp + row * QS_STRIDE + (d + 8) * 2);
                qf[ks][3] = *reinterpret_cast<const uint32_t*>(qp + (row + 8) * QS_STRIDE + (d + 8) * 2);
            }
            // S = Q K^T
            float sf[7][4];
#pragma unroll
            for (int nt = 0; nt < 7; ++nt) {
                sf[nt][0] = sf[nt][1] = sf[nt][2] = sf[nt][3] = 0.f;
                mma16816(sf[nt], qf[0], kf[nt][0]);
                mma16816(sf[nt], qf[1], kf[nt][1]);
            }
            // bias + exp (no max) + rowsums
            const int n0 = (row < 48) ? row : 48;
            const int n1 = (row + 8 < 48) ? (row + 8) : 48;
            float sum0 = 0.f, sum1 = 0.f;
#pragma unroll
            for (int nt = 0; nt < 7; ++nt) {
                const int key = nt * 8 + kc;
                float e0 = __expf(sf[nt][0] * scale + bias_s[n0 * NTOK + key]);
                float e1 = __expf(sf[nt][1] * scale + bias_s[n0 * NTOK + key + 1]);
                float e2 = __expf(sf[nt][2] * scale + bias_s[n1 * NTOK + key]);
                float e3 = __expf(sf[nt][3] * scale + bias_s[n1 * NTOK + key + 1]);
                if (nt == 6) {                      // keys 48..55: only 48 valid
                    if (kc != 0) { e0 = 0.f; e2 = 0.f; }
                    e1 = 0.f; e3 = 0.f;
                }
                sf[nt][0] = e0; sf[nt][1] = e1; sf[nt][2] = e2; sf[nt][3] = e3;
                sum0 += e0 + e1; sum1 += e2 + e3;
            }
            sum0 += __shfl_xor_sync(0xffffffffu, sum0, 1);
            sum0 += __shfl_xor_sync(0xffffffffu, sum0, 2);
            sum1 += __shfl_xor_sync(0xffffffffu, sum1, 1);
            sum1 += __shfl_xor_sync(0xffffffffu, sum1, 2);
            const float inv0 = 1.f / sum0, inv1 = 1.f / sum1;

            // O = P V  (P hi/lo from S frags; 3-term)
            float of[4][4];
#pragma unroll
            for (int nt = 0; nt < 4; ++nt)
                of[nt][0] = of[nt][1] = of[nt][2] = of[nt][3] = 0.f;

#pragma unroll
            for (int kt = 0; kt < 4; ++kt) {
                float e[8];
                e[0] = sf[2 * kt][0]; e[1] = sf[2 * kt][1];
                e[2] = sf[2 * kt][2]; e[3] = sf[2 * kt][3];
                if (2 * kt + 1 < 7) {
                    e[4] = sf[2 * kt + 1][0]; e[5] = sf[2 * kt + 1][1];
                    e[6] = sf[2 * kt + 1][2]; e[7] = sf[2 * kt + 1][3];
                } else {
                    e[4] = e[5] = e[6] = e[7] = 0.f;
                }
                __nv_bfloat16 hb[8], lb[8];
#pragma unroll
                for (int i = 0; i < 8; ++i) {
                    hb[i] = __float2bfloat16_rn(e[i]);
                    lb[i] = __float2bfloat16_rn(e[i] - __bfloat162float(hb[i]));
                }
                uint32_t ph[4], pl[4];
                // A-frag reg order: R0=(r, c0c1) R1=(r+8, c0c1) R2=(r, c8c9) R3=(r+8, c8c9)
                ph[0] = pack2(hb[0], hb[1]); ph[1] = pack2(hb[2], hb[3]);
                ph[2] = pack2(hb[4], hb[5]); ph[3] = pack2(hb[6], hb[7]);
                pl[0] = pack2(lb[0], lb[1]); pl[1] = pack2(lb[2], lb[3]);
                pl[2] = pack2(lb[4], lb[5]); pl[3] = pack2(lb[6], lb[7]);
#pragma unroll
                for (int nt = 0; nt < 4; ++nt) {
                    mma16816(of[nt], ph, vhf[nt][kt]);
                    mma16816(of[nt], pl, vhf[nt][kt]);
                    mma16816(of[nt], ph, vlf[nt][kt]);
                }
            }

            // store (normalize by rowsum; hi/lo bf16 pairs)
            const bool val0 = (row < NTOK), val1 = (row + 8 < NTOK);
            const size_t r0 = ((size_t)b * NTOK + row) * 768 + h * DHEAD;
            const size_t r1 = ((size_t)b * NTOK + row + 8) * 768 + h * DHEAD;
#pragma unroll
            for (int nt = 0; nt < 4; ++nt) {
                const int d = nt * 8 + kc;
                if (val0) {
                    const float o0 = of[nt][0] * inv0, o1 = of[nt][1] * inv0;
                    const __nv_bfloat16 h0 = __float2bfloat16_rn(o0);
                    const __nv_bfloat16 h1 = __float2bfloat16_rn(o1);
                    *reinterpret_cast<uint32_t*>(&g_attbf[r0 + d]) = pack2(h0, h1);
                    *reinterpret_cast<uint32_t*>(&g_attbf[r0 + 384 + d]) =
                        pack2(__float2bfloat16_rn(o0 - __bfloat162float(h0)),
                              __float2bfloat16_rn(o1 - __bfloat162float(h1)));
                }
                if (val1) {
                    const float o2 = of[nt][2] * inv1, o3 = of[nt][3] * inv1;
                    const __nv_bfloat16 h2 = __float2bfloat16_rn(o2);
                    const __nv_bfloat16 h3 = __float2bfloat16_rn(o3);
                    *reinterpret_cast<uint32_t*>(&g_attbf[r1 + d]) = pack2(h2, h3);
                    *reinterpret_cast<uint32_t*>(&g_attbf[r1 + 384 + d]) =
                        pack2(__float2bfloat16_rn(o2 - __bfloat162float(h2)),
                              __float2bfloat16_rn(o3 - __bfloat162float(h3)));
                }
            }
        }
    }
}

// ---------------------------------------------------------------------------
extern "C" void kernel_launch(void* const* d_in, const int* in_sizes, int n_in,
                              void* d_out, int out_size)
{
    const float* x      = (const float*)d_in[0];
    const float* mask   = (const float*)d_in[1];
    const float* qkv_w  = (const float*)d_in[2];
    const float* qkv_b  = (const float*)d_in[3];
    const float* proj_w = (const float*)d_in[4];
    const float* proj_b = (const float*)d_in[5];
    const float* relb   = (const float*)d_in[6];
    float* out = (float*)d_out;

    void *p_xbf, *p_attbf, *p_qkv, *p_wqt, *p_wpt;
    cudaGetSymbolAddress(&p_xbf,   g_xbf);
    cudaGetSymbolAddress(&p_attbf, g_attbf);
    cudaGetSymbolAddress(&p_qkv,   g_qkv);
    cudaGetSymbolAddress(&p_wqt,   g_wqt);
    cudaGetSymbolAddress(&p_wpt,   g_wpt);

    cudaFuncSetAttribute(gemm_bf16x3_kernel,
                         cudaFuncAttributeMaxDynamicSharedMemorySize, SMEM_GEMM);
    cudaFuncSetAttribute(attn_mma_kernel,
                         cudaFuncAttributeMaxDynamicSharedMemorySize, SM_ATT);

    // 0) fused preps
    prep_all_kernel<<<PX_BLKS + WQ_BLKS + WP_BLKS, 256>>>(x, qkv_w, proj_w);

    // 1) Q/K GEMM: 2-term (x * W_hi)
    {
        dim3 grid(768 / GBN, MTILES);
        gemm_bf16x3_kernel<<<grid, 256, SMEM_GEMM>>>(
            (const __nv_bfloat16*)p_xbf, (const __nv_bfloat16*)p_wqt,
            qkv_b, (float*)p_qkv, QKVC, 12);
    }
    // 2) V GEMM: full 3-term
    {
        dim3 grid(384 / GBN, MTILES);
        gemm_bf16x3_kernel<<<grid, 256, SMEM_GEMM>>>(
            (const __nv_bfloat16*)p_xbf,
            (const __nv_bfloat16*)p_wqt + (size_t)768 * KV,
            qkv_b + 768, (float*)p_qkv + 768, QKVC, 18);
    }
    // 3) MMA attention (launch idx 3 -> ncu capture)
    {
        dim3 grid(NWIN, HNUM, 2);
        attn_mma_kernel<<<grid, 128, SM_ATT>>>(relb, mask);
    }
    // 4) projection GEMM: full 3-term
    {
        dim3 grid(CDIM / GBN, MTILES);
        gemm_bf16x3_kernel<<<grid, 256, SMEM_GEMM>>>(
            (const __nv_bfloat16*)p_attbf, (const __nv_bfloat16*)p_wpt,
            proj_b, out, CDIM, 18);
    }
}

// round 9
// speedup vs baseline: 3.5723x; 1.1363x over previous
#include <cuda_runtime.h>
#include <cuda_bf16.h>
#include <cstdint>

// Problem constants: B_=2048, N=49, C=384, H=12, d=32, nW=64
#define BWIN   2048
#define NTOK   49
#define CDIM   384
#define HNUM   12
#define DHEAD  32
#define NWIN   64
#define MROWS  (BWIN * NTOK)     // 100352
#define QKVC   (3 * CDIM)        // 1152
#define KDIM   384
#define KV     1152              // virtual K = 3 * 384 (bf16x3 split)

// GEMM tiling
#define GBM   128
#define GBN   128
#define GKC   64
#define NSTG  3
#define ROWB  144
#define A_ST  (GBM * ROWB)
#define B_ST  (GBN * ROWB)
#define STG_B (A_ST + B_ST)
#define SMEM_GEMM (NSTG * STG_B)
#define MTILES (MROWS / GBM)     // 784

#define PX_BLKS 37632
#define WQ_BLKS 1728
#define WP_BLKS 576

// -------------------- device scratch --------------------------------------
__device__ __align__(16) __nv_bfloat16 g_xbf [(size_t)MROWS * 768];  // x hi|lo
__device__ __align__(16) __nv_bfloat16 g_attbf[(size_t)MROWS * 768]; // attn out hi|lo
__device__ __align__(16) __nv_bfloat16 g_qkh [(size_t)MROWS * 768];  // q|k bf16
__device__ __align__(16) __nv_bfloat16 g_vhl [(size_t)MROWS * 768];  // v hi|lo bf16
__device__ __align__(16) __nv_bfloat16 g_wqt [(size_t)QKVC * KV];
__device__ __align__(16) __nv_bfloat16 g_wpt [(size_t)CDIM * KV];

// -------------------- PTX helpers -----------------------------------------
__device__ __forceinline__ uint32_t smem_u32(const void* p) {
    uint32_t a;
    asm("{ .reg .u64 t; cvta.to.shared.u64 t, %1; cvt.u32.u64 %0, t; }"
        : "=r"(a) : "l"(p));
    return a;
}
__device__ __forceinline__ void cp16(uint32_t s, const void* g) {
    asm volatile("cp.async.cg.shared.global [%0], [%1], 16;" :: "r"(s), "l"(g));
}
__device__ __forceinline__ void cp_commit() {
    asm volatile("cp.async.commit_group;" ::: "memory");
}
__device__ __forceinline__ void ldsm4(uint32_t* r, uint32_t addr) {
    asm volatile("ldmatrix.sync.aligned.m8n8.x4.shared.b16 {%0,%1,%2,%3}, [%4];"
        : "=r"(r[0]), "=r"(r[1]), "=r"(r[2]), "=r"(r[3]) : "r"(addr));
}
__device__ __forceinline__ void mma16816(float* d, const uint32_t* a, const uint32_t* b) {
    asm volatile(
        "mma.sync.aligned.m16n8k16.row.col.f32.bf16.bf16.f32 "
        "{%0,%1,%2,%3}, {%4,%5,%6,%7}, {%8,%9}, {%0,%1,%2,%3};"
        : "+f"(d[0]), "+f"(d[1]), "+f"(d[2]), "+f"(d[3])
        : "r"(a[0]), "r"(a[1]), "r"(a[2]), "r"(a[3]), "r"(b[0]), "r"(b[1]));
}
__device__ __forceinline__ uint32_t pack2(__nv_bfloat16 lo, __nv_bfloat16 hi) {
    return (uint32_t)__bfloat16_as_ushort(lo) | ((uint32_t)__bfloat16_as_ushort(hi) << 16);
}

// -------------------- fused prep -------------------------------------------
__global__ __launch_bounds__(256)
void prep_all_kernel(const float* __restrict__ x,
                     const float* __restrict__ qkv_w,
                     const float* __restrict__ proj_w)
{
    const int bid = blockIdx.x;
    const int tid = threadIdx.x;

    if (bid < PX_BLKS) {
        size_t id = (size_t)bid * 256 + tid;
        size_t row = id / 96;
        int c4 = (int)(id % 96) * 4;
        float4 v = *reinterpret_cast<const float4*>(&x[row * KDIM + c4]);
        __nv_bfloat16 h[4], l[4];
        h[0] = __float2bfloat16_rn(v.x); l[0] = __float2bfloat16_rn(v.x - __bfloat162float(h[0]));
        h[1] = __float2bfloat16_rn(v.y); l[1] = __float2bfloat16_rn(v.y - __bfloat162float(h[1]));
        h[2] = __float2bfloat16_rn(v.z); l[2] = __float2bfloat16_rn(v.z - __bfloat162float(h[2]));
        h[3] = __float2bfloat16_rn(v.w); l[3] = __float2bfloat16_rn(v.w - __bfloat162float(h[3]));
        *reinterpret_cast<uint2*>(&g_xbf[row * 768 + c4])       = *reinterpret_cast<uint2*>(h);
        *reinterpret_cast<uint2*>(&g_xbf[row * 768 + 384 + c4]) = *reinterpret_cast<uint2*>(l);
    } else if (bid < PX_BLKS + WQ_BLKS) {
        int id = (bid - PX_BLKS) * 256 + tid;
        if (id < KDIM * QKVC) {
            int k = id / QKVC, n = id % QKVC;
            float a = qkv_w[(size_t)k * QKVC + n];
            __nv_bfloat16 h = __float2bfloat16_rn(a);
            __nv_bfloat16 l = __float2bfloat16_rn(a - __bfloat162float(h));
            __nv_bfloat16* row = g_wqt + (size_t)n * KV;
            row[k] = h; row[384 + k] = h; row[768 + k] = l;
        }
    } else {
        int id = (bid - PX_BLKS - WQ_BLKS) * 256 + tid;
        if (id < KDIM * CDIM) {
            int k = id / CDIM, n = id % CDIM;
            float a = proj_w[(size_t)k * CDIM + n];
            __nv_bfloat16 h = __float2bfloat16_rn(a);
            __nv_bfloat16 l = __float2bfloat16_rn(a - __bfloat162float(h));
            __nv_bfloat16* row = g_wpt + (size_t)n * KV;
            row[k] = h; row[384 + k] = h; row[768 + k] = l;
        }
    }
}

// -------------------- GEMM with output modes -------------------------------
// mode 0: fp32 out (ldc stride)           (proj)
// mode 1: bf16 out, row stride 768        (q|k)
// mode 2: bf16 hi at col, lo at col+384, row stride 768  (v)
__global__ __launch_bounds__(256, 2)
void gemm_bf16x3_kernel(const __nv_bfloat16* __restrict__ Ab,
                        const __nv_bfloat16* __restrict__ Bt,
                        const float* __restrict__ bias,
                        void* __restrict__ Cv, int ldc, int nch, int mode)
{
    extern __shared__ char smem[];
    const uint32_t s0 = smem_u32(smem);

    const int tid  = threadIdx.x;
    const int wid  = tid >> 5;
    const int lane = tid & 31;
    const int wm   = wid >> 1;
    const int wn   = wid & 1;
    const int bn   = blockIdx.x * GBN;
    const int bm   = blockIdx.y * GBM;

    const int lrow = tid >> 3;
    const int seg  = tid & 7;

    float acc[2][8][4];
#pragma unroll
    for (int i = 0; i < 2; ++i)
#pragma unroll
        for (int j = 0; j < 8; ++j)
#pragma unroll
            for (int q = 0; q < 4; ++q) acc[i][j][q] = 0.f;

    const int a_r  = (lane & 7) + ((lane >> 3) & 1) * 8;
    const int a_cb = (lane >> 4) * 16;
    const int b_r  = (lane & 7) + ((lane >> 4) & 1) * 8;
    const int b_cb = ((lane >> 3) & 1) * 16;

    auto issue = [&](int kc, int stg) {
        const int kp  = kc * GKC;
        const int src = (kp < 768) ? kp : (kp - 768);
        const uint32_t sa  = s0 + stg * STG_B;
        const uint32_t sbb = sa + A_ST;
#pragma unroll
        for (int i = 0; i < 4; ++i) {
            int r = lrow + i * 32;
            cp16(sa + r * ROWB + seg * 16,
                 Ab + (size_t)(bm + r) * 768 + src + seg * 8);
        }
#pragma unroll
        for (int i = 0; i < 4; ++i) {
            int r = lrow + i * 32;
            cp16(sbb + r * ROWB + seg * 16,
                 Bt + (size_t)(bn + r) * KV + kp + seg * 8);
        }
        cp_commit();
    };

    issue(0, 0);
    issue(1, 1);

    for (int kc = 0; kc < nch; ++kc) {
        if (kc < nch - 1)
            asm volatile("cp.async.wait_group 1;" ::: "memory");
        else
            asm volatile("cp.async.wait_group 0;" ::: "memory");
        __syncthreads();

        if (kc + 2 < nch) issue(kc + 2, (kc + 2) % NSTG);

        const uint32_t sa = s0 + (kc % NSTG) * STG_B;
        const uint32_t abase = sa + (wm * 32 + a_r) * ROWB + a_cb;
        const uint32_t bbase = sa + A_ST + (wn * 64 + b_r) * ROWB + b_cb;

#pragma unroll
        for (int ks = 0; ks < 4; ++ks) {
            const int kb = ks * 32;
            uint32_t af[2][4];
#pragma unroll
            for (int fm = 0; fm < 2; ++fm)
                ldsm4(af[fm], abase + fm * 16 * ROWB + kb);
            uint32_t bfr[8][2];
#pragma unroll
            for (int j = 0; j < 4; ++j) {
                uint32_t r[4];
                ldsm4(r, bbase + j * 16 * ROWB + kb);
                bfr[2 * j][0] = r[0]; bfr[2 * j][1] = r[1];
                bfr[2 * j + 1][0] = r[2]; bfr[2 * j + 1][1] = r[3];
            }
#pragma unroll
            for (int fm = 0; fm < 2; ++fm)
#pragma unroll
                for (int fn = 0; fn < 8; ++fn)
                    mma16816(acc[fm][fn], af[fm], bfr[fn]);
        }
    }

#pragma unroll
    for (int fm = 0; fm < 2; ++fm) {
        const int row0 = bm + wm * 32 + fm * 16 + (lane >> 2);
#pragma unroll
        for (int fn = 0; fn < 8; ++fn) {
            const int col = bn + wn * 64 + fn * 8 + (lane & 3) * 2;
            const float b0 = __ldg(&bias[col]);
            const float b1 = __ldg(&bias[col + 1]);
            const float o0 = acc[fm][fn][0] + b0, o1 = acc[fm][fn][1] + b1;
            const float o2 = acc[fm][fn][2] + b0, o3 = acc[fm][fn][3] + b1;
            if (mode == 0) {
                float* C = (float*)Cv;
                *reinterpret_cast<float2*>(&C[(size_t)row0 * ldc + col]) =
                    make_float2(o0, o1);
                *reinterpret_cast<float2*>(&C[(size_t)(row0 + 8) * ldc + col]) =
                    make_float2(o2, o3);
            } else if (mode == 1) {
                __nv_bfloat16* C = (__nv_bfloat16*)Cv;
                *reinterpret_cast<uint32_t*>(&C[(size_t)row0 * 768 + col]) =
                    pack2(__float2bfloat16_rn(o0), __float2bfloat16_rn(o1));
                *reinterpret_cast<uint32_t*>(&C[(size_t)(row0 + 8) * 768 + col]) =
                    pack2(__float2bfloat16_rn(o2), __float2bfloat16_rn(o3));
            } else {
                __nv_bfloat16* C = (__nv_bfloat16*)Cv;
                const __nv_bfloat16 h0 = __float2bfloat16_rn(o0);
                const __nv_bfloat16 h1 = __float2bfloat16_rn(o1);
                const __nv_bfloat16 h2 = __float2bfloat16_rn(o2);
                const __nv_bfloat16 h3 = __float2bfloat16_rn(o3);
                *reinterpret_cast<uint32_t*>(&C[(size_t)row0 * 768 + col]) = pack2(h0, h1);
                *reinterpret_cast<uint32_t*>(&C[(size_t)(row0 + 8) * 768 + col]) = pack2(h2, h3);
                *reinterpret_cast<uint32_t*>(&C[(size_t)row0 * 768 + 384 + col]) =
                    pack2(__float2bfloat16_rn(o0 - __bfloat162float(h0)),
                          __float2bfloat16_rn(o1 - __bfloat162float(h1)));
                *reinterpret_cast<uint32_t*>(&C[(size_t)(row0 + 8) * 768 + 384 + col]) =
                    pack2(__float2bfloat16_rn(o2 - __bfloat162float(h2)),
                          __float2bfloat16_rn(o3 - __bfloat162float(h3)));
            }
        }
    }
}

// -------------------- MMA attention, no smem staging -----------------------
// Block = (w, h, zh). 4 warps x 4 windows. All Q/K/V fragments loaded
// directly from bf16 gmem (written by GEMM epilogues). Only the fused
// bias table lives in smem.
__global__ __launch_bounds__(128)
void attn_mma_kernel(const float* __restrict__ relb,
                     const float* __restrict__ mask)
{
    __shared__ float bias_s[NTOK * NTOK];

    const int w = blockIdx.x, h = blockIdx.y, zh = blockIdx.z;
    const int tid = threadIdx.x, warp = tid >> 5, lane = tid & 31;
    const int kq = lane >> 2;
    const int kc = (lane & 3) * 2;

    {
        const float* rb = relb + (size_t)h * NTOK * NTOK;
        const float* mk = mask + (size_t)w * NTOK * NTOK;
        for (int i = tid; i < NTOK * NTOK; i += 128) bias_s[i] = rb[i] + mk[i];
    }
    __syncthreads();

    const float scale = 0.17677669529663687f;

    for (int win = 0; win < 4; ++win) {
        const int j = zh * 16 + warp * 4 + win;
        const int b = j * 64 + w;
        const __nv_bfloat16* qk = g_qkh + (size_t)b * NTOK * 768 + h * DHEAD;
        const __nv_bfloat16* vv = g_vhl + (size_t)b * NTOK * 768 + h * DHEAD;

        // ---- K B-frags (regs, reused across all mt) ----
        uint32_t kf[7][2][2];
#pragma unroll
        for (int nt = 0; nt < 7; ++nt) {
            const int key = nt * 8 + kq;
            const bool ok = (key < NTOK);
            const __nv_bfloat16* p = qk + (size_t)(ok ? key : 0) * 768 + 384;
#pragma unroll
            for (int ks = 0; ks < 2; ++ks) {
                const int d = ks * 16 + kc;
                kf[nt][ks][0] = ok ? *reinterpret_cast<const uint32_t*>(p + d)     : 0u;
                kf[nt][ks][1] = ok ? *reinterpret_cast<const uint32_t*>(p + d + 8) : 0u;
            }
        }
        // ---- V B-frags hi/lo (gather along keys, 2-byte loads) ----
        uint32_t vhf[4][4][2], vlf[4][4][2];
#pragma unroll
        for (int nt = 0; nt < 4; ++nt) {
            const int d = nt * 8 + kq;
#pragma unroll
            for (int kt = 0; kt < 4; ++kt) {
#pragma unroll
                for (int r2 = 0; r2 < 2; ++r2) {
                    const int k0 = kt * 16 + kc + r2 * 8;
                    const bool o0 = (k0 < NTOK), o1 = (k0 + 1 < NTOK);
                    const size_t a0 = (size_t)(o0 ? k0 : 0) * 768 + d;
                    const size_t a1 = (size_t)(o1 ? k0 + 1 : 0) * 768 + d;
                    const __nv_bfloat16 z = __ushort_as_bfloat16(0);
                    __nv_bfloat16 h0 = o0 ? vv[a0] : z;
                    __nv_bfloat16 h1 = o1 ? vv[a1] : z;
                    __nv_bfloat16 l0 = o0 ? vv[a0 + 384] : z;
                    __nv_bfloat16 l1 = o1 ? vv[a1 + 384] : z;
                    vhf[nt][kt][r2] = pack2(h0, h1);
                    vlf[nt][kt][r2] = pack2(l0, l1);
                }
            }
        }

        for (int mt = 0; mt < 4; ++mt) {
            const int row = mt * 16 + kq;
            const bool r0ok = (row < NTOK), r1ok = (row + 8 < NTOK);
            const __nv_bfloat16* q0 = qk + (size_t)(r0ok ? row : 0) * 768;
            const __nv_bfloat16* q1 = qk + (size_t)(r1ok ? row + 8 : 0) * 768;

            uint32_t qf[2][4];
#pragma unroll
            for (int ks = 0; ks < 2; ++ks) {
                const int d = ks * 16 + kc;
                qf[ks][0] = r0ok ? *reinterpret_cast<const uint32_t*>(q0 + d)     : 0u;
                qf[ks][1] = r1ok ? *reinterpret_cast<const uint32_t*>(q1 + d)     : 0u;
                qf[ks][2] = r0ok ? *reinterpret_cast<const uint32_t*>(q0 + d + 8) : 0u;
                qf[ks][3] = r1ok ? *reinterpret_cast<const uint32_t*>(q1 + d + 8) : 0u;
            }

            float sf[7][4];
#pragma unroll
            for (int nt = 0; nt < 7; ++nt) {
                sf[nt][0] = sf[nt][1] = sf[nt][2] = sf[nt][3] = 0.f;
                mma16816(sf[nt], qf[0], kf[nt][0]);
                mma16816(sf[nt], qf[1], kf[nt][1]);
            }

            const int n0 = (row < 48) ? row : 48;
            const int n1 = (row + 8 < 48) ? (row + 8) : 48;
            float sum0 = 0.f, sum1 = 0.f;
#pragma unroll
            for (int nt = 0; nt < 7; ++nt) {
                const int key = nt * 8 + kc;
                float e0 = __expf(sf[nt][0] * scale + bias_s[n0 * NTOK + key]);
                float e1 = __expf(sf[nt][1] * scale + bias_s[n0 * NTOK + key + 1]);
                float e2 = __expf(sf[nt][2] * scale + bias_s[n1 * NTOK + key]);
                float e3 = __expf(sf[nt][3] * scale + bias_s[n1 * NTOK + key + 1]);
                if (nt == 6) {
                    if (kc != 0) { e0 = 0.f; e2 = 0.f; }
                    e1 = 0.f; e3 = 0.f;
                }
                sf[nt][0] = e0; sf[nt][1] = e1; sf[nt][2] = e2; sf[nt][3] = e3;
                sum0 += e0 + e1; sum1 += e2 + e3;
            }
            sum0 += __shfl_xor_sync(0xffffffffu, sum0, 1);
            sum0 += __shfl_xor_sync(0xffffffffu, sum0, 2);
            sum1 += __shfl_xor_sync(0xffffffffu, sum1, 1);
            sum1 += __shfl_xor_sync(0xffffffffu, sum1, 2);
            const float inv0 = 1.f / sum0, inv1 = 1.f / sum1;

            float of[4][4];
#pragma unroll
            for (int nt = 0; nt < 4; ++nt)
                of[nt][0] = of[nt][1] = of[nt][2] = of[nt][3] = 0.f;

#pragma unroll
            for (int kt = 0; kt < 4; ++kt) {
                float e[8];
                e[0] = sf[2 * kt][0]; e[1] = sf[2 * kt][1];
                e[2] = sf[2 * kt][2]; e[3] = sf[2 * kt][3];
                if (2 * kt + 1 < 7) {
                    e[4] = sf[2 * kt + 1][0]; e[5] = sf[2 * kt + 1][1];
                    e[6] = sf[2 * kt + 1][2]; e[7] = sf[2 * kt + 1][3];
                } else {
                    e[4] = e[5] = e[6] = e[7] = 0.f;
                }
                __nv_bfloat16 hb[8], lb[8];
#pragma unroll
                for (int i = 0; i < 8; ++i) {
                    hb[i] = __float2bfloat16_rn(e[i]);
                    lb[i] = __float2bfloat16_rn(e[i] - __bfloat162float(hb[i]));
                }
                uint32_t ph[4], pl[4];
                ph[0] = pack2(hb[0], hb[1]); ph[1] = pack2(hb[2], hb[3]);
                ph[2] = pack2(hb[4], hb[5]); ph[3] = pack2(hb[6], hb[7]);
                pl[0] = pack2(lb[0], lb[1]); pl[1] = pack2(lb[2], lb[3]);
                pl[2] = pack2(lb[4], lb[5]); pl[3] = pack2(lb[6], lb[7]);
#pragma unroll
                for (int nt = 0; nt < 4; ++nt) {
                    mma16816(of[nt], ph, vhf[nt][kt]);
                    mma16816(of[nt], pl, vhf[nt][kt]);
                    mma16816(of[nt], ph, vlf[nt][kt]);
                }
            }

            const size_t r0 = ((size_t)b * NTOK + row) * 768 + h * DHEAD;
            const size_t r1 = ((size_t)b * NTOK + row + 8) * 768 + h * DHEAD;
#pragma unroll
            for (int nt = 0; nt < 4; ++nt) {
                const int d = nt * 8 + kc;
                if (r0ok) {
                    const float o0 = of[nt][0] * inv0, o1 = of[nt][1] * inv0;
                    const __nv_bfloat16 h0 = __float2bfloat16_rn(o0);
                    const __nv_bfloat16 h1 = __float2bfloat16_rn(o1);
                    *reinterpret_cast<uint32_t*>(&g_attbf[r0 + d]) = pack2(h0, h1);
                    *reinterpret_cast<uint32_t*>(&g_attbf[r0 + 384 + d]) =
                        pack2(__float2bfloat16_rn(o0 - __bfloat162float(h0)),
                              __float2bfloat16_rn(o1 - __bfloat162float(h1)));
                }
                if (r1ok) {
                    const float o2 = of[nt][2] * inv1, o3 = of[nt][3] * inv1;
                    const __nv_bfloat16 h2 = __float2bfloat16_rn(o2);
                    const __nv_bfloat16 h3 = __float2bfloat16_rn(o3);
                    *reinterpret_cast<uint32_t*>(&g_attbf[r1 + d]) = pack2(h2, h3);
                    *reinterpret_cast<uint32_t*>(&g_attbf[r1 + 384 + d]) =
                        pack2(__float2bfloat16_rn(o2 - __bfloat162float(h2)),
                              __float2bfloat16_rn(o3 - __bfloat162float(h3)));
                }
            }
        }
    }
}

// ---------------------------------------------------------------------------
extern "C" void kernel_launch(void* const* d_in, const int* in_sizes, int n_in,
                              void* d_out, int out_size)
{
    const float* x      = (const float*)d_in[0];
    const float* mask   = (const float*)d_in[1];
    const float* qkv_w  = (const float*)d_in[2];
    const float* qkv_b  = (const float*)d_in[3];
    const float* proj_w = (const float*)d_in[4];
    const float* proj_b = (const float*)d_in[5];
    const float* relb   = (const float*)d_in[6];
    float* out = (float*)d_out;

    void *p_xbf, *p_attbf, *p_qkh, *p_vhl, *p_wqt, *p_wpt;
    cudaGetSymbolAddress(&p_xbf,   g_xbf);
    cudaGetSymbolAddress(&p_attbf, g_attbf);
    cudaGetSymbolAddress(&p_qkh,   g_qkh);
    cudaGetSymbolAddress(&p_vhl,   g_vhl);
    cudaGetSymbolAddress(&p_wqt,   g_wqt);
    cudaGetSymbolAddress(&p_wpt,   g_wpt);

    cudaFuncSetAttribute(gemm_bf16x3_kernel,
                         cudaFuncAttributeMaxDynamicSharedMemorySize, SMEM_GEMM);

    // 0) fused preps
    prep_all_kernel<<<PX_BLKS + WQ_BLKS + WP_BLKS, 256>>>(x, qkv_w, proj_w);

    // 1) Q/K GEMM: 2-term, bf16 out (mode 1)
    {
        dim3 grid(768 / GBN, MTILES);
        gemm_bf16x3_kernel<<<grid, 256, SMEM_GEMM>>>(
            (const __nv_bfloat16*)p_xbf, (const __nv_bfloat16*)p_wqt,
            qkv_b, p_qkh, 768, 12, 1);
    }
    // 2) V GEMM: 3-term, bf16 hi/lo out (mode 2)
    {
        dim3 grid(384 / GBN, MTILES);
        gemm_bf16x3_kernel<<<grid, 256, SMEM_GEMM>>>(
            (const __nv_bfloat16*)p_xbf,
            (const __nv_bfloat16*)p_wqt + (size_t)768 * KV,
            qkv_b + 768, p_vhl, 768, 18, 2);
    }
    // 3) MMA attention (launch idx 3 -> ncu capture)
    {
        dim3 grid(NWIN, HNUM, 2);
        attn_mma_kernel<<<grid, 128>>>(relb, mask);
    }
    // 4) projection GEMM: fp32 out (mode 0)
    {
        dim3 grid(CDIM / GBN, MTILES);
        gemm_bf16x3_kernel<<<grid, 256, SMEM_GEMM>>>(
            (const __nv_bfloat16*)p_attbf, (const __nv_bfloat16*)p_wpt,
            proj_b, out, CDIM, 18, 0);
    }
}

// round 10
// speedup vs baseline: 3.9202x; 1.0974x over previous
#include <cuda_runtime.h>
#include <cuda_fp16.h>
#include <cstdint>

// Problem constants: B_=2048, N=49, C=384, H=12, d=32, nW=64
#define BWIN   2048
#define NTOK   49
#define CDIM   384
#define HNUM   12
#define DHEAD  32
#define NWIN   64
#define MROWS  (BWIN * NTOK)     // 100352
#define QKVC   (3 * CDIM)        // 1152
#define KDIM   384
#define KV     1152              // virtual K = 3 * 384 (hi*wh | lo*wh | hi*wl)

// GEMM tiling
#define GBM   128
#define GBN   128
#define GKC   64
#define NSTG  3
#define ROWB  144
#define A_ST  (GBM * ROWB)
#define B_ST  (GBN * ROWB)
#define STG_B (A_ST + B_ST)
#define SMEM_GEMM (NSTG * STG_B)
#define MTILES (MROWS / GBM)     // 784

#define PX_BLKS  37632
#define WQ_BLKS  1728
#define WP_BLKS  576
#define PAD_BLKS 12288           // zero vt pad keys 48..63: 1.57M rows x 2 uint4

// -------------------- device scratch --------------------------------------
__device__ __align__(16) __half g_xhf [(size_t)MROWS * 768];   // x hi|lo fp16
__device__ __align__(16) __half g_attf[(size_t)MROWS * 768];   // attn out hi|lo
__device__ __align__(16) __half g_qkh [(size_t)MROWS * 768];   // q|k fp16
__device__ __align__(16) __half g_vt  [(size_t)BWIN * 2 * CDIM * 64]; // vT hi|lo
__device__ __align__(16) __half g_wqt [(size_t)QKVC * KV];
__device__ __align__(16) __half g_wpt [(size_t)CDIM * KV];

// -------------------- PTX helpers -----------------------------------------
__device__ __forceinline__ uint32_t smem_u32(const void* p) {
    uint32_t a;
    asm("{ .reg .u64 t; cvta.to.shared.u64 t, %1; cvt.u32.u64 %0, t; }"
        : "=r"(a) : "l"(p));
    return a;
}
__device__ __forceinline__ void cp16(uint32_t s, const void* g) {
    asm volatile("cp.async.cg.shared.global [%0], [%1], 16;" :: "r"(s), "l"(g));
}
__device__ __forceinline__ void cp_commit() {
    asm volatile("cp.async.commit_group;" ::: "memory");
}
__device__ __forceinline__ void ldsm4(uint32_t* r, uint32_t addr) {
    asm volatile("ldmatrix.sync.aligned.m8n8.x4.shared.b16 {%0,%1,%2,%3}, [%4];"
        : "=r"(r[0]), "=r"(r[1]), "=r"(r[2]), "=r"(r[3]) : "r"(addr));
}
__device__ __forceinline__ void mma16816(float* d, const uint32_t* a, const uint32_t* b) {
    asm volatile(
        "mma.sync.aligned.m16n8k16.row.col.f32.f16.f16.f32 "
        "{%0,%1,%2,%3}, {%4,%5,%6,%7}, {%8,%9}, {%0,%1,%2,%3};"
        : "+f"(d[0]), "+f"(d[1]), "+f"(d[2]), "+f"(d[3])
        : "r"(a[0]), "r"(a[1]), "r"(a[2]), "r"(a[3]), "r"(b[0]), "r"(b[1]));
}
__device__ __forceinline__ uint32_t pack2(__half lo, __half hi) {
    return (uint32_t)__half_as_ushort(lo) | ((uint32_t)__half_as_ushort(hi) << 16);
}

// -------------------- fused prep -------------------------------------------
__global__ __launch_bounds__(256)
void prep_all_kernel(const float* __restrict__ x,
                     const float* __restrict__ qkv_w,
                     const float* __restrict__ proj_w)
{
    const int bid = blockIdx.x;
    const int tid = threadIdx.x;

    if (bid < PX_BLKS) {
        size_t id = (size_t)bid * 256 + tid;
        size_t row = id / 96;
        int c4 = (int)(id % 96) * 4;
        float4 v = *reinterpret_cast<const float4*>(&x[row * KDIM + c4]);
        __half h[4], l[4];
        h[0] = __float2half_rn(v.x); l[0] = __float2half_rn(v.x - __half2float(h[0]));
        h[1] = __float2half_rn(v.y); l[1] = __float2half_rn(v.y - __half2float(h[1]));
        h[2] = __float2half_rn(v.z); l[2] = __float2half_rn(v.z - __half2float(h[2]));
        h[3] = __float2half_rn(v.w); l[3] = __float2half_rn(v.w - __half2float(h[3]));
        *reinterpret_cast<uint2*>(&g_xhf[row * 768 + c4])       = *reinterpret_cast<uint2*>(h);
        *reinterpret_cast<uint2*>(&g_xhf[row * 768 + 384 + c4]) = *reinterpret_cast<uint2*>(l);
    } else if (bid < PX_BLKS + WQ_BLKS) {
        int id = (bid - PX_BLKS) * 256 + tid;
        if (id < KDIM * QKVC) {
            int k = id / QKVC, n = id % QKVC;
            float a = qkv_w[(size_t)k * QKVC + n];
            __half h = __float2half_rn(a);
            __half l = __float2half_rn(a - __half2float(h));
            __half* row = g_wqt + (size_t)n * KV;
            row[k] = h; row[384 + k] = h; row[768 + k] = l;
        }
    } else if (bid < PX_BLKS + WQ_BLKS + WP_BLKS) {
        int id = (bid - PX_BLKS - WQ_BLKS) * 256 + tid;
        if (id < KDIM * CDIM) {
            int k = id / CDIM, n = id % CDIM;
            float a = proj_w[(size_t)k * CDIM + n];
            __half h = __float2half_rn(a);
            __half l = __float2half_rn(a - __half2float(h));
            __half* row = g_wpt + (size_t)n * KV;
            row[k] = h; row[384 + k] = h; row[768 + k] = l;
        }
    } else {
        // zero vt pad: keys 48..63 (bytes 96..128) of every 128B vt row
        size_t s = (size_t)(bid - PX_BLKS - WQ_BLKS - WP_BLKS) * 256 + tid;
        size_t row = s >> 1;
        if (row < (size_t)BWIN * 2 * CDIM) {
            uint4* p = reinterpret_cast<uint4*>(
                reinterpret_cast<char*>(g_vt) + row * 128 + 96 + (s & 1) * 16);
            *p = make_uint4(0, 0, 0, 0);
        }
    }
}

// -------------------- GEMM with output modes -------------------------------
// mode 0: fp32 out (ldc stride)                       (proj)
// mode 1: fp16 out, row stride 768                    (q|k)
// mode 2: fp16 hi/lo scatter to vt[b][hl][col][key]   (v)
__global__ __launch_bounds__(256, 2)
void gemm_fp16x_kernel(const __half* __restrict__ Ab,
                       const __half* __restrict__ Bt,
                       const float* __restrict__ bias,
                       void* __restrict__ Cv, int ldc, int nch, int mode)
{
    extern __shared__ char smem[];
    const uint32_t s0 = smem_u32(smem);

    const int tid  = threadIdx.x;
    const int wid  = tid >> 5;
    const int lane = tid & 31;
    const int wm   = wid >> 1;
    const int wn   = wid & 1;
    const int bn   = blockIdx.x * GBN;
    const int bm   = blockIdx.y * GBM;

    const int lrow = tid >> 3;
    const int seg  = tid & 7;

    float acc[2][8][4];
#pragma unroll
    for (int i = 0; i < 2; ++i)
#pragma unroll
        for (int j = 0; j < 8; ++j)
#pragma unroll
            for (int q = 0; q < 4; ++q) acc[i][j][q] = 0.f;

    const int a_r  = (lane & 7) + ((lane >> 3) & 1) * 8;
    const int a_cb = (lane >> 4) * 16;
    const int b_r  = (lane & 7) + ((lane >> 4) & 1) * 8;
    const int b_cb = ((lane >> 3) & 1) * 16;

    auto issue = [&](int kc, int stg) {
        const int kp  = kc * GKC;
        const int src = (kp < 768) ? kp : (kp - 768);
        const uint32_t sa  = s0 + stg * STG_B;
        const uint32_t sbb = sa + A_ST;
#pragma unroll
        for (int i = 0; i < 4; ++i) {
            int r = lrow + i * 32;
            cp16(sa + r * ROWB + seg * 16,
                 Ab + (size_t)(bm + r) * 768 + src + seg * 8);
        }
#pragma unroll
        for (int i = 0; i < 4; ++i) {
            int r = lrow + i * 32;
            cp16(sbb + r * ROWB + seg * 16,
                 Bt + (size_t)(bn + r) * KV + kp + seg * 8);
        }
        cp_commit();
    };

    issue(0, 0);
    issue(1, 1);

    for (int kc = 0; kc < nch; ++kc) {
        if (kc < nch - 1)
            asm volatile("cp.async.wait_group 1;" ::: "memory");
        else
            asm volatile("cp.async.wait_group 0;" ::: "memory");
        __syncthreads();

        if (kc + 2 < nch) issue(kc + 2, (kc + 2) % NSTG);

        const uint32_t sa = s0 + (kc % NSTG) * STG_B;
        const uint32_t abase = sa + (wm * 32 + a_r) * ROWB + a_cb;
        const uint32_t bbase = sa + A_ST + (wn * 64 + b_r) * ROWB + b_cb;

#pragma unroll
        for (int ks = 0; ks < 4; ++ks) {
            const int kb = ks * 32;
            uint32_t af[2][4];
#pragma unroll
            for (int fm = 0; fm < 2; ++fm)
                ldsm4(af[fm], abase + fm * 16 * ROWB + kb);
            uint32_t bfr[8][2];
#pragma unroll
            for (int j = 0; j < 4; ++j) {
                uint32_t r[4];
                ldsm4(r, bbase + j * 16 * ROWB + kb);
                bfr[2 * j][0] = r[0]; bfr[2 * j][1] = r[1];
                bfr[2 * j + 1][0] = r[2]; bfr[2 * j + 1][1] = r[3];
            }
#pragma unroll
            for (int fm = 0; fm < 2; ++fm)
#pragma unroll
                for (int fn = 0; fn < 8; ++fn)
                    mma16816(acc[fm][fn], af[fm], bfr[fn]);
        }
    }

#pragma unroll
    for (int fm = 0; fm < 2; ++fm) {
        const int row0 = bm + wm * 32 + fm * 16 + (lane >> 2);
        // window/token decomposition for vt scatter (mode 2)
        const int b0 = row0 / NTOK,        n0 = row0 - b0 * NTOK;
        const int b1 = (row0 + 8) / NTOK,  n1 = (row0 + 8) - b1 * NTOK;
#pragma unroll
        for (int fn = 0; fn < 8; ++fn) {
            const int col = bn + wn * 64 + fn * 8 + (lane & 3) * 2;
            const float b0f = __ldg(&bias[col]);
            const float b1f = __ldg(&bias[col + 1]);
            const float o0 = acc[fm][fn][0] + b0f, o1 = acc[fm][fn][1] + b1f;
            const float o2 = acc[fm][fn][2] + b0f, o3 = acc[fm][fn][3] + b1f;
            if (mode == 0) {
                float* C = (float*)Cv;
                *reinterpret_cast<float2*>(&C[(size_t)row0 * ldc + col]) =
                    make_float2(o0, o1);
                *reinterpret_cast<float2*>(&C[(size_t)(row0 + 8) * ldc + col]) =
                    make_float2(o2, o3);
            } else if (mode == 1) {
                __half* C = (__half*)Cv;
                *reinterpret_cast<uint32_t*>(&C[(size_t)row0 * 768 + col]) =
                    pack2(__float2half_rn(o0), __float2half_rn(o1));
                *reinterpret_cast<uint32_t*>(&C[(size_t)(row0 + 8) * 768 + col]) =
                    pack2(__float2half_rn(o2), __float2half_rn(o3));
            } else {
                __half* C = (__half*)Cv;
                const __half h0 = __float2half_rn(o0);
                const __half h1 = __float2half_rn(o1);
                const __half h2 = __float2half_rn(o2);
                const __half h3 = __float2half_rn(o3);
                const size_t LHL = (size_t)CDIM * 64;   // hi->lo offset
                const size_t i0 = ((size_t)b0 * 2 * CDIM + col) * 64 + n0;
                const size_t i1 = ((size_t)b1 * 2 * CDIM + col) * 64 + n1;
                C[i0]            = h0;
                C[i0 + 64]       = h1;
                C[i0 + LHL]      = __float2half_rn(o0 - __half2float(h0));
                C[i0 + 64 + LHL] = __float2half_rn(o1 - __half2float(h1));
                C[i1]            = h2;
                C[i1 + 64]       = h3;
                C[i1 + LHL]      = __float2half_rn(o2 - __half2float(h2));
                C[i1 + 64 + LHL] = __float2half_rn(o3 - __half2float(h3));
            }
        }
    }
}

// -------------------- MMA attention, fp16, vT layout ------------------------
__global__ __launch_bounds__(128)
void attn_mma_kernel(const float* __restrict__ relb,
                     const float* __restrict__ mask)
{
    __shared__ float bias_s[NTOK * NTOK];

    const int w = blockIdx.x, h = blockIdx.y, zh = blockIdx.z;
    const int tid = threadIdx.x, warp = tid >> 5, lane = tid & 31;
    const int kq = lane >> 2;
    const int kc = (lane & 3) * 2;

    {
        const float* rb = relb + (size_t)h * NTOK * NTOK;
        const float* mk = mask + (size_t)w * NTOK * NTOK;
        for (int i = tid; i < NTOK * NTOK; i += 128) bias_s[i] = rb[i] + mk[i];
    }
    __syncthreads();

    const float scale = 0.17677669529663687f;

    for (int win = 0; win < 4; ++win) {
        const int j = zh * 16 + warp * 4 + win;
        const int b = j * 64 + w;
        const __half* qk = g_qkh + (size_t)b * NTOK * 768 + h * DHEAD;
        const __half* vth = g_vt + ((size_t)b * 2 * CDIM + h * DHEAD) * 64;
        const __half* vtl = vth + (size_t)CDIM * 64;

        // K B-frags
        uint32_t kf[7][2][2];
#pragma unroll
        for (int nt = 0; nt < 7; ++nt) {
            const int key = nt * 8 + kq;
            const bool ok = (key < NTOK);
            const __half* p = qk + (size_t)(ok ? key : 0) * 768 + 384;
#pragma unroll
            for (int ks = 0; ks < 2; ++ks) {
                const int d = ks * 16 + kc;
                kf[nt][ks][0] = ok ? *reinterpret_cast<const uint32_t*>(p + d)     : 0u;
                kf[nt][ks][1] = ok ? *reinterpret_cast<const uint32_t*>(p + d + 8) : 0u;
            }
        }
        // V B-frags hi/lo from transposed layout: 4-byte loads (k0,k0+1 adjacent)
        uint32_t vhf[4][4][2], vlf[4][4][2];
#pragma unroll
        for (int nt = 0; nt < 4; ++nt) {
            const size_t drow = (size_t)(nt * 8 + kq) * 64;
#pragma unroll
            for (int kt = 0; kt < 4; ++kt) {
#pragma unroll
                for (int r2 = 0; r2 < 2; ++r2) {
                    const int k0 = kt * 16 + kc + r2 * 8;
                    vhf[nt][kt][r2] = *reinterpret_cast<const uint32_t*>(vth + drow + k0);
                    vlf[nt][kt][r2] = *reinterpret_cast<const uint32_t*>(vtl + drow + k0);
                }
            }
        }

        for (int mt = 0; mt < 4; ++mt) {
            const int row = mt * 16 + kq;
            const bool r0ok = (row < NTOK), r1ok = (row + 8 < NTOK);
            const __half* q0 = qk + (size_t)(r0ok ? row : 0) * 768;
            const __half* q1 = qk + (size_t)(r1ok ? row + 8 : 0) * 768;

            uint32_t qf[2][4];
#pragma unroll
            for (int ks = 0; ks < 2; ++ks) {
                const int d = ks * 16 + kc;
                qf[ks][0] = r0ok ? *reinterpret_cast<const uint32_t*>(q0 + d)     : 0u;
                qf[ks][1] = r1ok ? *reinterpret_cast<const uint32_t*>(q1 + d)     : 0u;
                qf[ks][2] = r0ok ? *reinterpret_cast<const uint32_t*>(q0 + d + 8) : 0u;
                qf[ks][3] = r1ok ? *reinterpret_cast<const uint32_t*>(q1 + d + 8) : 0u;
            }

            float sf[7][4];
#pragma unroll
            for (int nt = 0; nt < 7; ++nt) {
                sf[nt][0] = sf[nt][1] = sf[nt][2] = sf[nt][3] = 0.f;
                mma16816(sf[nt], qf[0], kf[nt][0]);
                mma16816(sf[nt], qf[1], kf[nt][1]);
            }

            const int n0 = (row < 48) ? row : 48;
            const int n1 = (row + 8 < 48) ? (row + 8) : 48;
            float sum0 = 0.f, sum1 = 0.f;
#pragma unroll
            for (int nt = 0; nt < 7; ++nt) {
                const int key = nt * 8 + kc;
                float e0 = __expf(sf[nt][0] * scale + bias_s[n0 * NTOK + key]);
                float e1 = __expf(sf[nt][1] * scale + bias_s[n0 * NTOK + key + 1]);
                float e2 = __expf(sf[nt][2] * scale + bias_s[n1 * NTOK + key]);
                float e3 = __expf(sf[nt][3] * scale + bias_s[n1 * NTOK + key + 1]);
                if (nt == 6) {
                    if (kc != 0) { e0 = 0.f; e2 = 0.f; }
                    e1 = 0.f; e3 = 0.f;
                }
                sf[nt][0] = e0; sf[nt][1] = e1; sf[nt][2] = e2; sf[nt][3] = e3;
                sum0 += e0 + e1; sum1 += e2 + e3;
            }
            sum0 += __shfl_xor_sync(0xffffffffu, sum0, 1);
            sum0 += __shfl_xor_sync(0xffffffffu, sum0, 2);
            sum1 += __shfl_xor_sync(0xffffffffu, sum1, 1);
            sum1 += __shfl_xor_sync(0xffffffffu, sum1, 2);
            const float inv0 = 1.f / sum0, inv1 = 1.f / sum1;

            float of[4][4];
#pragma unroll
            for (int nt = 0; nt < 4; ++nt)
                of[nt][0] = of[nt][1] = of[nt][2] = of[nt][3] = 0.f;

#pragma unroll
            for (int kt = 0; kt < 4; ++kt) {
                float e[8];
                e[0] = sf[2 * kt][0]; e[1] = sf[2 * kt][1];
                e[2] = sf[2 * kt][2]; e[3] = sf[2 * kt][3];
                if (2 * kt + 1 < 7) {
                    e[4] = sf[2 * kt + 1][0]; e[5] = sf[2 * kt + 1][1];
                    e[6] = sf[2 * kt + 1][2]; e[7] = sf[2 * kt + 1][3];
                } else {
                    e[4] = e[5] = e[6] = e[7] = 0.f;
                }
                __half hb[8], lb[8];
#pragma unroll
                for (int i = 0; i < 8; ++i) {
                    hb[i] = __float2half_rn(e[i]);
                    lb[i] = __float2half_rn(e[i] - __half2float(hb[i]));
                }
                uint32_t ph[4], pl[4];
                ph[0] = pack2(hb[0], hb[1]); ph[1] = pack2(hb[2], hb[3]);
                ph[2] = pack2(hb[4], hb[5]); ph[3] = pack2(hb[6], hb[7]);
                pl[0] = pack2(lb[0], lb[1]); pl[1] = pack2(lb[2], lb[3]);
                pl[2] = pack2(lb[4], lb[5]); pl[3] = pack2(lb[6], lb[7]);
#pragma unroll
                for (int nt = 0; nt < 4; ++nt) {
                    mma16816(of[nt], ph, vhf[nt][kt]);
                    mma16816(of[nt], pl, vhf[nt][kt]);
                    mma16816(of[nt], ph, vlf[nt][kt]);
                }
            }

            const size_t r0 = ((size_t)b * NTOK + row) * 768 + h * DHEAD;
            const size_t r1 = ((size_t)b * NTOK + row + 8) * 768 + h * DHEAD;
#pragma unroll
            for (int nt = 0; nt < 4; ++nt) {
                const int d = nt * 8 + kc;
                if (r0ok) {
                    const float o0 = of[nt][0] * inv0, o1 = of[nt][1] * inv0;
                    const __half h0 = __float2half_rn(o0);
                    const __half h1 = __float2half_rn(o1);
                    *reinterpret_cast<uint32_t*>(&g_attf[r0 + d]) = pack2(h0, h1);
                    *reinterpret_cast<uint32_t*>(&g_attf[r0 + 384 + d]) =
                        pack2(__float2half_rn(o0 - __half2float(h0)),
                              __float2half_rn(o1 - __half2float(h1)));
                }
                if (r1ok) {
                    const float o2 = of[nt][2] * inv1, o3 = of[nt][3] * inv1;
                    const __half h2 = __float2half_rn(o2);
                    const __half h3 = __float2half_rn(o3);
                    *reinterpret_cast<uint32_t*>(&g_attf[r1 + d]) = pack2(h2, h3);
                    *reinterpret_cast<uint32_t*>(&g_attf[r1 + 384 + d]) =
                        pack2(__float2half_rn(o2 - __half2float(h2)),
                              __float2half_rn(o3 - __half2float(h3)));
                }
            }
        }
    }
}

// ---------------------------------------------------------------------------
extern "C" void kernel_launch(void* const* d_in, const int* in_sizes, int n_in,
                              void* d_out, int out_size)
{
    const float* x      = (const float*)d_in[0];
    const float* mask   = (const float*)d_in[1];
    const float* qkv_w  = (const float*)d_in[2];
    const float* qkv_b  = (const float*)d_in[3];
    const float* proj_w = (const float*)d_in[4];
    const float* proj_b = (const float*)d_in[5];
    const float* relb   = (const float*)d_in[6];
    float* out = (float*)d_out;

    void *p_xhf, *p_attf, *p_qkh, *p_vt, *p_wqt, *p_wpt;
    cudaGetSymbolAddress(&p_xhf,  g_xhf);
    cudaGetSymbolAddress(&p_attf, g_attf);
    cudaGetSymbolAddress(&p_qkh,  g_qkh);
    cudaGetSymbolAddress(&p_vt,   g_vt);
    cudaGetSymbolAddress(&p_wqt,  g_wqt);
    cudaGetSymbolAddress(&p_wpt,  g_wpt);

    cudaFuncSetAttribute(gemm_fp16x_kernel,
                         cudaFuncAttributeMaxDynamicSharedMemorySize, SMEM_GEMM);

    // 0) fused preps (+ vt pad zeroing)
    prep_all_kernel<<<PX_BLKS + WQ_BLKS + WP_BLKS + PAD_BLKS, 256>>>(x, qkv_w, proj_w);

    // 1) Q/K GEMM: 1 product set (x_hi * w_hi), fp16 out (mode 1)
    {
        dim3 grid(768 / GBN, MTILES);
        gemm_fp16x_kernel<<<grid, 256, SMEM_GEMM>>>(
            (const __half*)p_xhf, (const __half*)p_wqt,
            qkv_b, p_qkh, 768, 6, 1);
    }
    // 2) V GEMM: 3-term fp16, transposed hi/lo out (mode 2)
    {
        dim3 grid(384 / GBN, MTILES);
        gemm_fp16x_kernel<<<grid, 256, SMEM_GEMM>>>(
            (const __half*)p_xhf,
            (const __half*)p_wqt + (size_t)768 * KV,
            qkv_b + 768, p_vt, 0, 18, 2);
    }
    // 3) MMA attention (launch idx 3 -> ncu capture)
    {
        dim3 grid(NWIN, HNUM, 2);
        attn_mma_kernel<<<grid, 128>>>(relb, mask);
    }
    // 4) projection GEMM: 3-term fp16, fp32 out (mode 0)
    {
        dim3 grid(CDIM / GBN, MTILES);
        gemm_fp16x_kernel<<<grid, 256, SMEM_GEMM>>>(
            (const __half*)p_attf, (const __half*)p_wpt,
            proj_b, out, CDIM, 18, 0);
    }
}

// round 11
// speedup vs baseline: 5.1038x; 1.3019x over previous
#include <cuda_runtime.h>
#include <cuda_fp16.h>
#include <cstdint>

// Problem constants: B_=2048, N=49, C=384, H=12, d=32, nW=64
#define BWIN   2048
#define NTOK   49
#define CDIM   384
#define HNUM   12
#define DHEAD  32
#define NWIN   64
#define MROWS  (BWIN * NTOK)     // 100352
#define QKVC   (3 * CDIM)        // 1152
#define KDIM   384
#define KV     1152              // weight layout: wh | wh | wl

// GEMM tiling
#define GBM   128
#define GBN   128
#define GKC   64
#define NSTG  3
#define ROWB  144
#define A_ST  (GBM * ROWB)
#define B_ST  (GBN * ROWB)
#define STG_B (A_ST + B_ST)
#define SMEM_GEMM (NSTG * STG_B)
#define MTILES (MROWS / GBM)     // 784

#define PX_BLKS  37632
#define WQ_BLKS  1728
#define WP_BLKS  576
#define PAD_BLKS 6144            // zero vt pad keys 48..63: 786432 rows x 2 uint4

#define BSTR 50                  // bias smem row stride (floats) — float2 aligned

// -------------------- device scratch --------------------------------------
__device__ __align__(16) __half g_xhf [(size_t)MROWS * 768];   // x hi|lo fp16
__device__ __align__(16) __half g_attf[(size_t)MROWS * 768];   // attn out hi|lo
__device__ __align__(16) __half g_qkh [(size_t)MROWS * 768];   // q|k fp16
__device__ __align__(16) __half g_vt  [(size_t)BWIN * CDIM * 64]; // vT single fp16
__device__ __align__(16) __half g_wqt [(size_t)QKVC * KV];
__device__ __align__(16) __half g_wpt [(size_t)CDIM * KV];

// -------------------- PTX helpers -----------------------------------------
__device__ __forceinline__ uint32_t smem_u32(const void* p) {
    uint32_t a;
    asm("{ .reg .u64 t; cvta.to.shared.u64 t, %1; cvt.u32.u64 %0, t; }"
        : "=r"(a) : "l"(p));
    return a;
}
__device__ __forceinline__ void cp16(uint32_t s, const void* g) {
    asm volatile("cp.async.cg.shared.global [%0], [%1], 16;" :: "r"(s), "l"(g));
}
__device__ __forceinline__ void cp_commit() {
    asm volatile("cp.async.commit_group;" ::: "memory");
}
__device__ __forceinline__ void ldsm4(uint32_t* r, uint32_t addr) {
    asm volatile("ldmatrix.sync.aligned.m8n8.x4.shared.b16 {%0,%1,%2,%3}, [%4];"
        : "=r"(r[0]), "=r"(r[1]), "=r"(r[2]), "=r"(r[3]) : "r"(addr));
}
__device__ __forceinline__ void mma16816(float* d, const uint32_t* a, const uint32_t* b) {
    asm volatile(
        "mma.sync.aligned.m16n8k16.row.col.f32.f16.f16.f32 "
        "{%0,%1,%2,%3}, {%4,%5,%6,%7}, {%8,%9}, {%0,%1,%2,%3};"
        : "+f"(d[0]), "+f"(d[1]), "+f"(d[2]), "+f"(d[3])
        : "r"(a[0]), "r"(a[1]), "r"(a[2]), "r"(a[3]), "r"(b[0]), "r"(b[1]));
}
__device__ __forceinline__ uint32_t pack2(__half lo, __half hi) {
    return (uint32_t)__half_as_ushort(lo) | ((uint32_t)__half_as_ushort(hi) << 16);
}

// -------------------- fused prep -------------------------------------------
__global__ __launch_bounds__(256)
void prep_all_kernel(const float* __restrict__ x,
                     const float* __restrict__ qkv_w,
                     const float* __restrict__ proj_w)
{
    const int bid = blockIdx.x;
    const int tid = threadIdx.x;

    if (bid < PX_BLKS) {
        size_t id = (size_t)bid * 256 + tid;
        size_t row = id / 96;
        int c4 = (int)(id % 96) * 4;
        float4 v = *reinterpret_cast<const float4*>(&x[row * KDIM + c4]);
        __half h[4], l[4];
        h[0] = __float2half_rn(v.x); l[0] = __float2half_rn(v.x - __half2float(h[0]));
        h[1] = __float2half_rn(v.y); l[1] = __float2half_rn(v.y - __half2float(h[1]));
        h[2] = __float2half_rn(v.z); l[2] = __float2half_rn(v.z - __half2float(h[2]));
        h[3] = __float2half_rn(v.w); l[3] = __float2half_rn(v.w - __half2float(h[3]));
        *reinterpret_cast<uint2*>(&g_xhf[row * 768 + c4])       = *reinterpret_cast<uint2*>(h);
        *reinterpret_cast<uint2*>(&g_xhf[row * 768 + 384 + c4]) = *reinterpret_cast<uint2*>(l);
    } else if (bid < PX_BLKS + WQ_BLKS) {
        int id = (bid - PX_BLKS) * 256 + tid;
        if (id < KDIM * QKVC) {
            int k = id / QKVC, n = id % QKVC;
            float a = qkv_w[(size_t)k * QKVC + n];
            __half h = __float2half_rn(a);
            __half l = __float2half_rn(a - __half2float(h));
            __half* row = g_wqt + (size_t)n * KV;
            row[k] = h; row[384 + k] = h; row[768 + k] = l;
        }
    } else if (bid < PX_BLKS + WQ_BLKS + WP_BLKS) {
        int id = (bid - PX_BLKS - WQ_BLKS) * 256 + tid;
        if (id < KDIM * CDIM) {
            int k = id / CDIM, n = id % CDIM;
            float a = proj_w[(size_t)k * CDIM + n];
            __half h = __float2half_rn(a);
            __half l = __float2half_rn(a - __half2float(h));
            __half* row = g_wpt + (size_t)n * KV;
            row[k] = h; row[384 + k] = h; row[768 + k] = l;
        }
    } else {
        // zero vt pad: keys 48..63 (bytes 96..128) of every 128B vt row
        size_t s = (size_t)(bid - PX_BLKS - WQ_BLKS - WP_BLKS) * 256 + tid;
        size_t row = s >> 1;
        if (row < (size_t)BWIN * CDIM) {
            uint4* p = reinterpret_cast<uint4*>(
                reinterpret_cast<char*>(g_vt) + row * 128 + 96 + (s & 1) * 16);
            *p = make_uint4(0, 0, 0, 0);
        }
    }
}

// -------------------- GEMM with output modes -------------------------------
// mode 0: fp32 out (ldc stride)                      (proj)
// mode 1: fp16 out, row stride 768                   (q|k)
// mode 2: fp16 single scatter to vt[b][col][key]     (v)
__global__ __launch_bounds__(256, 2)
void gemm_fp16x_kernel(const __half* __restrict__ Ab,
                       const __half* __restrict__ Bt,
                       const float* __restrict__ bias,
                       void* __restrict__ Cv, int ldc, int nch, int mode)
{
    extern __shared__ char smem[];
    const uint32_t s0 = smem_u32(smem);

    const int tid  = threadIdx.x;
    const int wid  = tid >> 5;
    const int lane = tid & 31;
    const int wm   = wid >> 1;
    const int wn   = wid & 1;
    const int bn   = blockIdx.x * GBN;
    const int bm   = blockIdx.y * GBM;

    const int lrow = tid >> 3;
    const int seg  = tid & 7;

    float acc[2][8][4];
#pragma unroll
    for (int i = 0; i < 2; ++i)
#pragma unroll
        for (int j = 0; j < 8; ++j)
#pragma unroll
            for (int q = 0; q < 4; ++q) acc[i][j][q] = 0.f;

    const int a_r  = (lane & 7) + ((lane >> 3) & 1) * 8;
    const int a_cb = (lane >> 4) * 16;
    const int b_r  = (lane & 7) + ((lane >> 4) & 1) * 8;
    const int b_cb = ((lane >> 3) & 1) * 16;

    auto issue = [&](int kc, int stg) {
        const int kp  = kc * GKC;
        const int src = (kp < 768) ? kp : (kp - 768);
        const uint32_t sa  = s0 + stg * STG_B;
        const uint32_t sbb = sa + A_ST;
#pragma unroll
        for (int i = 0; i < 4; ++i) {
            int r = lrow + i * 32;
            cp16(sa + r * ROWB + seg * 16,
                 Ab + (size_t)(bm + r) * 768 + src + seg * 8);
        }
#pragma unroll
        for (int i = 0; i < 4; ++i) {
            int r = lrow + i * 32;
            cp16(sbb + r * ROWB + seg * 16,
                 Bt + (size_t)(bn + r) * KV + kp + seg * 8);
        }
        cp_commit();
    };

    issue(0, 0);
    issue(1, 1);

    for (int kc = 0; kc < nch; ++kc) {
        if (kc < nch - 1)
            asm volatile("cp.async.wait_group 1;" ::: "memory");
        else
            asm volatile("cp.async.wait_group 0;" ::: "memory");
        __syncthreads();

        if (kc + 2 < nch) issue(kc + 2, (kc + 2) % NSTG);

        const uint32_t sa = s0 + (kc % NSTG) * STG_B;
        const uint32_t abase = sa + (wm * 32 + a_r) * ROWB + a_cb;
        const uint32_t bbase = sa + A_ST + (wn * 64 + b_r) * ROWB + b_cb;

#pragma unroll
        for (int ks = 0; ks < 4; ++ks) {
            const int kb = ks * 32;
            uint32_t af[2][4];
#pragma unroll
            for (int fm = 0; fm < 2; ++fm)
                ldsm4(af[fm], abase + fm * 16 * ROWB + kb);
            uint32_t bfr[8][2];
#pragma unroll
            for (int j = 0; j < 4; ++j) {
                uint32_t r[4];
                ldsm4(r, bbase + j * 16 * ROWB + kb);
                bfr[2 * j][0] = r[0]; bfr[2 * j][1] = r[1];
                bfr[2 * j + 1][0] = r[2]; bfr[2 * j + 1][1] = r[3];
            }
#pragma unroll
            for (int fm = 0; fm < 2; ++fm)
#pragma unroll
                for (int fn = 0; fn < 8; ++fn)
                    mma16816(acc[fm][fn], af[fm], bfr[fn]);
        }
    }

#pragma unroll
    for (int fm = 0; fm < 2; ++fm) {
        const int row0 = bm + wm * 32 + fm * 16 + (lane >> 2);
        const int b0 = row0 / NTOK,        n0 = row0 - b0 * NTOK;
        const int b1 = (row0 + 8) / NTOK,  n1 = (row0 + 8) - b1 * NTOK;
#pragma unroll
        for (int fn = 0; fn < 8; ++fn) {
            const int col = bn + wn * 64 + fn * 8 + (lane & 3) * 2;
            const float b0f = __ldg(&bias[col]);
            const float b1f = __ldg(&bias[col + 1]);
            const float o0 = acc[fm][fn][0] + b0f, o1 = acc[fm][fn][1] + b1f;
            const float o2 = acc[fm][fn][2] + b0f, o3 = acc[fm][fn][3] + b1f;
            if (mode == 0) {
                float* C = (float*)Cv;
                *reinterpret_cast<float2*>(&C[(size_t)row0 * ldc + col]) =
                    make_float2(o0, o1);
                *reinterpret_cast<float2*>(&C[(size_t)(row0 + 8) * ldc + col]) =
                    make_float2(o2, o3);
            } else if (mode == 1) {
                __half* C = (__half*)Cv;
                *reinterpret_cast<uint32_t*>(&C[(size_t)row0 * 768 + col]) =
                    pack2(__float2half_rn(o0), __float2half_rn(o1));
                *reinterpret_cast<uint32_t*>(&C[(size_t)(row0 + 8) * 768 + col]) =
                    pack2(__float2half_rn(o2), __float2half_rn(o3));
            } else {
                __half* C = (__half*)Cv;
                const size_t i0 = ((size_t)b0 * CDIM + col) * 64 + n0;
                const size_t i1 = ((size_t)b1 * CDIM + col) * 64 + n1;
                C[i0]      = __float2half_rn(o0);
                C[i0 + 64] = __float2half_rn(o1);
                C[i1]      = __float2half_rn(o2);
                C[i1 + 64] = __float2half_rn(o3);
            }
        }
    }
}

// -------------------- MMA attention: single-V, split-P ----------------------
__global__ __launch_bounds__(128)
void attn_mma_kernel(const float* __restrict__ relb,
                     const float* __restrict__ mask)
{
    __shared__ float bias_s[NTOK * BSTR];

    const int w = blockIdx.x, h = blockIdx.y, zh = blockIdx.z;
    const int tid = threadIdx.x, warp = tid >> 5, lane = tid & 31;
    const int kq = lane >> 2;
    const int kc = (lane & 3) * 2;

    {
        const float* rb = relb + (size_t)h * NTOK * NTOK;
        const float* mk = mask + (size_t)w * NTOK * NTOK;
        for (int i = tid; i < NTOK * NTOK; i += 128)
            bias_s[(i / NTOK) * BSTR + (i % NTOK)] = rb[i] + mk[i];
    }
    __syncthreads();

    const float scale = 0.17677669529663687f;

    for (int win = 0; win < 4; ++win) {
        const int j = zh * 16 + warp * 4 + win;
        const int b = j * 64 + w;
        const __half* qk  = g_qkh + (size_t)b * NTOK * 768 + h * DHEAD;
        const __half* vth = g_vt + ((size_t)b * CDIM + h * DHEAD) * 64;

        // K B-frags
        uint32_t kf[7][2][2];
#pragma unroll
        for (int nt = 0; nt < 7; ++nt) {
            const int key = nt * 8 + kq;
            const bool ok = (key < NTOK);
            const __half* p = qk + (size_t)(ok ? key : 0) * 768 + 384;
#pragma unroll
            for (int ks = 0; ks < 2; ++ks) {
                const int d = ks * 16 + kc;
                kf[nt][ks][0] = ok ? *reinterpret_cast<const uint32_t*>(p + d)     : 0u;
                kf[nt][ks][1] = ok ? *reinterpret_cast<const uint32_t*>(p + d + 8) : 0u;
            }
        }
        // V B-frags (single fp16, transposed layout, aligned 4B loads)
        uint32_t vhf[4][4][2];
#pragma unroll
        for (int nt = 0; nt < 4; ++nt) {
            const size_t drow = (size_t)(nt * 8 + kq) * 64;
#pragma unroll
            for (int kt = 0; kt < 4; ++kt) {
#pragma unroll
                for (int r2 = 0; r2 < 2; ++r2) {
                    const int k0 = kt * 16 + kc + r2 * 8;
                    vhf[nt][kt][r2] = *reinterpret_cast<const uint32_t*>(vth + drow + k0);
                }
            }
        }

        for (int mt = 0; mt < 4; ++mt) {
            const int row = mt * 16 + kq;
            const bool r0ok = (row < NTOK), r1ok = (row + 8 < NTOK);
            const __half* q0 = qk + (size_t)(r0ok ? row : 0) * 768;
            const __half* q1 = qk + (size_t)(r1ok ? row + 8 : 0) * 768;

            uint32_t qf[2][4];
#pragma unroll
            for (int ks = 0; ks < 2; ++ks) {
                const int d = ks * 16 + kc;
                qf[ks][0] = r0ok ? *reinterpret_cast<const uint32_t*>(q0 + d)     : 0u;
                qf[ks][1] = r1ok ? *reinterpret_cast<const uint32_t*>(q1 + d)     : 0u;
                qf[ks][2] = r0ok ? *reinterpret_cast<const uint32_t*>(q0 + d + 8) : 0u;
                qf[ks][3] = r1ok ? *reinterpret_cast<const uint32_t*>(q1 + d + 8) : 0u;
            }

            float sf[7][4];
#pragma unroll
            for (int nt = 0; nt < 7; ++nt) {
                sf[nt][0] = sf[nt][1] = sf[nt][2] = sf[nt][3] = 0.f;
                mma16816(sf[nt], qf[0], kf[nt][0]);
                mma16816(sf[nt], qf[1], kf[nt][1]);
            }

            const int n0 = (row < 48) ? row : 48;
            const int n1 = (row + 8 < 48) ? (row + 8) : 48;
            float sum0 = 0.f, sum1 = 0.f;
#pragma unroll
            for (int nt = 0; nt < 7; ++nt) {
                const int key = nt * 8 + kc;
                const float2 bq0 = *reinterpret_cast<const float2*>(&bias_s[n0 * BSTR + key]);
                const float2 bq1 = *reinterpret_cast<const float2*>(&bias_s[n1 * BSTR + key]);
                float e0 = __expf(sf[nt][0] * scale + bq0.x);
                float e1 = __expf(sf[nt][1] * scale + bq0.y);
                float e2 = __expf(sf[nt][2] * scale + bq1.x);
                float e3 = __expf(sf[nt][3] * scale + bq1.y);
                if (nt == 6) {
                    if (kc != 0) { e0 = 0.f; e2 = 0.f; }
                    e1 = 0.f; e3 = 0.f;
                }
                sf[nt][0] = e0; sf[nt][1] = e1; sf[nt][2] = e2; sf[nt][3] = e3;
                sum0 += e0 + e1; sum1 += e2 + e3;
            }
            sum0 += __shfl_xor_sync(0xffffffffu, sum0, 1);
            sum0 += __shfl_xor_sync(0xffffffffu, sum0, 2);
            sum1 += __shfl_xor_sync(0xffffffffu, sum1, 1);
            sum1 += __shfl_xor_sync(0xffffffffu, sum1, 2);
            const float inv0 = 1.f / sum0, inv1 = 1.f / sum1;

            float of[4][4];
#pragma unroll
            for (int nt = 0; nt < 4; ++nt)
                of[nt][0] = of[nt][1] = of[nt][2] = of[nt][3] = 0.f;

#pragma unroll
            for (int kt = 0; kt < 4; ++kt) {
                float e[8];
                e[0] = sf[2 * kt][0]; e[1] = sf[2 * kt][1];
                e[2] = sf[2 * kt][2]; e[3] = sf[2 * kt][3];
                if (2 * kt + 1 < 7) {
                    e[4] = sf[2 * kt + 1][0]; e[5] = sf[2 * kt + 1][1];
                    e[6] = sf[2 * kt + 1][2]; e[7] = sf[2 * kt + 1][3];
                } else {
                    e[4] = e[5] = e[6] = e[7] = 0.f;
                }
                __half hb[8], lb[8];
#pragma unroll
                for (int i = 0; i < 8; ++i) {
                    hb[i] = __float2half_rn(e[i]);
                    lb[i] = __float2half_rn(e[i] - __half2float(hb[i]));
                }
                uint32_t ph[4], pl[4];
                ph[0] = pack2(hb[0], hb[1]); ph[1] = pack2(hb[2], hb[3]);
                ph[2] = pack2(hb[4], hb[5]); ph[3] = pack2(hb[6], hb[7]);
                pl[0] = pack2(lb[0], lb[1]); pl[1] = pack2(lb[2], lb[3]);
                pl[2] = pack2(lb[4], lb[5]); pl[3] = pack2(lb[6], lb[7]);
#pragma unroll
                for (int nt = 0; nt < 4; ++nt) {
                    mma16816(of[nt], ph, vhf[nt][kt]);
                    mma16816(of[nt], pl, vhf[nt][kt]);
                }
            }

            const size_t r0 = ((size_t)b * NTOK + row) * 768 + h * DHEAD;
            const size_t r1 = ((size_t)b * NTOK + row + 8) * 768 + h * DHEAD;
#pragma unroll
            for (int nt = 0; nt < 4; ++nt) {
                const int d = nt * 8 + kc;
                if (r0ok) {
                    const float o0 = of[nt][0] * inv0, o1 = of[nt][1] * inv0;
                    const __half h0 = __float2half_rn(o0);
                    const __half h1 = __float2half_rn(o1);
                    *reinterpret_cast<uint32_t*>(&g_attf[r0 + d]) = pack2(h0, h1);
                    *reinterpret_cast<uint32_t*>(&g_attf[r0 + 384 + d]) =
                        pack2(__float2half_rn(o0 - __half2float(h0)),
                              __float2half_rn(o1 - __half2float(h1)));
                }
                if (r1ok) {
                    const float o2 = of[nt][2] * inv1, o3 = of[nt][3] * inv1;
                    const __half h2 = __float2half_rn(o2);
                    const __half h3 = __float2half_rn(o3);
                    *reinterpret_cast<uint32_t*>(&g_attf[r1 + d]) = pack2(h2, h3);
                    *reinterpret_cast<uint32_t*>(&g_attf[r1 + 384 + d]) =
                        pack2(__float2half_rn(o2 - __half2float(h2)),
                              __float2half_rn(o3 - __half2float(h3)));
                }
            }
        }
    }
}

// ---------------------------------------------------------------------------
extern "C" void kernel_launch(void* const* d_in, const int* in_sizes, int n_in,
                              void* d_out, int out_size)
{
    const float* x      = (const float*)d_in[0];
    const float* mask   = (const float*)d_in[1];
    const float* qkv_w  = (const float*)d_in[2];
    const float* qkv_b  = (const float*)d_in[3];
    const float* proj_w = (const float*)d_in[4];
    const float* proj_b = (const float*)d_in[5];
    const float* relb   = (const float*)d_in[6];
    float* out = (float*)d_out;

    void *p_xhf, *p_attf, *p_qkh, *p_vt, *p_wqt, *p_wpt;
    cudaGetSymbolAddress(&p_xhf,  g_xhf);
    cudaGetSymbolAddress(&p_attf, g_attf);
    cudaGetSymbolAddress(&p_qkh,  g_qkh);
    cudaGetSymbolAddress(&p_vt,   g_vt);
    cudaGetSymbolAddress(&p_wqt,  g_wqt);
    cudaGetSymbolAddress(&p_wpt,  g_wpt);

    cudaFuncSetAttribute(gemm_fp16x_kernel,
                         cudaFuncAttributeMaxDynamicSharedMemorySize, SMEM_GEMM);

    // 0) fused preps (+ vt pad zeroing)
    prep_all_kernel<<<PX_BLKS + WQ_BLKS + WP_BLKS + PAD_BLKS, 256>>>(x, qkv_w, proj_w);

    // 1) Q/K GEMM: 1 product set (x_hi * w_hi), fp16 out (mode 1)
    {
        dim3 grid(768 / GBN, MTILES);
        gemm_fp16x_kernel<<<grid, 256, SMEM_GEMM>>>(
            (const __half*)p_xhf, (const __half*)p_wqt,
            qkv_b, p_qkh, 768, 6, 1);
    }
    // 2) V GEMM: 2-term (x_hi + x_lo) * w_hi, fp16 transposed out (mode 2)
    {
        dim3 grid(384 / GBN, MTILES);
        gemm_fp16x_kernel<<<grid, 256, SMEM_GEMM>>>(
            (const __half*)p_xhf,
            (const __half*)p_wqt + (size_t)768 * KV,
            qkv_b + 768, p_vt, 0, 12, 2);
    }
    // 3) MMA attention (launch idx 3 -> ncu capture)
    {
        dim3 grid(NWIN, HNUM, 2);
        attn_mma_kernel<<<grid, 128>>>(relb, mask);
    }
    // 4) projection GEMM: 2-term (a_hi + a_lo) * w_hi, fp32 out (mode 0)
    {
        dim3 grid(CDIM / GBN, MTILES);
        gemm_fp16x_kernel<<<grid, 256, SMEM_GEMM>>>(
            (const __half*)p_attf, (const __half*)p_wpt,
            proj_b, out, CDIM, 12, 0);
    }
}

// round 12
// speedup vs baseline: 6.8122x; 1.3347x over previous
#include <cuda_runtime.h>
#include <cuda_fp16.h>
#include <cstdint>

// Problem constants: B_=2048, N=49, C=384, H=12, d=32, nW=64
#define BWIN   2048
#define NTOK   49
#define CDIM   384
#define HNUM   12
#define DHEAD  32
#define NWIN   64
#define MROWS  (BWIN * NTOK)     // 100352
#define QKVC   (3 * CDIM)        // 1152
#define KDIM   384

// GEMM tiling
#define GBM   128
#define GBN   128
#define GKC   64
#define NCH   6                  // 384 / 64
#define NSTG  3
#define ROWB  144
#define A_ST  (GBM * ROWB)
#define B_ST  (GBN * ROWB)
#define STG_B (A_ST + B_ST)
#define SMEM_GEMM (NSTG * STG_B)
#define MTILES (MROWS / GBM)     // 784

#define PX_BLKS  37632           // MROWS*96/256
#define WQ_BLKS  1728            // 1152*384/256
#define WP_BLKS  576             // 384*384/256
#define PAD_BLKS 6144            // zero vt pad keys 48..63

#define BSTR 50                  // bias smem row stride (floats)

// -------------------- device scratch --------------------------------------
__device__ __align__(16) __half g_xh  [(size_t)MROWS * KDIM];       // x fp16
__device__ __align__(16) __half g_attf[(size_t)MROWS * CDIM];       // attn out fp16
__device__ __align__(16) __half g_qkh [(size_t)MROWS * 768];        // q|k fp16
__device__ __align__(16) __half g_vt  [(size_t)BWIN * CDIM * 64];   // vT fp16
__device__ __align__(16) __half g_wq  [(size_t)QKVC * KDIM];        // qkv_w^T fp16
__device__ __align__(16) __half g_wp  [(size_t)CDIM * KDIM];        // proj_w^T fp16

// -------------------- PTX helpers -----------------------------------------
__device__ __forceinline__ uint32_t smem_u32(const void* p) {
    uint32_t a;
    asm("{ .reg .u64 t; cvta.to.shared.u64 t, %1; cvt.u32.u64 %0, t; }"
        : "=r"(a) : "l"(p));
    return a;
}
__device__ __forceinline__ void cp16(uint32_t s, const void* g) {
    asm volatile("cp.async.cg.shared.global [%0], [%1], 16;" :: "r"(s), "l"(g));
}
__device__ __forceinline__ void cp_commit() {
    asm volatile("cp.async.commit_group;" ::: "memory");
}
__device__ __forceinline__ void ldsm4(uint32_t* r, uint32_t addr) {
    asm volatile("ldmatrix.sync.aligned.m8n8.x4.shared.b16 {%0,%1,%2,%3}, [%4];"
        : "=r"(r[0]), "=r"(r[1]), "=r"(r[2]), "=r"(r[3]) : "r"(addr));
}
__device__ __forceinline__ void mma16816(float* d, const uint32_t* a, const uint32_t* b) {
    asm volatile(
        "mma.sync.aligned.m16n8k16.row.col.f32.f16.f16.f32 "
        "{%0,%1,%2,%3}, {%4,%5,%6,%7}, {%8,%9}, {%0,%1,%2,%3};"
        : "+f"(d[0]), "+f"(d[1]), "+f"(d[2]), "+f"(d[3])
        : "r"(a[0]), "r"(a[1]), "r"(a[2]), "r"(a[3]), "r"(b[0]), "r"(b[1]));
}
__device__ __forceinline__ uint32_t pack2(__half lo, __half hi) {
    return (uint32_t)__half_as_ushort(lo) | ((uint32_t)__half_as_ushort(hi) << 16);
}

// -------------------- fused prep -------------------------------------------
__global__ __launch_bounds__(256)
void prep_all_kernel(const float* __restrict__ x,
                     const float* __restrict__ qkv_w,
                     const float* __restrict__ proj_w)
{
    const int bid = blockIdx.x;
    const int tid = threadIdx.x;

    if (bid < PX_BLKS) {
        size_t id = (size_t)bid * 256 + tid;     // one per 4 cols of x
        size_t row = id / 96;
        int c4 = (int)(id % 96) * 4;
        float4 v = *reinterpret_cast<const float4*>(&x[row * KDIM + c4]);
        __half h[4];
        h[0] = __float2half_rn(v.x); h[1] = __float2half_rn(v.y);
        h[2] = __float2half_rn(v.z); h[3] = __float2half_rn(v.w);
        *reinterpret_cast<uint2*>(&g_xh[row * KDIM + c4]) = *reinterpret_cast<uint2*>(h);
    } else if (bid < PX_BLKS + WQ_BLKS) {
        int id = (bid - PX_BLKS) * 256 + tid;
        if (id < KDIM * QKVC) {
            int k = id / QKVC, n = id % QKVC;
            g_wq[(size_t)n * KDIM + k] = __float2half_rn(qkv_w[(size_t)k * QKVC + n]);
        }
    } else if (bid < PX_BLKS + WQ_BLKS + WP_BLKS) {
        int id = (bid - PX_BLKS - WQ_BLKS) * 256 + tid;
        if (id < KDIM * CDIM) {
            int k = id / CDIM, n = id % CDIM;
            g_wp[(size_t)n * KDIM + k] = __float2half_rn(proj_w[(size_t)k * CDIM + n]);
        }
    } else {
        size_t s = (size_t)(bid - PX_BLKS - WQ_BLKS - WP_BLKS) * 256 + tid;
        size_t row = s >> 1;
        if (row < (size_t)BWIN * CDIM) {
            uint4* p = reinterpret_cast<uint4*>(
                reinterpret_cast<char*>(g_vt) + row * 128 + 96 + (s & 1) * 16);
            *p = make_uint4(0, 0, 0, 0);
        }
    }
}

// -------------------- GEMM (single fp16 product) ----------------------------
// mode 0: fp32 out to Cv (ldc stride)                         (proj)
// mode 3: qkv fused — bn<768: fp16 out to g_qkh (stride 768);
//                     bn>=768: fp16 scatter to g_vt[b][col][key]
__global__ __launch_bounds__(256, 2)
void gemm_fp16_kernel(const __half* __restrict__ Ab, int lda,
                      const __half* __restrict__ Bt,
                      const float* __restrict__ bias,
                      void* __restrict__ Cv, int ldc, int mode)
{
    extern __shared__ char smem[];
    const uint32_t s0 = smem_u32(smem);

    const int tid  = threadIdx.x;
    const int wid  = tid >> 5;
    const int lane = tid & 31;
    const int wm   = wid >> 1;
    const int wn   = wid & 1;
    const int bn   = blockIdx.x * GBN;
    const int bm   = blockIdx.y * GBM;

    const int lrow = tid >> 3;
    const int seg  = tid & 7;

    float acc[2][8][4];
#pragma unroll
    for (int i = 0; i < 2; ++i)
#pragma unroll
        for (int j = 0; j < 8; ++j)
#pragma unroll
            for (int q = 0; q < 4; ++q) acc[i][j][q] = 0.f;

    const int a_r  = (lane & 7) + ((lane >> 3) & 1) * 8;
    const int a_cb = (lane >> 4) * 16;
    const int b_r  = (lane & 7) + ((lane >> 4) & 1) * 8;
    const int b_cb = ((lane >> 3) & 1) * 16;

    auto issue = [&](int kc, int stg) {
        const int kp  = kc * GKC;
        const uint32_t sa  = s0 + stg * STG_B;
        const uint32_t sbb = sa + A_ST;
#pragma unroll
        for (int i = 0; i < 4; ++i) {
            int r = lrow + i * 32;
            cp16(sa + r * ROWB + seg * 16,
                 Ab + (size_t)(bm + r) * lda + kp + seg * 8);
        }
#pragma unroll
        for (int i = 0; i < 4; ++i) {
            int r = lrow + i * 32;
            cp16(sbb + r * ROWB + seg * 16,
                 Bt + (size_t)(bn + r) * KDIM + kp + seg * 8);
        }
        cp_commit();
    };

    issue(0, 0);
    issue(1, 1);

    for (int kc = 0; kc < NCH; ++kc) {
        if (kc < NCH - 1)
            asm volatile("cp.async.wait_group 1;" ::: "memory");
        else
            asm volatile("cp.async.wait_group 0;" ::: "memory");
        __syncthreads();

        if (kc + 2 < NCH) issue(kc + 2, (kc + 2) % NSTG);

        const uint32_t sa = s0 + (kc % NSTG) * STG_B;
        const uint32_t abase = sa + (wm * 32 + a_r) * ROWB + a_cb;
        const uint32_t bbase = sa + A_ST + (wn * 64 + b_r) * ROWB + b_cb;

#pragma unroll
        for (int ks = 0; ks < 4; ++ks) {
            const int kb = ks * 32;
            uint32_t af[2][4];
#pragma unroll
            for (int fm = 0; fm < 2; ++fm)
                ldsm4(af[fm], abase + fm * 16 * ROWB + kb);
            uint32_t bfr[8][2];
#pragma unroll
            for (int j = 0; j < 4; ++j) {
                uint32_t r[4];
                ldsm4(r, bbase + j * 16 * ROWB + kb);
                bfr[2 * j][0] = r[0]; bfr[2 * j][1] = r[1];
                bfr[2 * j + 1][0] = r[2]; bfr[2 * j + 1][1] = r[3];
            }
#pragma unroll
            for (int fm = 0; fm < 2; ++fm)
#pragma unroll
                for (int fn = 0; fn < 8; ++fn)
                    mma16816(acc[fm][fn], af[fm], bfr[fn]);
        }
    }

#pragma unroll
    for (int fm = 0; fm < 2; ++fm) {
        const int row0 = bm + wm * 32 + fm * 16 + (lane >> 2);
        const int b0 = row0 / NTOK,        n0 = row0 - b0 * NTOK;
        const int b1 = (row0 + 8) / NTOK,  n1 = (row0 + 8) - b1 * NTOK;
#pragma unroll
        for (int fn = 0; fn < 8; ++fn) {
            const int col = bn + wn * 64 + fn * 8 + (lane & 3) * 2;
            const float b0f = __ldg(&bias[col]);
            const float b1f = __ldg(&bias[col + 1]);
            const float o0 = acc[fm][fn][0] + b0f, o1 = acc[fm][fn][1] + b1f;
            const float o2 = acc[fm][fn][2] + b0f, o3 = acc[fm][fn][3] + b1f;
            if (mode == 0) {
                float* C = (float*)Cv;
                *reinterpret_cast<float2*>(&C[(size_t)row0 * ldc + col]) =
                    make_float2(o0, o1);
                *reinterpret_cast<float2*>(&C[(size_t)(row0 + 8) * ldc + col]) =
                    make_float2(o2, o3);
            } else if (col < 768) {
                // q|k fp16 out
                *reinterpret_cast<uint32_t*>(&g_qkh[(size_t)row0 * 768 + col]) =
                    pack2(__float2half_rn(o0), __float2half_rn(o1));
                *reinterpret_cast<uint32_t*>(&g_qkh[(size_t)(row0 + 8) * 768 + col]) =
                    pack2(__float2half_rn(o2), __float2half_rn(o3));
            } else {
                // v fp16 transposed scatter
                const int cv = col - 768;
                const size_t i0 = ((size_t)b0 * CDIM + cv) * 64 + n0;
                const size_t i1 = ((size_t)b1 * CDIM + cv) * 64 + n1;
                g_vt[i0]      = __float2half_rn(o0);
                g_vt[i0 + 64] = __float2half_rn(o1);
                g_vt[i1]      = __float2half_rn(o2);
                g_vt[i1 + 64] = __float2half_rn(o3);
            }
        }
    }
}

// -------------------- MMA attention: single-V, split-P, fp16 out ------------
__global__ __launch_bounds__(128)
void attn_mma_kernel(const float* __restrict__ relb,
                     const float* __restrict__ mask)
{
    __shared__ float bias_s[NTOK * BSTR];

    const int w = blockIdx.x, h = blockIdx.y, zh = blockIdx.z;
    const int tid = threadIdx.x, warp = tid >> 5, lane = tid & 31;
    const int kq = lane >> 2;
    const int kc = (lane & 3) * 2;

    {
        const float* rb = relb + (size_t)h * NTOK * NTOK;
        const float* mk = mask + (size_t)w * NTOK * NTOK;
        for (int i = tid; i < NTOK * NTOK; i += 128)
            bias_s[(i / NTOK) * BSTR + (i % NTOK)] = rb[i] + mk[i];
    }
    __syncthreads();

    const float scale = 0.17677669529663687f;

    for (int win = 0; win < 4; ++win) {
        const int j = zh * 16 + warp * 4 + win;
        const int b = j * 64 + w;
        const __half* qk  = g_qkh + (size_t)b * NTOK * 768 + h * DHEAD;
        const __half* vth = g_vt + ((size_t)b * CDIM + h * DHEAD) * 64;

        // K B-frags
        uint32_t kf[7][2][2];
#pragma unroll
        for (int nt = 0; nt < 7; ++nt) {
            const int key = nt * 8 + kq;
            const bool ok = (key < NTOK);
            const __half* p = qk + (size_t)(ok ? key : 0) * 768 + 384;
#pragma unroll
            for (int ks = 0; ks < 2; ++ks) {
                const int d = ks * 16 + kc;
                kf[nt][ks][0] = ok ? *reinterpret_cast<const uint32_t*>(p + d)     : 0u;
                kf[nt][ks][1] = ok ? *reinterpret_cast<const uint32_t*>(p + d + 8) : 0u;
            }
        }
        // V B-frags (single fp16, transposed layout)
        uint32_t vhf[4][4][2];
#pragma unroll
        for (int nt = 0; nt < 4; ++nt) {
            const size_t drow = (size_t)(nt * 8 + kq) * 64;
#pragma unroll
            for (int kt = 0; kt < 4; ++kt) {
#pragma unroll
                for (int r2 = 0; r2 < 2; ++r2) {
                    const int k0 = kt * 16 + kc + r2 * 8;
                    vhf[nt][kt][r2] = *reinterpret_cast<const uint32_t*>(vth + drow + k0);
                }
            }
        }

        for (int mt = 0; mt < 4; ++mt) {
            const int row = mt * 16 + kq;
            const bool r0ok = (row < NTOK), r1ok = (row + 8 < NTOK);
            const __half* q0 = qk + (size_t)(r0ok ? row : 0) * 768;
            const __half* q1 = qk + (size_t)(r1ok ? row + 8 : 0) * 768;

            uint32_t qf[2][4];
#pragma unroll
            for (int ks = 0; ks < 2; ++ks) {
                const int d = ks * 16 + kc;
                qf[ks][0] = r0ok ? *reinterpret_cast<const uint32_t*>(q0 + d)     : 0u;
                qf[ks][1] = r1ok ? *reinterpret_cast<const uint32_t*>(q1 + d)     : 0u;
                qf[ks][2] = r0ok ? *reinterpret_cast<const uint32_t*>(q0 + d + 8) : 0u;
                qf[ks][3] = r1ok ? *reinterpret_cast<const uint32_t*>(q1 + d + 8) : 0u;
            }

            float sf[7][4];
#pragma unroll
            for (int nt = 0; nt < 7; ++nt) {
                sf[nt][0] = sf[nt][1] = sf[nt][2] = sf[nt][3] = 0.f;
                mma16816(sf[nt], qf[0], kf[nt][0]);
                mma16816(sf[nt], qf[1], kf[nt][1]);
            }

            const int n0 = (row < 48) ? row : 48;
            const int n1 = (row + 8 < 48) ? (row + 8) : 48;
            float sum0 = 0.f, sum1 = 0.f;
#pragma unroll
            for (int nt = 0; nt < 7; ++nt) {
                const int key = nt * 8 + kc;
                const float2 bq0 = *reinterpret_cast<const float2*>(&bias_s[n0 * BSTR + key]);
                const float2 bq1 = *reinterpret_cast<const float2*>(&bias_s[n1 * BSTR + key]);
                float e0 = __expf(sf[nt][0] * scale + bq0.x);
                float e1 = __expf(sf[nt][1] * scale + bq0.y);
                float e2 = __expf(sf[nt][2] * scale + bq1.x);
                float e3 = __expf(sf[nt][3] * scale + bq1.y);
                if (nt == 6) {
                    if (kc != 0) { e0 = 0.f; e2 = 0.f; }
                    e1 = 0.f; e3 = 0.f;
                }
                sf[nt][0] = e0; sf[nt][1] = e1; sf[nt][2] = e2; sf[nt][3] = e3;
                sum0 += e0 + e1; sum1 += e2 + e3;
            }
            sum0 += __shfl_xor_sync(0xffffffffu, sum0, 1);
            sum0 += __shfl_xor_sync(0xffffffffu, sum0, 2);
            sum1 += __shfl_xor_sync(0xffffffffu, sum1, 1);
            sum1 += __shfl_xor_sync(0xffffffffu, sum1, 2);
            const float inv0 = 1.f / sum0, inv1 = 1.f / sum1;

            float of[4][4];
#pragma unroll
            for (int nt = 0; nt < 4; ++nt)
                of[nt][0] = of[nt][1] = of[nt][2] = of[nt][3] = 0.f;

#pragma unroll
            for (int kt = 0; kt < 4; ++kt) {
                float e[8];
                e[0] = sf[2 * kt][0]; e[1] = sf[2 * kt][1];
                e[2] = sf[2 * kt][2]; e[3] = sf[2 * kt][3];
                if (2 * kt + 1 < 7) {
                    e[4] = sf[2 * kt + 1][0]; e[5] = sf[2 * kt + 1][1];
                    e[6] = sf[2 * kt + 1][2]; e[7] = sf[2 * kt + 1][3];
                } else {
                    e[4] = e[5] = e[6] = e[7] = 0.f;
                }
                __half hb[8], lb[8];
#pragma unroll
                for (int i = 0; i < 8; ++i) {
                    hb[i] = __float2half_rn(e[i]);
                    lb[i] = __float2half_rn(e[i] - __half2float(hb[i]));
                }
                uint32_t ph[4], pl[4];
                ph[0] = pack2(hb[0], hb[1]); ph[1] = pack2(hb[2], hb[3]);
                ph[2] = pack2(hb[4], hb[5]); ph[3] = pack2(hb[6], hb[7]);
                pl[0] = pack2(lb[0], lb[1]); pl[1] = pack2(lb[2], lb[3]);
                pl[2] = pack2(lb[4], lb[5]); pl[3] = pack2(lb[6], lb[7]);
#pragma unroll
                for (int nt = 0; nt < 4; ++nt) {
                    mma16816(of[nt], ph, vhf[nt][kt]);
                    mma16816(of[nt], pl, vhf[nt][kt]);
                }
            }

            const size_t r0 = ((size_t)b * NTOK + row) * CDIM + h * DHEAD;
            const size_t r1 = ((size_t)b * NTOK + row + 8) * CDIM + h * DHEAD;
#pragma unroll
            for (int nt = 0; nt < 4; ++nt) {
                const int d = nt * 8 + kc;
                if (r0ok) {
                    *reinterpret_cast<uint32_t*>(&g_attf[r0 + d]) =
                        pack2(__float2half_rn(of[nt][0] * inv0),
                              __float2half_rn(of[nt][1] * inv0));
                }
                if (r1ok) {
                    *reinterpret_cast<uint32_t*>(&g_attf[r1 + d]) =
                        pack2(__float2half_rn(of[nt][2] * inv1),
                              __float2half_rn(of[nt][3] * inv1));
                }
            }
        }
    }
}

// ---------------------------------------------------------------------------
extern "C" void kernel_launch(void* const* d_in, const int* in_sizes, int n_in,
                              void* d_out, int out_size)
{
    const float* x      = (const float*)d_in[0];
    const float* mask   = (const float*)d_in[1];
    const float* qkv_w  = (const float*)d_in[2];
    const float* qkv_b  = (const float*)d_in[3];
    const float* proj_w = (const float*)d_in[4];
    const float* proj_b = (const float*)d_in[5];
    const float* relb   = (const float*)d_in[6];
    float* out = (float*)d_out;

    void *p_xh, *p_attf, *p_wq, *p_wp;
    cudaGetSymbolAddress(&p_xh,   g_xh);
    cudaGetSymbolAddress(&p_attf, g_attf);
    cudaGetSymbolAddress(&p_wq,   g_wq);
    cudaGetSymbolAddress(&p_wp,   g_wp);

    cudaFuncSetAttribute(gemm_fp16_kernel,
                         cudaFuncAttributeMaxDynamicSharedMemorySize, SMEM_GEMM);

    // 0) fused preps (+ vt pad zeroing)
    prep_all_kernel<<<PX_BLKS + WQ_BLKS + WP_BLKS + PAD_BLKS, 256>>>(x, qkv_w, proj_w);

    // 1) fused QKV GEMM: all 1152 cols, single fp16 product (mode 3)
    {
        dim3 grid(QKVC / GBN, MTILES);    // 9 x 784
        gemm_fp16_kernel<<<grid, 256, SMEM_GEMM>>>(
            (const __half*)p_xh, KDIM, (const __half*)p_wq,
            qkv_b, nullptr, 0, 3);
    }
    // 2) MMA attention
    {
        dim3 grid(NWIN, HNUM, 2);
        attn_mma_kernel<<<grid, 128>>>(relb, mask);
    }
    // 3) projection GEMM: fp32 out (mode 0)
    {
        dim3 grid(CDIM / GBN, MTILES);    // 3 x 784
        gemm_fp16_kernel<<<grid, 256, SMEM_GEMM>>>(
            (const __half*)p_attf, CDIM, (const __half*)p_wp,
            proj_b, out, CDIM, 0);
    }
}